// round 10
// baseline (speedup 1.0000x reference)
#include <cuda_runtime.h>
#include <cuda_bf16.h>
#include <cstdint>

#define BATCH   4
#define SEQ     1024
#define DMODEL  512
#define NHEADS  8
#define DK      64
#define NLAYERS 6
#define DFFN    2048
#define MROWS   (BATCH*SEQ)   // 4096
#define ALSTRIDE ((long long)BATCH*NHEADS*SEQ*SEQ)   // attn layer stride

// ---------------- scratch (device globals) -------------------------------------
__device__ float g_x  [MROWS*DMODEL];     // residual stream (fp32)
__device__ float g_y  [MROWS*DMODEL];     // gemm fp32 out (pre-LN)
__device__ float g_rinv[NLAYERS*BATCH*NHEADS*SEQ];                    // 1/rowsum
__device__ __nv_bfloat16 g_xh[MROWS*DMODEL],  g_xl[MROWS*DMODEL];    // x split
__device__ __nv_bfloat16 g_qh[3*MROWS*DMODEL], g_ql[3*MROWS*DMODEL]; // q|k|v split
__device__ __nv_bfloat16 g_ch[MROWS*DMODEL],  g_cl[MROWS*DMODEL];    // ctx split
__device__ __nv_bfloat16 g_fh[MROWS*DFFN],    g_fl[MROWS*DFFN];      // ffn split

// bf16 split transposed weights Wt[n][k]: qkv(1536x512)|o(512x512)|w1(2048x512)|w2(512x2048)
#define WL_STRIDE 3145728
#define WOFF_QKV  0
#define WOFF_O    786432
#define WOFF_1    1048576
#define WOFF_2    2097152
__device__ __nv_bfloat16 g_whi[NLAYERS*WL_STRIDE];
__device__ __nv_bfloat16 g_wlo[NLAYERS*WL_STRIDE];

// ---------------- helpers -------------------------------------------------------
__device__ __forceinline__ uint32_t smem_u32(const void* p) {
    uint32_t a;
    asm("{ .reg .u64 t; cvta.to.shared.u64 t, %1; cvt.u32.u64 %0, t; }" : "=r"(a) : "l"(p));
    return a;
}
__device__ __forceinline__ void ldm4(uint32_t* r, uint32_t a) {
    asm volatile("ldmatrix.sync.aligned.m8n8.x4.shared.b16 {%0,%1,%2,%3}, [%4];"
        : "=r"(r[0]), "=r"(r[1]), "=r"(r[2]), "=r"(r[3]) : "r"(a));
}
__device__ __forceinline__ void ldm4t(uint32_t* r, uint32_t a) {
    asm volatile("ldmatrix.sync.aligned.m8n8.x4.trans.shared.b16 {%0,%1,%2,%3}, [%4];"
        : "=r"(r[0]), "=r"(r[1]), "=r"(r[2]), "=r"(r[3]) : "r"(a));
}
__device__ __forceinline__ void mma16816(float* d, const uint32_t* a, const uint32_t* b) {
    asm volatile("mma.sync.aligned.m16n8k16.row.col.f32.bf16.bf16.f32 "
        "{%0,%1,%2,%3}, {%4,%5,%6,%7}, {%8,%9}, {%0,%1,%2,%3};"
        : "+f"(d[0]), "+f"(d[1]), "+f"(d[2]), "+f"(d[3])
        : "r"(a[0]), "r"(a[1]), "r"(a[2]), "r"(a[3]), "r"(b[0]), "r"(b[1]));
}
__device__ __forceinline__ void split2(float x, float y, uint32_t& hi, uint32_t& lo) {
    __nv_bfloat162 h = __floats2bfloat162_rn(x, y);
    float hx = __bfloat162float(h.x), hy = __bfloat162float(h.y);
    __nv_bfloat162 l2 = __floats2bfloat162_rn(x - hx, y - hy);
    hi = *(uint32_t*)&h;
    lo = *(uint32_t*)&l2;
}
__device__ __forceinline__ void cpa16(uint32_t dst, const void* src) {
    asm volatile("cp.async.cg.shared.global [%0], [%1], 16;" :: "r"(dst), "l"(src));
}
#define CP_COMMIT() asm volatile("cp.async.commit_group;" ::: "memory")
template<int N> __device__ __forceinline__ void cp_wait() {
    asm volatile("cp.async.wait_group %0;" :: "n"(N) : "memory");
}

// ---------------- embedding + positional encoding (writes x + split) -----------
__global__ void embed_kernel(const int* __restrict__ tok,
                             const float* __restrict__ emb) {
    int p = blockIdx.x * 256 + threadIdx.x;
    if (p >= MROWS*DMODEL/2) return;
    int idx = p * 2;
    int row = idx >> 9;
    int d   = idx & (DMODEL-1);
    int s   = row & (SEQ-1);
    int tk  = tok[row];
    float freq = expf((float)d * (-9.210340371976184f / (float)DMODEL));
    float ang  = (float)s * freq;
    float v0 = emb[tk*DMODEL + d]     + sinf(ang);
    float v1 = emb[tk*DMODEL + d + 1] + cosf(ang);
    *(float2*)&g_x[idx] = make_float2(v0, v1);
    uint32_t h, l; split2(v0, v1, h, l);
    *(uint32_t*)&g_xh[idx] = h;
    *(uint32_t*)&g_xl[idx] = l;
}

// ---------------- weight transpose + split kernels ------------------------------
__global__ void wconv4_kernel(const float* __restrict__ Wq, const float* __restrict__ Wk,
                              const float* __restrict__ Wv, const float* __restrict__ Wo,
                              __nv_bfloat16* __restrict__ hi, __nv_bfloat16* __restrict__ lo) {
    __shared__ float tl[32][33];
    int z = blockIdx.z, lyr = z >> 2, which = z & 3;
    const float* src;
    size_t doff;
    switch (which) {
        case 0: src = Wq; doff = WOFF_QKV;          break;
        case 1: src = Wk; doff = WOFF_QKV + 262144; break;
        case 2: src = Wv; doff = WOFF_QKV + 524288; break;
        default: src = Wo; doff = WOFF_O;           break;
    }
    src += (size_t)lyr * 262144;
    hi  += (size_t)lyr * WL_STRIDE + doff;
    lo  += (size_t)lyr * WL_STRIDE + doff;
    int n0 = blockIdx.x*32, k0 = blockIdx.y*32;
    int tx = threadIdx.x & 31, tg = threadIdx.x >> 5;
    #pragma unroll
    for (int r = tg; r < 32; r += 8)
        tl[r][tx] = src[(size_t)(k0 + r)*512 + n0 + tx];
    __syncthreads();
    #pragma unroll
    for (int r = tg; r < 32; r += 8) {
        float x = tl[tx][r];
        __nv_bfloat16 h = __float2bfloat16(x);
        size_t o = (size_t)(n0 + r)*512 + k0 + tx;
        hi[o] = h;
        lo[o] = __float2bfloat16(x - __bfloat162float(h));
    }
}

__global__ void wconv_kernel(const float* __restrict__ src,
                             __nv_bfloat16* __restrict__ hi,
                             __nv_bfloat16* __restrict__ lo,
                             int K, int N, long srcStride, long dstStride) {
    __shared__ float tl[32][33];
    int l = blockIdx.z;
    src += (size_t)l * srcStride;
    hi  += (size_t)l * dstStride;
    lo  += (size_t)l * dstStride;
    int n0 = blockIdx.x*32, k0 = blockIdx.y*32;
    int tx = threadIdx.x & 31, tg = threadIdx.x >> 5;
    #pragma unroll
    for (int r = tg; r < 32; r += 8)
        tl[r][tx] = src[(size_t)(k0 + r)*N + n0 + tx];
    __syncthreads();
    #pragma unroll
    for (int r = tg; r < 32; r += 8) {
        float x = tl[tx][r];
        __nv_bfloat16 h = __float2bfloat16(x);
        size_t o = (size_t)(n0 + r)*K + k0 + tx;
        hi[o] = h;
        lo[o] = __float2bfloat16(x - __bfloat162float(h));
    }
}

// ---------------- 3-stage pipelined HMMA GEMM: C = A @ Bt^T ---------------------
// Tile 128 x NT (NT = 128 or 64), 8 warps (4m x 2n), warp tile 32 x NT/2.
template<int NT>
__device__ __forceinline__ void gemm_stage_load(
        uint32_t sbase, int t,
        const __nv_bfloat16* Ah, const __nv_bfloat16* Al,
        const __nv_bfloat16* Bh, const __nv_bfloat16* Bl,
        int m0, int n0, int k0, int K) {
    #pragma unroll
    for (int i = 0; i < 4; i++) {                      // A: 128 rows
        int seg = i*256 + t;
        int r = seg >> 3, c = seg & 7;
        uint32_t so = (uint32_t)r*144 + c*16;
        size_t ga = (size_t)(m0 + r)*K + k0 + c*8;
        cpa16(sbase +         so, Ah + ga);
        cpa16(sbase + 18432 + so, Al + ga);
    }
    #pragma unroll
    for (int i = 0; i < NT/32; i++) {                  // B: NT rows
        int seg = i*256 + t;
        int r = seg >> 3, c = seg & 7;
        uint32_t so = (uint32_t)r*144 + c*16;
        size_t gb = (size_t)(n0 + r)*K + k0 + c*8;
        cpa16(sbase + 36864 +          so, Bh + gb);
        cpa16(sbase + 36864 + NT*144 + so, Bl + gb);
    }
}

template<int MODE, int NT>
__global__ __launch_bounds__(256) void mma_gemm(
        const __nv_bfloat16* __restrict__ Ah, const __nv_bfloat16* __restrict__ Al,
        const __nv_bfloat16* __restrict__ Bh, const __nv_bfloat16* __restrict__ Bl,
        float* __restrict__ Cf,
        __nv_bfloat16* __restrict__ Ch, __nv_bfloat16* __restrict__ Cl,
        int N, int K) {
    constexpr int STG = 36864 + NT*288;        // stage bytes
    constexpr int WN  = NT/2;                  // warp n extent
    constexpr int G   = WN/16;                 // b-groups per warp
    extern __shared__ char sm[];
    const uint32_t sb = smem_u32(sm);
    int t = threadIdx.x, l = t & 31, wid = t >> 5;
    int m0 = blockIdx.y * 128, n0 = blockIdx.x * NT;
    int wm = (wid & 3) * 32, wn = (wid >> 2) * WN;

    float acc[2][2*G][4];
    #pragma unroll
    for (int i = 0; i < 2; i++)
        #pragma unroll
        for (int j = 0; j < 2*G; j++)
            #pragma unroll
            for (int q = 0; q < 4; q++) acc[i][j][q] = 0.f;

    const int NK = K >> 6;
    gemm_stage_load<NT>(sb, t, Ah, Al, Bh, Bl, m0, n0, 0, K);
    CP_COMMIT();
    if (NK > 1) {
        gemm_stage_load<NT>(sb + STG, t, Ah, Al, Bh, Bl, m0, n0, 64, K);
        CP_COMMIT();
    }

    int s_cur = 0, s_pre = 2;
    for (int kc = 0; kc < NK; kc++) {
        if (kc < NK - 1) cp_wait<1>(); else cp_wait<0>();
        __syncthreads();
        if (kc + 2 < NK) {
            gemm_stage_load<NT>(sb + s_pre*STG, t, Ah, Al, Bh, Bl,
                                m0, n0, (kc+2)*64, K);
            CP_COMMIT();
        }

        const uint32_t SB = sb + s_cur*STG;
        const uint32_t AH = SB, AL = SB + 18432;
        const uint32_t BH = SB + 36864, BL = SB + 36864 + NT*144;
        #pragma unroll
        for (int ks = 0; ks < 4; ks++) {
            uint32_t aH[2][4], aL[2][4];
            #pragma unroll
            for (int ra = 0; ra < 2; ra++) {
                uint32_t off = (uint32_t)(wm + ra*16 + (l & 15))*144 + (ks*16 + (l >> 4)*8)*2;
                ldm4(aH[ra], AH + off);
                ldm4(aL[ra], AL + off);
            }
            #pragma unroll
            for (int g = 0; g < G; g++) {
                uint32_t bH[4], bL[4];
                uint32_t off = (uint32_t)(wn + g*16 + (l & 7) + ((l >> 4) << 3))*144
                             + (ks*16 + ((l >> 3) & 1)*8)*2;
                ldm4(bH, BH + off); ldm4(bL, BL + off);
                mma16816(acc[0][2*g],   aH[0], &bH[0]);
                mma16816(acc[0][2*g+1], aH[0], &bH[2]);
                mma16816(acc[1][2*g],   aH[1], &bH[0]);
                mma16816(acc[1][2*g+1], aH[1], &bH[2]);
                mma16816(acc[0][2*g],   aH[0], &bL[0]);
                mma16816(acc[0][2*g+1], aH[0], &bL[2]);
                mma16816(acc[1][2*g],   aH[1], &bL[0]);
                mma16816(acc[1][2*g+1], aH[1], &bL[2]);
                mma16816(acc[0][2*g],   aL[0], &bH[0]);
                mma16816(acc[0][2*g+1], aL[0], &bH[2]);
                mma16816(acc[1][2*g],   aL[1], &bH[0]);
                mma16816(acc[1][2*g+1], aL[1], &bH[2]);
            }
        }
        s_cur = (s_cur == 2) ? 0 : s_cur + 1;
        s_pre = (s_pre == 2) ? 0 : s_pre + 1;
    }

    #pragma unroll
    for (int ra = 0; ra < 2; ra++)
        #pragma unroll
        for (int na = 0; na < 2*G; na++) {
            int n = n0 + wn + na*8 + 2*(l & 3);
            #pragma unroll
            for (int half = 0; half < 2; half++) {
                int m = m0 + wm + ra*16 + (l >> 2) + half*8;
                float2 v = make_float2(acc[ra][na][half*2], acc[ra][na][half*2 + 1]);
                if (MODE == 0) {
                    *(float2*)&Cf[(size_t)m*N + n] = v;
                } else {
                    if (MODE == 2) { v.x = fmaxf(v.x, 0.f); v.y = fmaxf(v.y, 0.f); }
                    uint32_t hh, ll; split2(v.x, v.y, hh, ll);
                    size_t off;
                    if (MODE == 1) {
                        int sel = n >> 9, n2 = n & 511;
                        int h = n2 >> 6, dk = n2 & 63;
                        int b = m >> 10, s = m & 1023;
                        off = (size_t)sel*MROWS*DMODEL
                            + ((size_t)((b*NHEADS + h)*SEQ + s))*DK + dk;
                    } else {
                        off = (size_t)m*N + n;
                    }
                    *(uint32_t*)&Ch[off] = hh;
                    *(uint32_t*)&Cl[off] = ll;
                }
            }
        }
}

#define GEMM_SMEM_128 (3*(36864 + 128*288))   // 221184
#define GEMM_SMEM_64  (3*(36864 +  64*288))   // 165888

// ---------------- single-pass HMMA attention, K double-buffered ------------------
#define ATTN_SMEM 221184

__global__ __launch_bounds__(256) void attn_kernel(
        const int* __restrict__ tok, float* __restrict__ attn_out,
        float* __restrict__ rinv_g, int layer) {
    extern __shared__ char sm[];
    const uint32_t sb = smem_u32(sm);
    const uint32_t QH = sb,           QL = sb + 18432;
    const uint32_t VH = sb + 110592,  VL = sb + 129024;
    const uint32_t PH = sb + 147456,  PL = sb + 182272;
    char* cPH = sm + 147456;  char* cPL = sm + 182272;
    float* mskS = (float*)(sm + 217088);   // 1024 floats

    int t = threadIdx.x, l = t & 31, wid = t >> 5;
    int qb = blockIdx.x, h = blockIdx.y, b = blockIdx.z;
    int q0 = qb * 128;
    size_t hoff = ((size_t)(b*NHEADS + h)*SEQ)*DK;
    const __nv_bfloat16* qh = g_qh + hoff + (size_t)q0*DK;
    const __nv_bfloat16* ql = g_ql + hoff + (size_t)q0*DK;
    const __nv_bfloat16* kh = g_qh + (size_t)MROWS*DMODEL + hoff;
    const __nv_bfloat16* kl = g_ql + (size_t)MROWS*DMODEL + hoff;
    const __nv_bfloat16* vh = kh + (size_t)MROWS*DMODEL;
    const __nv_bfloat16* vl = kl + (size_t)MROWS*DMODEL;

    for (int j = t; j < SEQ; j += 256)
        mskS[j] = (tok[b*SEQ + j] == 0) ? 1.f : 0.f;
    #pragma unroll
    for (int i = 0; i < 4; i++) {                 // Q + K(0) prologue
        int seg = i*256 + t, r = seg >> 3, c = seg & 7;
        uint32_t so = (uint32_t)r*144 + c*16;
        cpa16(QH + so, qh + (size_t)r*64 + c*8);
        cpa16(QL + so, ql + (size_t)r*64 + c*8);
        cpa16(sb + 36864 + so, kh + (size_t)r*64 + c*8);
        cpa16(sb + 55296 + so, kl + (size_t)r*64 + c*8);
    }
    CP_COMMIT(); cp_wait<0>();
    __syncthreads();

    float rs0 = 0.f, rs1 = 0.f;
    float cacc[8][4];
    #pragma unroll
    for (int j = 0; j < 8; j++)
        #pragma unroll
        for (int q = 0; q < 4; q++) cacc[j][q] = 0.f;

    int r0 = wid*16 + (l >> 2);
    long long abase = ((((long long)layer*BATCH + b)*NHEADS + h)*SEQ + q0)
                      * (long long)SEQ;

    for (int kc = 0; kc < 8; kc++) {
        const uint32_t KHc = sb + 36864 + (uint32_t)(kc & 1)*36864;
        const uint32_t KLc = KHc + 18432;
        #pragma unroll
        for (int i = 0; i < 4; i++) {
            int seg = i*256 + t, r = seg >> 3, c = seg & 7;
            uint32_t so = (uint32_t)r*144 + c*16;
            cpa16(VH + so, vh + (size_t)(kc*128 + r)*64 + c*8);
            cpa16(VL + so, vl + (size_t)(kc*128 + r)*64 + c*8);
        }
        CP_COMMIT();
        if (kc < 7) {
            const uint32_t KHn = sb + 36864 + (uint32_t)((kc+1) & 1)*36864;
            #pragma unroll
            for (int i = 0; i < 4; i++) {
                int seg = i*256 + t, r = seg >> 3, c = seg & 7;
                uint32_t so = (uint32_t)r*144 + c*16;
                cpa16(KHn + so,         kh + (size_t)((kc+1)*128 + r)*64 + c*8);
                cpa16(KHn + 18432 + so, kl + (size_t)((kc+1)*128 + r)*64 + c*8);
            }
            CP_COMMIT();
        }

        // ---- QK on resident K(kc) ----
        float sacc[16][4];
        #pragma unroll
        for (int j = 0; j < 16; j++)
            #pragma unroll
            for (int q = 0; q < 4; q++) sacc[j][q] = 0.f;

        #pragma unroll
        for (int ks = 0; ks < 4; ks++) {
            uint32_t aH[4], aL[4];
            uint32_t aoff = (uint32_t)(wid*16 + (l & 15))*144 + (ks*16 + (l >> 4)*8)*2;
            ldm4(aH, QH + aoff); ldm4(aL, QL + aoff);
            #pragma unroll
            for (int gp = 0; gp < 4; gp++) {
                int g0 = 2*gp, g1 = g0 + 1;
                uint32_t b0H[4], b0L[4], b1H[4], b1L[4];
                uint32_t bo0 = (uint32_t)(g0*16 + (l & 7) + ((l >> 4) << 3))*144
                             + (ks*16 + ((l >> 3) & 1)*8)*2;
                uint32_t bo1 = (uint32_t)(g1*16 + (l & 7) + ((l >> 4) << 3))*144
                             + (ks*16 + ((l >> 3) & 1)*8)*2;
                ldm4(b0H, KHc + bo0); ldm4(b0L, KLc + bo0);
                ldm4(b1H, KHc + bo1); ldm4(b1L, KLc + bo1);
                mma16816(sacc[2*g0],   aH, &b0H[0]);
                mma16816(sacc[2*g0+1], aH, &b0H[2]);
                mma16816(sacc[2*g1],   aH, &b1H[0]);
                mma16816(sacc[2*g1+1], aH, &b1H[2]);
                mma16816(sacc[2*g0],   aH, &b0L[0]);
                mma16816(sacc[2*g0+1], aH, &b0L[2]);
                mma16816(sacc[2*g1],   aH, &b1L[0]);
                mma16816(sacc[2*g1+1], aH, &b1L[2]);
                mma16816(sacc[2*g0],   aL, &b0H[0]);
                mma16816(sacc[2*g0+1], aL, &b0H[2]);
                mma16816(sacc[2*g1],   aL, &b1H[0]);
                mma16816(sacc[2*g1+1], aL, &b1H[2]);
            }
        }

        // ---- exp, rowsum, attn write, P split -> smem ----
        #pragma unroll
        for (int na = 0; na < 16; na++) {
            float e[4];
            #pragma unroll
            for (int j = 0; j < 4; j++) {
                int col = kc*128 + na*8 + 2*(l & 3) + (j & 1);
                e[j] = (mskS[col] != 0.f) ? 0.f : __expf(sacc[na][j]*0.125f);
            }
            rs0 += e[0] + e[1];
            rs1 += e[2] + e[3];
            int c0 = kc*128 + na*8 + 2*(l & 3);
            if (attn_out) {
                *(float2*)&attn_out[abase + (long long)r0*SEQ + c0]
                    = make_float2(e[0], e[1]);
                *(float2*)&attn_out[abase + (long long)(r0 + 8)*SEQ + c0]
                    = make_float2(e[2], e[3]);
            }
            uint32_t h01, l01, h23, l23;
            split2(e[0], e[1], h01, l01);
            split2(e[2], e[3], h23, l23);
            int pc = na*8 + 2*(l & 3);
            *(uint32_t*)(cPH + r0*272 + pc*2)     = h01;
            *(uint32_t*)(cPL + r0*272 + pc*2)     = l01;
            *(uint32_t*)(cPH + (r0+8)*272 + pc*2) = h23;
            *(uint32_t*)(cPL + (r0+8)*272 + pc*2) = l23;
        }

        if (kc < 7) cp_wait<1>(); else cp_wait<0>();   // V ready
        __syncthreads();                                // V + P visible

        // ---- PV ----
        #pragma unroll
        for (int ks = 0; ks < 8; ks++) {
            uint32_t pH[4], pL[4];
            uint32_t poff = (uint32_t)(wid*16 + (l & 15))*272 + (ks*16 + (l >> 4)*8)*2;
            ldm4(pH, PH + poff); ldm4(pL, PL + poff);
            #pragma unroll
            for (int gp = 0; gp < 2; gp++) {
                int g0 = 2*gp, g1 = g0 + 1;
                uint32_t v0H[4], v0L[4], v1H[4], v1L[4];
                uint32_t vo0 = (uint32_t)(ks*16 + (l & 15))*144 + (g0*16 + ((l >> 4) << 3))*2;
                uint32_t vo1 = (uint32_t)(ks*16 + (l & 15))*144 + (g1*16 + ((l >> 4) << 3))*2;
                ldm4t(v0H, VH + vo0); ldm4t(v0L, VL + vo0);
                ldm4t(v1H, VH + vo1); ldm4t(v1L, VL + vo1);
                mma16816(cacc[2*g0],   pH, &v0H[0]);
                mma16816(cacc[2*g0+1], pH, &v0H[2]);
                mma16816(cacc[2*g1],   pH, &v1H[0]);
                mma16816(cacc[2*g1+1], pH, &v1H[2]);
                mma16816(cacc[2*g0],   pH, &v0L[0]);
                mma16816(cacc[2*g0+1], pH, &v0L[2]);
                mma16816(cacc[2*g1],   pH, &v1L[0]);
                mma16816(cacc[2*g1+1], pH, &v1L[2]);
                mma16816(cacc[2*g0],   pL, &v0H[0]);
                mma16816(cacc[2*g0+1], pL, &v0H[2]);
                mma16816(cacc[2*g1],   pL, &v1H[0]);
                mma16816(cacc[2*g1+1], pL, &v1H[2]);
            }
        }

        cp_wait<0>();      // K(kc+1) complete
        __syncthreads();
    }

    rs0 += __shfl_xor_sync(0xffffffffu, rs0, 1);
    rs0 += __shfl_xor_sync(0xffffffffu, rs0, 2);
    rs1 += __shfl_xor_sync(0xffffffffu, rs1, 1);
    rs1 += __shfl_xor_sync(0xffffffffu, rs1, 2);
    float inv0 = 1.f / rs0, inv1 = 1.f / rs1;
    if ((l & 3) == 0) {
        size_t rb = ((size_t)(layer*BATCH + b)*NHEADS + h)*SEQ + q0;
        rinv_g[rb + r0]     = inv0;
        rinv_g[rb + r0 + 8] = inv1;
    }
    #pragma unroll
    for (int na = 0; na < 8; na++) {
        int d = na*8 + 2*(l & 3);
        size_t o = ((size_t)(b*SEQ + q0 + r0))*DMODEL + h*DK + d;
        uint32_t h0, l0, h1, l1;
        split2(cacc[na][0]*inv0, cacc[na][1]*inv0, h0, l0);
        split2(cacc[na][2]*inv1, cacc[na][3]*inv1, h1, l1);
        *(uint32_t*)&g_ch[o]            = h0;
        *(uint32_t*)&g_cl[o]            = l0;
        *(uint32_t*)&g_ch[o + 8*DMODEL] = h1;
        *(uint32_t*)&g_cl[o + 8*DMODEL] = l1;
    }
}

// ---------------- normalize one layer's attention in place ----------------------
__global__ void attn_scale_kernel(float* __restrict__ attn,
                                  const float* __restrict__ rinv) {
    size_t i4 = ((size_t)blockIdx.x*256 + threadIdx.x) * 4;
    float inv = __ldg(&rinv[i4 >> 10]);
    float4 v = *(float4*)&attn[i4];
    v.x *= inv; v.y *= inv; v.z *= inv; v.w *= inv;
    *(float4*)&attn[i4] = v;
}

// ---------------- x = LayerNorm(y + x), writes x fp32 + hi/lo -------------------
__global__ __launch_bounds__(128) void add_ln_kernel(
        const float* __restrict__ y, float* __restrict__ x,
        __nv_bfloat16* __restrict__ xh, __nv_bfloat16* __restrict__ xl) {
    int row = blockIdx.x;
    int t   = threadIdx.x;
    const float* yr = y + (size_t)row*DMODEL;
    float*       xr = x + (size_t)row*DMODEL;
    float4 a = *(const float4*)&xr[t*4];
    float4 c = *(const float4*)&yr[t*4];
    float v[4] = {a.x + c.x, a.y + c.y, a.z + c.z, a.w + c.w};
    float s = v[0]+v[1]+v[2]+v[3];
    float s2 = v[0]*v[0]+v[1]*v[1]+v[2]*v[2]+v[3]*v[3];
    #pragma unroll
    for (int o = 16; o; o >>= 1) {
        s  += __shfl_xor_sync(0xffffffffu, s,  o);
        s2 += __shfl_xor_sync(0xffffffffu, s2, o);
    }
    __shared__ float sh[8];
    int w = t >> 5;
    if ((t & 31) == 0) { sh[w] = s; sh[4 + w] = s2; }
    __syncthreads();
    s  = sh[0] + sh[1] + sh[2] + sh[3];
    s2 = sh[4] + sh[5] + sh[6] + sh[7];
    float mean = s * (1.f/DMODEL);
    float var  = s2 * (1.f/DMODEL) - mean*mean;
    float invs = rsqrtf(var + 1e-5f);
    float o0 = (v[0]-mean)*invs, o1 = (v[1]-mean)*invs;
    float o2 = (v[2]-mean)*invs, o3 = (v[3]-mean)*invs;
    *(float4*)&xr[t*4] = make_float4(o0, o1, o2, o3);
    uint32_t h0, l0, h1, l1;
    split2(o0, o1, h0, l0); split2(o2, o3, h1, l1);
    size_t ob = (size_t)row*DMODEL + t*4;
    *(uint32_t*)&xh[ob]     = h0;  *(uint32_t*)&xl[ob]     = l0;
    *(uint32_t*)&xh[ob + 2] = h1;  *(uint32_t*)&xl[ob + 2] = l1;
}

__global__ void copy_x_kernel(float* __restrict__ out) {
    int i = blockIdx.x*256 + threadIdx.x;
    if (i < MROWS*DMODEL) out[i] = g_x[i];
}

// ---------------- driver ---------------------------------------------------------
extern "C" void kernel_launch(void* const* d_in, const int* in_sizes, int n_in,
                              void* d_out, int out_size) {
    const int*   tok = (const int*)  d_in[0];
    const float* emb = (const float*)d_in[1];
    const float* Wq  = (const float*)d_in[2];
    const float* Wk  = (const float*)d_in[3];
    const float* Wv  = (const float*)d_in[4];
    const float* Wo  = (const float*)d_in[5];
    const float* W1  = (const float*)d_in[6];
    const float* W2  = (const float*)d_in[7];
    float* out = (float*)d_out;

    float* attn_base = out + MROWS*DMODEL;
    bool   write_x   = true;
    if (out_size == MROWS*DMODEL)   { attn_base = nullptr; }
    else if (out_size == 201326592) { attn_base = out; write_x = false; }

    float *px, *py, *prinv;
    cudaGetSymbolAddress((void**)&px, g_x);
    cudaGetSymbolAddress((void**)&py, g_y);
    cudaGetSymbolAddress((void**)&prinv, g_rinv);
    __nv_bfloat16 *xh, *xl, *qh, *ql, *ch, *cl, *fh, *fl, *whi, *wlo;
    cudaGetSymbolAddress((void**)&xh, g_xh);
    cudaGetSymbolAddress((void**)&xl, g_xl);
    cudaGetSymbolAddress((void**)&qh, g_qh);
    cudaGetSymbolAddress((void**)&ql, g_ql);
    cudaGetSymbolAddress((void**)&ch, g_ch);
    cudaGetSymbolAddress((void**)&cl, g_cl);
    cudaGetSymbolAddress((void**)&fh, g_fh);
    cudaGetSymbolAddress((void**)&fl, g_fl);
    cudaGetSymbolAddress((void**)&whi, g_whi);
    cudaGetSymbolAddress((void**)&wlo, g_wlo);

    cudaFuncSetAttribute(attn_kernel, cudaFuncAttributeMaxDynamicSharedMemorySize, ATTN_SMEM);
    cudaFuncSetAttribute((mma_gemm<1,128>), cudaFuncAttributeMaxDynamicSharedMemorySize, GEMM_SMEM_128);
    cudaFuncSetAttribute((mma_gemm<0,128>), cudaFuncAttributeMaxDynamicSharedMemorySize, GEMM_SMEM_128);
    cudaFuncSetAttribute((mma_gemm<2,64>),  cudaFuncAttributeMaxDynamicSharedMemorySize, GEMM_SMEM_64);

    // ---- side stream (fresh per call). Fallback: everything on main stream. ----
    cudaStream_t side = 0;
    cudaEvent_t evFork[NLAYERS], evJoin, evW, evInit;
    bool useSide = true;
    if (cudaStreamCreateWithFlags(&side, cudaStreamNonBlocking) != cudaSuccess)
        useSide = false;
    if (useSide) {
        for (int l = 0; l < NLAYERS && useSide; l++)
            if (cudaEventCreateWithFlags(&evFork[l], cudaEventDisableTiming) != cudaSuccess)
                useSide = false;
        if (useSide && cudaEventCreateWithFlags(&evJoin, cudaEventDisableTiming) != cudaSuccess)
            useSide = false;
        if (useSide && cudaEventCreateWithFlags(&evW, cudaEventDisableTiming) != cudaSuccess)
            useSide = false;
        if (useSide && cudaEventCreateWithFlags(&evInit, cudaEventDisableTiming) != cudaSuccess)
            useSide = false;
    }

    // embed on main first (also the capture-origin event for the side stream)
    embed_kernel<<<(MROWS*DMODEL/2 + 255)/256, 256>>>(tok, emb);
    if (useSide) {
        // side stream must join the capture via an event from the capturing
        // stream BEFORE any work is launched on it
        cudaEventRecord(evInit, 0);
        cudaStreamWaitEvent(side, evInit, 0);
    }
    {
        dim3 g4(16, 16, 4*NLAYERS);
        wconv4_kernel<<<g4, 256>>>(Wq, Wk, Wv, Wo, whi, wlo);
        dim3 g1(64, 16, NLAYERS);
        dim3 g2(16, 64, NLAYERS);
        cudaStream_t ws = useSide ? side : 0;
        wconv_kernel<<<g1, 256, 0, ws>>>(W1, whi + WOFF_1, wlo + WOFF_1, 512, 2048,
                                         (long)DMODEL*DFFN, (long)WL_STRIDE);
        wconv_kernel<<<g2, 256, 0, ws>>>(W2, whi + WOFF_2, wlo + WOFF_2, 2048, 512,
                                         (long)DFFN*DMODEL, (long)WL_STRIDE);
        if (useSide) cudaEventRecord(evW, side);
    }

    dim3 gQKV(12, 32);    // N=1536, NT=128
    dim3 gO(4, 32);       // N=512,  NT=128
    dim3 gF1(32, 32);     // N=2048, NT=64  -> 1024 CTAs
    dim3 gAttn(SEQ/128, NHEADS, BATCH);
    const unsigned gScale = (unsigned)(ALSTRIDE/1024);

    for (int l = 0; l < NLAYERS; l++) {
        const __nv_bfloat16* wh = whi + (size_t)l*WL_STRIDE;
        const __nv_bfloat16* wl = wlo + (size_t)l*WL_STRIDE;

        mma_gemm<1,128><<<gQKV, 256, GEMM_SMEM_128>>>(xh, xl, wh + WOFF_QKV, wl + WOFF_QKV,
                                                      nullptr, qh, ql, 1536, 512);
        attn_kernel<<<gAttn, 256, ATTN_SMEM>>>(tok, attn_base, prinv, l);

        if (attn_base) {
            float* al = attn_base + (long long)l*ALSTRIDE;
            const float* rl = prinv + (size_t)l*BATCH*NHEADS*SEQ;
            if (useSide) {
                cudaEventRecord(evFork[l], 0);
                cudaStreamWaitEvent(side, evFork[l], 0);
                attn_scale_kernel<<<gScale, 256, 0, side>>>(al, rl);
            } else {
                attn_scale_kernel<<<gScale, 256>>>(al, rl);
            }
        }

        mma_gemm<0,128><<<gO, 256, GEMM_SMEM_128>>>(ch, cl, wh + WOFF_O, wl + WOFF_O,
                                                    py, nullptr, nullptr, 512, 512);
        add_ln_kernel<<<MROWS, 128>>>(py, px, xh, xl);

        if (l == 0 && useSide)                 // FFN weights must be ready
            cudaStreamWaitEvent(0, evW, 0);

        mma_gemm<2,64><<<gF1, 256, GEMM_SMEM_64>>>(xh, xl, wh + WOFF_1, wl + WOFF_1,
                                                   nullptr, fh, fl, 2048, 512);
        mma_gemm<0,128><<<gO, 256, GEMM_SMEM_128>>>(fh, fl, wh + WOFF_2, wl + WOFF_2,
                                                    py, nullptr, nullptr, 512, 2048);
        add_ln_kernel<<<MROWS, 128>>>(py, px, xh, xl);
    }

    // copy_x is independent of attn normalization — launch before the join
    if (write_x)
        copy_x_kernel<<<(MROWS*DMODEL + 255)/256, 256>>>(out);

    if (useSide) {          // join side stream back into the captured main stream
        cudaEventRecord(evJoin, side);
        cudaStreamWaitEvent(0, evJoin, 0);
    }
}

// round 12
// speedup vs baseline: 1.0002x; 1.0002x over previous
#include <cuda_runtime.h>
#include <cuda_bf16.h>
#include <cstdint>

#define BATCH   4
#define SEQ     1024
#define DMODEL  512
#define NHEADS  8
#define DK      64
#define NLAYERS 6
#define DFFN    2048
#define MROWS   (BATCH*SEQ)   // 4096
#define ALSTRIDE ((long long)BATCH*NHEADS*SEQ*SEQ)   // attn layer stride

// ---------------- scratch (device globals) -------------------------------------
__device__ float g_x  [MROWS*DMODEL];     // residual stream (fp32)
__device__ float g_y  [MROWS*DMODEL];     // gemm fp32 out (pre-LN)
__device__ float g_rinv[NLAYERS*BATCH*NHEADS*SEQ];                    // 1/rowsum
__device__ __nv_bfloat16 g_xh[MROWS*DMODEL],  g_xl[MROWS*DMODEL];    // x split
__device__ __nv_bfloat16 g_qh[3*MROWS*DMODEL], g_ql[3*MROWS*DMODEL]; // q|k|v split
__device__ __nv_bfloat16 g_ch[MROWS*DMODEL],  g_cl[MROWS*DMODEL];    // ctx split
__device__ __nv_bfloat16 g_fh[MROWS*DFFN],    g_fl[MROWS*DFFN];      // ffn split

// bf16 split transposed weights Wt[n][k]: qkv(1536x512)|o(512x512)|w1(2048x512)|w2(512x2048)
#define WL_STRIDE 3145728
#define WOFF_QKV  0
#define WOFF_O    786432
#define WOFF_1    1048576
#define WOFF_2    2097152
__device__ __nv_bfloat16 g_whi[NLAYERS*WL_STRIDE];
__device__ __nv_bfloat16 g_wlo[NLAYERS*WL_STRIDE];

// ---------------- helpers -------------------------------------------------------
__device__ __forceinline__ uint32_t smem_u32(const void* p) {
    uint32_t a;
    asm("{ .reg .u64 t; cvta.to.shared.u64 t, %1; cvt.u32.u64 %0, t; }" : "=r"(a) : "l"(p));
    return a;
}
__device__ __forceinline__ void ldm4(uint32_t* r, uint32_t a) {
    asm volatile("ldmatrix.sync.aligned.m8n8.x4.shared.b16 {%0,%1,%2,%3}, [%4];"
        : "=r"(r[0]), "=r"(r[1]), "=r"(r[2]), "=r"(r[3]) : "r"(a));
}
__device__ __forceinline__ void ldm4t(uint32_t* r, uint32_t a) {
    asm volatile("ldmatrix.sync.aligned.m8n8.x4.trans.shared.b16 {%0,%1,%2,%3}, [%4];"
        : "=r"(r[0]), "=r"(r[1]), "=r"(r[2]), "=r"(r[3]) : "r"(a));
}
__device__ __forceinline__ void mma16816(float* d, const uint32_t* a, const uint32_t* b) {
    asm volatile("mma.sync.aligned.m16n8k16.row.col.f32.bf16.bf16.f32 "
        "{%0,%1,%2,%3}, {%4,%5,%6,%7}, {%8,%9}, {%0,%1,%2,%3};"
        : "+f"(d[0]), "+f"(d[1]), "+f"(d[2]), "+f"(d[3])
        : "r"(a[0]), "r"(a[1]), "r"(a[2]), "r"(a[3]), "r"(b[0]), "r"(b[1]));
}
__device__ __forceinline__ void split2(float x, float y, uint32_t& hi, uint32_t& lo) {
    __nv_bfloat162 h = __floats2bfloat162_rn(x, y);
    float hx = __bfloat162float(h.x), hy = __bfloat162float(h.y);
    __nv_bfloat162 l2 = __floats2bfloat162_rn(x - hx, y - hy);
    hi = *(uint32_t*)&h;
    lo = *(uint32_t*)&l2;
}
__device__ __forceinline__ void cpa16(uint32_t dst, const void* src) {
    asm volatile("cp.async.cg.shared.global [%0], [%1], 16;" :: "r"(dst), "l"(src));
}
#define CP_COMMIT() asm volatile("cp.async.commit_group;" ::: "memory")
template<int N> __device__ __forceinline__ void cp_wait() {
    asm volatile("cp.async.wait_group %0;" :: "n"(N) : "memory");
}

// ---------------- embedding + positional encoding (writes x + split) -----------
__global__ void embed_kernel(const int* __restrict__ tok,
                             const float* __restrict__ emb) {
    int p = blockIdx.x * 256 + threadIdx.x;
    if (p >= MROWS*DMODEL/2) return;
    int idx = p * 2;
    int row = idx >> 9;
    int d   = idx & (DMODEL-1);
    int s   = row & (SEQ-1);
    int tk  = tok[row];
    float freq = expf((float)d * (-9.210340371976184f / (float)DMODEL));
    float ang  = (float)s * freq;
    float v0 = emb[tk*DMODEL + d]     + sinf(ang);
    float v1 = emb[tk*DMODEL + d + 1] + cosf(ang);
    *(float2*)&g_x[idx] = make_float2(v0, v1);
    uint32_t h, l; split2(v0, v1, h, l);
    *(uint32_t*)&g_xh[idx] = h;
    *(uint32_t*)&g_xl[idx] = l;
}

// ---------------- weight transpose + split kernels ------------------------------
__global__ void wconv4_kernel(const float* __restrict__ Wq, const float* __restrict__ Wk,
                              const float* __restrict__ Wv, const float* __restrict__ Wo,
                              __nv_bfloat16* __restrict__ hi, __nv_bfloat16* __restrict__ lo) {
    __shared__ float tl[32][33];
    int z = blockIdx.z, lyr = z >> 2, which = z & 3;
    const float* src;
    size_t doff;
    switch (which) {
        case 0: src = Wq; doff = WOFF_QKV;          break;
        case 1: src = Wk; doff = WOFF_QKV + 262144; break;
        case 2: src = Wv; doff = WOFF_QKV + 524288; break;
        default: src = Wo; doff = WOFF_O;           break;
    }
    src += (size_t)lyr * 262144;
    hi  += (size_t)lyr * WL_STRIDE + doff;
    lo  += (size_t)lyr * WL_STRIDE + doff;
    int n0 = blockIdx.x*32, k0 = blockIdx.y*32;
    int tx = threadIdx.x & 31, tg = threadIdx.x >> 5;
    #pragma unroll
    for (int r = tg; r < 32; r += 8)
        tl[r][tx] = src[(size_t)(k0 + r)*512 + n0 + tx];
    __syncthreads();
    #pragma unroll
    for (int r = tg; r < 32; r += 8) {
        float x = tl[tx][r];
        __nv_bfloat16 h = __float2bfloat16(x);
        size_t o = (size_t)(n0 + r)*512 + k0 + tx;
        hi[o] = h;
        lo[o] = __float2bfloat16(x - __bfloat162float(h));
    }
}

__global__ void wconv_kernel(const float* __restrict__ src,
                             __nv_bfloat16* __restrict__ hi,
                             __nv_bfloat16* __restrict__ lo,
                             int K, int N, long srcStride, long dstStride) {
    __shared__ float tl[32][33];
    int l = blockIdx.z;
    src += (size_t)l * srcStride;
    hi  += (size_t)l * dstStride;
    lo  += (size_t)l * dstStride;
    int n0 = blockIdx.x*32, k0 = blockIdx.y*32;
    int tx = threadIdx.x & 31, tg = threadIdx.x >> 5;
    #pragma unroll
    for (int r = tg; r < 32; r += 8)
        tl[r][tx] = src[(size_t)(k0 + r)*N + n0 + tx];
    __syncthreads();
    #pragma unroll
    for (int r = tg; r < 32; r += 8) {
        float x = tl[tx][r];
        __nv_bfloat16 h = __float2bfloat16(x);
        size_t o = (size_t)(n0 + r)*K + k0 + tx;
        hi[o] = h;
        lo[o] = __float2bfloat16(x - __bfloat162float(h));
    }
}

// ---------------- 2-stage pipelined HMMA GEMM, 2 CTAs/SM ------------------------
// Tile 128x64, 8 warps (4m x 2n), warp tile 32x32. Stage = 55296 B; 2 stages
// = 110592 B -> two CTAs co-resident per SM hide barrier/epilogue bubbles.
#define GSTG      55296
#define GEMM_SMEM (2*GSTG)

__device__ __forceinline__ void gemm_stage_load(
        uint32_t sbase, int t,
        const __nv_bfloat16* Ah, const __nv_bfloat16* Al,
        const __nv_bfloat16* Bh, const __nv_bfloat16* Bl,
        int m0, int n0, int k0, int K) {
    #pragma unroll
    for (int i = 0; i < 4; i++) {                      // A: 128 rows x 8 chunks
        int seg = i*256 + t;
        int r = seg >> 3, c = seg & 7;
        uint32_t so = (uint32_t)r*144 + c*16;
        size_t ga = (size_t)(m0 + r)*K + k0 + c*8;
        cpa16(sbase +         so, Ah + ga);
        cpa16(sbase + 18432 + so, Al + ga);
    }
    #pragma unroll
    for (int i = 0; i < 2; i++) {                      // B: 64 rows x 8 chunks
        int seg = i*256 + t;
        int r = seg >> 3, c = seg & 7;
        uint32_t so = (uint32_t)r*144 + c*16;
        size_t gb = (size_t)(n0 + r)*K + k0 + c*8;
        cpa16(sbase + 36864 + so, Bh + gb);
        cpa16(sbase + 46080 + so, Bl + gb);
    }
}

template<int MODE>
__global__ __launch_bounds__(256, 2) void mma_gemm(
        const __nv_bfloat16* __restrict__ Ah, const __nv_bfloat16* __restrict__ Al,
        const __nv_bfloat16* __restrict__ Bh, const __nv_bfloat16* __restrict__ Bl,
        float* __restrict__ Cf,
        __nv_bfloat16* __restrict__ Ch, __nv_bfloat16* __restrict__ Cl,
        int N, int K) {
    extern __shared__ char sm[];
    const uint32_t sb = smem_u32(sm);
    int t = threadIdx.x, l = t & 31, wid = t >> 5;
    int m0 = blockIdx.y * 128, n0 = blockIdx.x * 64;
    int wm = (wid & 3) * 32, wn = (wid >> 2) * 32;

    float acc[2][4][4];
    #pragma unroll
    for (int i = 0; i < 2; i++)
        #pragma unroll
        for (int j = 0; j < 4; j++)
            #pragma unroll
            for (int q = 0; q < 4; q++) acc[i][j][q] = 0.f;

    const int NK = K >> 6;
    gemm_stage_load(sb, t, Ah, Al, Bh, Bl, m0, n0, 0, K);
    CP_COMMIT();

    for (int kc = 0; kc < NK; kc++) {
        if (kc + 1 < NK) {
            gemm_stage_load(sb + ((kc+1)&1)*GSTG, t, Ah, Al, Bh, Bl,
                            m0, n0, (kc+1)*64, K);
            CP_COMMIT();
            cp_wait<1>();
        } else {
            cp_wait<0>();
        }
        __syncthreads();

        const uint32_t SB = sb + (kc & 1)*GSTG;
        const uint32_t AH = SB, AL = SB + 18432;
        const uint32_t BH = SB + 36864, BL = SB + 46080;
        #pragma unroll
        for (int ks = 0; ks < 4; ks++) {
            uint32_t aH[2][4], aL[2][4];
            #pragma unroll
            for (int ra = 0; ra < 2; ra++) {
                uint32_t off = (uint32_t)(wm + ra*16 + (l & 15))*144 + (ks*16 + (l >> 4)*8)*2;
                ldm4(aH[ra], AH + off);
                ldm4(aL[ra], AL + off);
            }
            #pragma unroll
            for (int g = 0; g < 2; g++) {
                uint32_t bH[4], bL[4];
                uint32_t off = (uint32_t)(wn + g*16 + (l & 7) + ((l >> 4) << 3))*144
                             + (ks*16 + ((l >> 3) & 1)*8)*2;
                ldm4(bH, BH + off); ldm4(bL, BL + off);
                mma16816(acc[0][2*g],   aH[0], &bH[0]);
                mma16816(acc[0][2*g+1], aH[0], &bH[2]);
                mma16816(acc[1][2*g],   aH[1], &bH[0]);
                mma16816(acc[1][2*g+1], aH[1], &bH[2]);
                mma16816(acc[0][2*g],   aH[0], &bL[0]);
                mma16816(acc[0][2*g+1], aH[0], &bL[2]);
                mma16816(acc[1][2*g],   aH[1], &bL[0]);
                mma16816(acc[1][2*g+1], aH[1], &bL[2]);
                mma16816(acc[0][2*g],   aL[0], &bH[0]);
                mma16816(acc[0][2*g+1], aL[0], &bH[2]);
                mma16816(acc[1][2*g],   aL[1], &bH[0]);
                mma16816(acc[1][2*g+1], aL[1], &bH[2]);
            }
        }
        __syncthreads();
    }

    #pragma unroll
    for (int ra = 0; ra < 2; ra++)
        #pragma unroll
        for (int na = 0; na < 4; na++) {
            int n = n0 + wn + na*8 + 2*(l & 3);
            #pragma unroll
            for (int half = 0; half < 2; half++) {
                int m = m0 + wm + ra*16 + (l >> 2) + half*8;
                float2 v = make_float2(acc[ra][na][half*2], acc[ra][na][half*2 + 1]);
                if (MODE == 0) {
                    *(float2*)&Cf[(size_t)m*N + n] = v;
                } else {
                    if (MODE == 2) { v.x = fmaxf(v.x, 0.f); v.y = fmaxf(v.y, 0.f); }
                    uint32_t hh, ll; split2(v.x, v.y, hh, ll);
                    size_t off;
                    if (MODE == 1) {
                        int sel = n >> 9, n2 = n & 511;
                        int h = n2 >> 6, dk = n2 & 63;
                        int b = m >> 10, s = m & 1023;
                        off = (size_t)sel*MROWS*DMODEL
                            + ((size_t)((b*NHEADS + h)*SEQ + s))*DK + dk;
                    } else {
                        off = (size_t)m*N + n;
                    }
                    *(uint32_t*)&Ch[off] = hh;
                    *(uint32_t*)&Cl[off] = ll;
                }
            }
        }
}

// ---------------- single-pass HMMA attention, K double-buffered ------------------
#define ATTN_SMEM 221184

__global__ __launch_bounds__(256) void attn_kernel(
        const int* __restrict__ tok, float* __restrict__ attn_out,
        float* __restrict__ rinv_g, int layer) {
    extern __shared__ char sm[];
    const uint32_t sb = smem_u32(sm);
    const uint32_t QH = sb,           QL = sb + 18432;
    const uint32_t VH = sb + 110592,  VL = sb + 129024;
    const uint32_t PH = sb + 147456,  PL = sb + 182272;
    char* cPH = sm + 147456;  char* cPL = sm + 182272;
    float* mskS = (float*)(sm + 217088);   // 1024 floats

    int t = threadIdx.x, l = t & 31, wid = t >> 5;
    int qb = blockIdx.x, h = blockIdx.y, b = blockIdx.z;
    int q0 = qb * 128;
    size_t hoff = ((size_t)(b*NHEADS + h)*SEQ)*DK;
    const __nv_bfloat16* qh = g_qh + hoff + (size_t)q0*DK;
    const __nv_bfloat16* ql = g_ql + hoff + (size_t)q0*DK;
    const __nv_bfloat16* kh = g_qh + (size_t)MROWS*DMODEL + hoff;
    const __nv_bfloat16* kl = g_ql + (size_t)MROWS*DMODEL + hoff;
    const __nv_bfloat16* vh = kh + (size_t)MROWS*DMODEL;
    const __nv_bfloat16* vl = kl + (size_t)MROWS*DMODEL;

    for (int j = t; j < SEQ; j += 256)
        mskS[j] = (tok[b*SEQ + j] == 0) ? 1.f : 0.f;
    #pragma unroll
    for (int i = 0; i < 4; i++) {                 // Q + K(0) prologue
        int seg = i*256 + t, r = seg >> 3, c = seg & 7;
        uint32_t so = (uint32_t)r*144 + c*16;
        cpa16(QH + so, qh + (size_t)r*64 + c*8);
        cpa16(QL + so, ql + (size_t)r*64 + c*8);
        cpa16(sb + 36864 + so, kh + (size_t)r*64 + c*8);
        cpa16(sb + 55296 + so, kl + (size_t)r*64 + c*8);
    }
    CP_COMMIT(); cp_wait<0>();
    __syncthreads();

    float rs0 = 0.f, rs1 = 0.f;
    float cacc[8][4];
    #pragma unroll
    for (int j = 0; j < 8; j++)
        #pragma unroll
        for (int q = 0; q < 4; q++) cacc[j][q] = 0.f;

    int r0 = wid*16 + (l >> 2);
    long long abase = ((((long long)layer*BATCH + b)*NHEADS + h)*SEQ + q0)
                      * (long long)SEQ;

    for (int kc = 0; kc < 8; kc++) {
        const uint32_t KHc = sb + 36864 + (uint32_t)(kc & 1)*36864;
        const uint32_t KLc = KHc + 18432;
        #pragma unroll
        for (int i = 0; i < 4; i++) {
            int seg = i*256 + t, r = seg >> 3, c = seg & 7;
            uint32_t so = (uint32_t)r*144 + c*16;
            cpa16(VH + so, vh + (size_t)(kc*128 + r)*64 + c*8);
            cpa16(VL + so, vl + (size_t)(kc*128 + r)*64 + c*8);
        }
        CP_COMMIT();
        if (kc < 7) {
            const uint32_t KHn = sb + 36864 + (uint32_t)((kc+1) & 1)*36864;
            #pragma unroll
            for (int i = 0; i < 4; i++) {
                int seg = i*256 + t, r = seg >> 3, c = seg & 7;
                uint32_t so = (uint32_t)r*144 + c*16;
                cpa16(KHn + so,         kh + (size_t)((kc+1)*128 + r)*64 + c*8);
                cpa16(KHn + 18432 + so, kl + (size_t)((kc+1)*128 + r)*64 + c*8);
            }
            CP_COMMIT();
        }

        // ---- QK on resident K(kc) ----
        float sacc[16][4];
        #pragma unroll
        for (int j = 0; j < 16; j++)
            #pragma unroll
            for (int q = 0; q < 4; q++) sacc[j][q] = 0.f;

        #pragma unroll
        for (int ks = 0; ks < 4; ks++) {
            uint32_t aH[4], aL[4];
            uint32_t aoff = (uint32_t)(wid*16 + (l & 15))*144 + (ks*16 + (l >> 4)*8)*2;
            ldm4(aH, QH + aoff); ldm4(aL, QL + aoff);
            #pragma unroll
            for (int gp = 0; gp < 4; gp++) {
                int g0 = 2*gp, g1 = g0 + 1;
                uint32_t b0H[4], b0L[4], b1H[4], b1L[4];
                uint32_t bo0 = (uint32_t)(g0*16 + (l & 7) + ((l >> 4) << 3))*144
                             + (ks*16 + ((l >> 3) & 1)*8)*2;
                uint32_t bo1 = (uint32_t)(g1*16 + (l & 7) + ((l >> 4) << 3))*144
                             + (ks*16 + ((l >> 3) & 1)*8)*2;
                ldm4(b0H, KHc + bo0); ldm4(b0L, KLc + bo0);
                ldm4(b1H, KHc + bo1); ldm4(b1L, KLc + bo1);
                mma16816(sacc[2*g0],   aH, &b0H[0]);
                mma16816(sacc[2*g0+1], aH, &b0H[2]);
                mma16816(sacc[2*g1],   aH, &b1H[0]);
                mma16816(sacc[2*g1+1], aH, &b1H[2]);
                mma16816(sacc[2*g0],   aH, &b0L[0]);
                mma16816(sacc[2*g0+1], aH, &b0L[2]);
                mma16816(sacc[2*g1],   aH, &b1L[0]);
                mma16816(sacc[2*g1+1], aH, &b1L[2]);
                mma16816(sacc[2*g0],   aL, &b0H[0]);
                mma16816(sacc[2*g0+1], aL, &b0H[2]);
                mma16816(sacc[2*g1],   aL, &b1H[0]);
                mma16816(sacc[2*g1+1], aL, &b1H[2]);
            }
        }

        // ---- exp, rowsum, attn write, P split -> smem ----
        #pragma unroll
        for (int na = 0; na < 16; na++) {
            float e[4];
            #pragma unroll
            for (int j = 0; j < 4; j++) {
                int col = kc*128 + na*8 + 2*(l & 3) + (j & 1);
                e[j] = (mskS[col] != 0.f) ? 0.f : __expf(sacc[na][j]*0.125f);
            }
            rs0 += e[0] + e[1];
            rs1 += e[2] + e[3];
            int c0 = kc*128 + na*8 + 2*(l & 3);
            if (attn_out) {
                *(float2*)&attn_out[abase + (long long)r0*SEQ + c0]
                    = make_float2(e[0], e[1]);
                *(float2*)&attn_out[abase + (long long)(r0 + 8)*SEQ + c0]
                    = make_float2(e[2], e[3]);
            }
            uint32_t h01, l01, h23, l23;
            split2(e[0], e[1], h01, l01);
            split2(e[2], e[3], h23, l23);
            int pc = na*8 + 2*(l & 3);
            *(uint32_t*)(cPH + r0*272 + pc*2)     = h01;
            *(uint32_t*)(cPL + r0*272 + pc*2)     = l01;
            *(uint32_t*)(cPH + (r0+8)*272 + pc*2) = h23;
            *(uint32_t*)(cPL + (r0+8)*272 + pc*2) = l23;
        }

        if (kc < 7) cp_wait<1>(); else cp_wait<0>();   // V ready
        __syncthreads();                                // V + P visible

        // ---- PV ----
        #pragma unroll
        for (int ks = 0; ks < 8; ks++) {
            uint32_t pH[4], pL[4];
            uint32_t poff = (uint32_t)(wid*16 + (l & 15))*272 + (ks*16 + (l >> 4)*8)*2;
            ldm4(pH, PH + poff); ldm4(pL, PL + poff);
            #pragma unroll
            for (int gp = 0; gp < 2; gp++) {
                int g0 = 2*gp, g1 = g0 + 1;
                uint32_t v0H[4], v0L[4], v1H[4], v1L[4];
                uint32_t vo0 = (uint32_t)(ks*16 + (l & 15))*144 + (g0*16 + ((l >> 4) << 3))*2;
                uint32_t vo1 = (uint32_t)(ks*16 + (l & 15))*144 + (g1*16 + ((l >> 4) << 3))*2;
                ldm4t(v0H, VH + vo0); ldm4t(v0L, VL + vo0);
                ldm4t(v1H, VH + vo1); ldm4t(v1L, VL + vo1);
                mma16816(cacc[2*g0],   pH, &v0H[0]);
                mma16816(cacc[2*g0+1], pH, &v0H[2]);
                mma16816(cacc[2*g1],   pH, &v1H[0]);
                mma16816(cacc[2*g1+1], pH, &v1H[2]);
                mma16816(cacc[2*g0],   pH, &v0L[0]);
                mma16816(cacc[2*g0+1], pH, &v0L[2]);
                mma16816(cacc[2*g1],   pH, &v1L[0]);
                mma16816(cacc[2*g1+1], pH, &v1L[2]);
                mma16816(cacc[2*g0],   pL, &v0H[0]);
                mma16816(cacc[2*g0+1], pL, &v0H[2]);
                mma16816(cacc[2*g1],   pL, &v1H[0]);
                mma16816(cacc[2*g1+1], pL, &v1H[2]);
            }
        }

        cp_wait<0>();      // K(kc+1) complete
        __syncthreads();
    }

    rs0 += __shfl_xor_sync(0xffffffffu, rs0, 1);
    rs0 += __shfl_xor_sync(0xffffffffu, rs0, 2);
    rs1 += __shfl_xor_sync(0xffffffffu, rs1, 1);
    rs1 += __shfl_xor_sync(0xffffffffu, rs1, 2);
    float inv0 = 1.f / rs0, inv1 = 1.f / rs1;
    if ((l & 3) == 0) {
        size_t rb = ((size_t)(layer*BATCH + b)*NHEADS + h)*SEQ + q0;
        rinv_g[rb + r0]     = inv0;
        rinv_g[rb + r0 + 8] = inv1;
    }
    #pragma unroll
    for (int na = 0; na < 8; na++) {
        int d = na*8 + 2*(l & 3);
        size_t o = ((size_t)(b*SEQ + q0 + r0))*DMODEL + h*DK + d;
        uint32_t h0, l0, h1, l1;
        split2(cacc[na][0]*inv0, cacc[na][1]*inv0, h0, l0);
        split2(cacc[na][2]*inv1, cacc[na][3]*inv1, h1, l1);
        *(uint32_t*)&g_ch[o]            = h0;
        *(uint32_t*)&g_cl[o]            = l0;
        *(uint32_t*)&g_ch[o + 8*DMODEL] = h1;
        *(uint32_t*)&g_cl[o + 8*DMODEL] = l1;
    }
}

// ---------------- normalize one layer's attention in place ----------------------
__global__ void attn_scale_kernel(float* __restrict__ attn,
                                  const float* __restrict__ rinv) {
    size_t i4 = ((size_t)blockIdx.x*256 + threadIdx.x) * 4;
    float inv = __ldg(&rinv[i4 >> 10]);
    float4 v = *(float4*)&attn[i4];
    v.x *= inv; v.y *= inv; v.z *= inv; v.w *= inv;
    *(float4*)&attn[i4] = v;
}

// ---------------- x = LayerNorm(y + x), writes x fp32 + hi/lo -------------------
__global__ __launch_bounds__(128) void add_ln_kernel(
        const float* __restrict__ y, float* __restrict__ x,
        __nv_bfloat16* __restrict__ xh, __nv_bfloat16* __restrict__ xl) {
    int row = blockIdx.x;
    int t   = threadIdx.x;
    const float* yr = y + (size_t)row*DMODEL;
    float*       xr = x + (size_t)row*DMODEL;
    float4 a = *(const float4*)&xr[t*4];
    float4 c = *(const float4*)&yr[t*4];
    float v[4] = {a.x + c.x, a.y + c.y, a.z + c.z, a.w + c.w};
    float s = v[0]+v[1]+v[2]+v[3];
    float s2 = v[0]*v[0]+v[1]*v[1]+v[2]*v[2]+v[3]*v[3];
    #pragma unroll
    for (int o = 16; o; o >>= 1) {
        s  += __shfl_xor_sync(0xffffffffu, s,  o);
        s2 += __shfl_xor_sync(0xffffffffu, s2, o);
    }
    __shared__ float sh[8];
    int w = t >> 5;
    if ((t & 31) == 0) { sh[w] = s; sh[4 + w] = s2; }
    __syncthreads();
    s  = sh[0] + sh[1] + sh[2] + sh[3];
    s2 = sh[4] + sh[5] + sh[6] + sh[7];
    float mean = s * (1.f/DMODEL);
    float var  = s2 * (1.f/DMODEL) - mean*mean;
    float invs = rsqrtf(var + 1e-5f);
    float o0 = (v[0]-mean)*invs, o1 = (v[1]-mean)*invs;
    float o2 = (v[2]-mean)*invs, o3 = (v[3]-mean)*invs;
    *(float4*)&xr[t*4] = make_float4(o0, o1, o2, o3);
    uint32_t h0, l0, h1, l1;
    split2(o0, o1, h0, l0); split2(o2, o3, h1, l1);
    size_t ob = (size_t)row*DMODEL + t*4;
    *(uint32_t*)&xh[ob]     = h0;  *(uint32_t*)&xl[ob]     = l0;
    *(uint32_t*)&xh[ob + 2] = h1;  *(uint32_t*)&xl[ob + 2] = l1;
}

__global__ void copy_x_kernel(float* __restrict__ out) {
    int i = blockIdx.x*256 + threadIdx.x;
    if (i < MROWS*DMODEL) out[i] = g_x[i];
}

// ---------------- driver ---------------------------------------------------------
extern "C" void kernel_launch(void* const* d_in, const int* in_sizes, int n_in,
                              void* d_out, int out_size) {
    const int*   tok = (const int*)  d_in[0];
    const float* emb = (const float*)d_in[1];
    const float* Wq  = (const float*)d_in[2];
    const float* Wk  = (const float*)d_in[3];
    const float* Wv  = (const float*)d_in[4];
    const float* Wo  = (const float*)d_in[5];
    const float* W1  = (const float*)d_in[6];
    const float* W2  = (const float*)d_in[7];
    float* out = (float*)d_out;

    float* attn_base = out + MROWS*DMODEL;
    bool   write_x   = true;
    if (out_size == MROWS*DMODEL)   { attn_base = nullptr; }
    else if (out_size == 201326592) { attn_base = out; write_x = false; }

    float *px, *py, *prinv;
    cudaGetSymbolAddress((void**)&px, g_x);
    cudaGetSymbolAddress((void**)&py, g_y);
    cudaGetSymbolAddress((void**)&prinv, g_rinv);
    __nv_bfloat16 *xh, *xl, *qh, *ql, *ch, *cl, *fh, *fl, *whi, *wlo;
    cudaGetSymbolAddress((void**)&xh, g_xh);
    cudaGetSymbolAddress((void**)&xl, g_xl);
    cudaGetSymbolAddress((void**)&qh, g_qh);
    cudaGetSymbolAddress((void**)&ql, g_ql);
    cudaGetSymbolAddress((void**)&ch, g_ch);
    cudaGetSymbolAddress((void**)&cl, g_cl);
    cudaGetSymbolAddress((void**)&fh, g_fh);
    cudaGetSymbolAddress((void**)&fl, g_fl);
    cudaGetSymbolAddress((void**)&whi, g_whi);
    cudaGetSymbolAddress((void**)&wlo, g_wlo);

    cudaFuncSetAttribute(attn_kernel, cudaFuncAttributeMaxDynamicSharedMemorySize, ATTN_SMEM);
    cudaFuncSetAttribute(mma_gemm<0>, cudaFuncAttributeMaxDynamicSharedMemorySize, GEMM_SMEM);
    cudaFuncSetAttribute(mma_gemm<1>, cudaFuncAttributeMaxDynamicSharedMemorySize, GEMM_SMEM);
    cudaFuncSetAttribute(mma_gemm<2>, cudaFuncAttributeMaxDynamicSharedMemorySize, GEMM_SMEM);

    // ---- side stream used ONLY for attn_scale overlap (round-8 pattern). ----
    cudaStream_t side = 0;
    cudaEvent_t evFork[NLAYERS], evJoin;
    bool useSide = attn_base != nullptr;
    if (useSide && cudaStreamCreateWithFlags(&side, cudaStreamNonBlocking) != cudaSuccess)
        useSide = false;
    if (useSide) {
        for (int l = 0; l < NLAYERS && useSide; l++)
            if (cudaEventCreateWithFlags(&evFork[l], cudaEventDisableTiming) != cudaSuccess)
                useSide = false;
        if (useSide && cudaEventCreateWithFlags(&evJoin, cudaEventDisableTiming) != cudaSuccess)
            useSide = false;
    }

    embed_kernel<<<(MROWS*DMODEL/2 + 255)/256, 256>>>(tok, emb);
    {
        dim3 g4(16, 16, 4*NLAYERS);
        wconv4_kernel<<<g4, 256>>>(Wq, Wk, Wv, Wo, whi, wlo);
        dim3 g1(64, 16, NLAYERS);
        wconv_kernel<<<g1, 256>>>(W1, whi + WOFF_1, wlo + WOFF_1, 512, 2048,
                                  (long)DMODEL*DFFN, (long)WL_STRIDE);
        dim3 g2(16, 64, NLAYERS);
        wconv_kernel<<<g2, 256>>>(W2, whi + WOFF_2, wlo + WOFF_2, 2048, 512,
                                  (long)DFFN*DMODEL, (long)WL_STRIDE);
    }

    dim3 gQKV(24, 32);    // N=1536, 64-wide tiles -> 768 CTAs
    dim3 gO(8, 32);       // N=512  -> 256 CTAs
    dim3 gF1(32, 32);     // N=2048 -> 1024 CTAs
    dim3 gAttn(SEQ/128, NHEADS, BATCH);
    const unsigned gScale = (unsigned)(ALSTRIDE/1024);

    for (int l = 0; l < NLAYERS; l++) {
        const __nv_bfloat16* wh = whi + (size_t)l*WL_STRIDE;
        const __nv_bfloat16* wl = wlo + (size_t)l*WL_STRIDE;

        mma_gemm<1><<<gQKV, 256, GEMM_SMEM>>>(xh, xl, wh + WOFF_QKV, wl + WOFF_QKV,
                                              nullptr, qh, ql, 1536, 512);
        attn_kernel<<<gAttn, 256, ATTN_SMEM>>>(tok, attn_base, prinv, l);

        if (attn_base) {
            float* al = attn_base + (long long)l*ALSTRIDE;
            const float* rl = prinv + (size_t)l*BATCH*NHEADS*SEQ;
            if (useSide) {
                cudaEventRecord(evFork[l], 0);
                cudaStreamWaitEvent(side, evFork[l], 0);
                attn_scale_kernel<<<gScale, 256, 0, side>>>(al, rl);
            } else {
                attn_scale_kernel<<<gScale, 256>>>(al, rl);
            }
        }

        mma_gemm<0><<<gO, 256, GEMM_SMEM>>>(ch, cl, wh + WOFF_O, wl + WOFF_O,
                                            py, nullptr, nullptr, 512, 512);
        add_ln_kernel<<<MROWS, 128>>>(py, px, xh, xl);
        mma_gemm<2><<<gF1, 256, GEMM_SMEM>>>(xh, xl, wh + WOFF_1, wl + WOFF_1,
                                             nullptr, fh, fl, 2048, 512);
        mma_gemm<0><<<gO, 256, GEMM_SMEM>>>(fh, fl, wh + WOFF_2, wl + WOFF_2,
                                            py, nullptr, nullptr, 512, 2048);
        add_ln_kernel<<<MROWS, 128>>>(py, px, xh, xl);
    }

    // copy_x is independent of attn normalization — launch before the join
    if (write_x)
        copy_x_kernel<<<(MROWS*DMODEL + 255)/256, 256>>>(out);

    if (useSide) {          // join side stream back into the captured main stream
        cudaEventRecord(evJoin, side);
        cudaStreamWaitEvent(0, evJoin, 0);
    }
}

// round 13
// speedup vs baseline: 1.1683x; 1.1681x over previous
#include <cuda_runtime.h>
#include <cuda_bf16.h>
#include <cuda_fp16.h>
#include <cstdint>

#define BATCH   4
#define SEQ     1024
#define DMODEL  512
#define NHEADS  8
#define DK      64
#define NLAYERS 6
#define DFFN    2048
#define MROWS   (BATCH*SEQ)   // 4096
#define ALSTRIDE ((long long)BATCH*NHEADS*SEQ*SEQ)   // attn layer stride

// ---------------- scratch (device globals) -------------------------------------
__device__ float g_x  [MROWS*DMODEL];     // residual stream (fp32)
__device__ float g_y  [MROWS*DMODEL];     // gemm fp32 out (pre-LN)
__device__ float g_rinv[NLAYERS*BATCH*NHEADS*SEQ];                    // 1/rowsum
__device__ __half g_xh[MROWS*DMODEL],  g_xl[MROWS*DMODEL];           // x fp16 split
__device__ __nv_bfloat16 g_qh[3*MROWS*DMODEL], g_ql[3*MROWS*DMODEL]; // q|k|v bf16 split
__device__ __half g_ch[MROWS*DMODEL],  g_cl[MROWS*DMODEL];           // ctx fp16 split
__device__ __half g_fh[MROWS*DFFN],    g_fl[MROWS*DFFN];             // ffn fp16 split

// single-fp16 transposed weights Wt[n][k]: qkv(1536x512)|o(512x512)|w1(2048x512)|w2(512x2048)
#define WL_STRIDE 3145728
#define WOFF_QKV  0
#define WOFF_O    786432
#define WOFF_1    1048576
#define WOFF_2    2097152
__device__ __half g_wf[NLAYERS*WL_STRIDE];

// ---------------- helpers -------------------------------------------------------
__device__ __forceinline__ uint32_t smem_u32(const void* p) {
    uint32_t a;
    asm("{ .reg .u64 t; cvta.to.shared.u64 t, %1; cvt.u32.u64 %0, t; }" : "=r"(a) : "l"(p));
    return a;
}
__device__ __forceinline__ void ldm4(uint32_t* r, uint32_t a) {
    asm volatile("ldmatrix.sync.aligned.m8n8.x4.shared.b16 {%0,%1,%2,%3}, [%4];"
        : "=r"(r[0]), "=r"(r[1]), "=r"(r[2]), "=r"(r[3]) : "r"(a));
}
__device__ __forceinline__ void ldm4t(uint32_t* r, uint32_t a) {
    asm volatile("ldmatrix.sync.aligned.m8n8.x4.trans.shared.b16 {%0,%1,%2,%3}, [%4];"
        : "=r"(r[0]), "=r"(r[1]), "=r"(r[2]), "=r"(r[3]) : "r"(a));
}
// bf16 MMA (attention path)
__device__ __forceinline__ void mma16816(float* d, const uint32_t* a, const uint32_t* b) {
    asm volatile("mma.sync.aligned.m16n8k16.row.col.f32.bf16.bf16.f32 "
        "{%0,%1,%2,%3}, {%4,%5,%6,%7}, {%8,%9}, {%0,%1,%2,%3};"
        : "+f"(d[0]), "+f"(d[1]), "+f"(d[2]), "+f"(d[3])
        : "r"(a[0]), "r"(a[1]), "r"(a[2]), "r"(a[3]), "r"(b[0]), "r"(b[1]));
}
// fp16 MMA (linear GEMMs)
__device__ __forceinline__ void mma16816h(float* d, const uint32_t* a, const uint32_t* b) {
    asm volatile("mma.sync.aligned.m16n8k16.row.col.f32.f16.f16.f32 "
        "{%0,%1,%2,%3}, {%4,%5,%6,%7}, {%8,%9}, {%0,%1,%2,%3};"
        : "+f"(d[0]), "+f"(d[1]), "+f"(d[2]), "+f"(d[3])
        : "r"(a[0]), "r"(a[1]), "r"(a[2]), "r"(a[3]), "r"(b[0]), "r"(b[1]));
}
// fp32 pair -> bf16 hi/lo (attention operands)
__device__ __forceinline__ void split2(float x, float y, uint32_t& hi, uint32_t& lo) {
    __nv_bfloat162 h = __floats2bfloat162_rn(x, y);
    float hx = __bfloat162float(h.x), hy = __bfloat162float(h.y);
    __nv_bfloat162 l2 = __floats2bfloat162_rn(x - hx, y - hy);
    hi = *(uint32_t*)&h;
    lo = *(uint32_t*)&l2;
}
// fp32 pair -> fp16 hi/lo (linear-GEMM A operands)
__device__ __forceinline__ void split2h(float x, float y, uint32_t& hi, uint32_t& lo) {
    __half2 h = __floats2half2_rn(x, y);
    float hx = __low2float(h), hy = __high2float(h);
    __half2 l2 = __floats2half2_rn(x - hx, y - hy);
    hi = *(uint32_t*)&h;
    lo = *(uint32_t*)&l2;
}
__device__ __forceinline__ void cpa16(uint32_t dst, const void* src) {
    asm volatile("cp.async.cg.shared.global [%0], [%1], 16;" :: "r"(dst), "l"(src));
}
#define CP_COMMIT() asm volatile("cp.async.commit_group;" ::: "memory")
template<int N> __device__ __forceinline__ void cp_wait() {
    asm volatile("cp.async.wait_group %0;" :: "n"(N) : "memory");
}

// ---------------- embedding + positional encoding (writes x + fp16 split) ------
__global__ void embed_kernel(const int* __restrict__ tok,
                             const float* __restrict__ emb) {
    int p = blockIdx.x * 256 + threadIdx.x;
    if (p >= MROWS*DMODEL/2) return;
    int idx = p * 2;
    int row = idx >> 9;
    int d   = idx & (DMODEL-1);
    int s   = row & (SEQ-1);
    int tk  = tok[row];
    float freq = expf((float)d * (-9.210340371976184f / (float)DMODEL));
    float ang  = (float)s * freq;
    float v0 = emb[tk*DMODEL + d]     + sinf(ang);
    float v1 = emb[tk*DMODEL + d + 1] + cosf(ang);
    *(float2*)&g_x[idx] = make_float2(v0, v1);
    uint32_t h, l; split2h(v0, v1, h, l);
    *(uint32_t*)&g_xh[idx] = h;
    *(uint32_t*)&g_xl[idx] = l;
}

// ---------------- weight transpose + fp16 convert --------------------------------
__global__ void wconv4_kernel(const float* __restrict__ Wq, const float* __restrict__ Wk,
                              const float* __restrict__ Wv, const float* __restrict__ Wo,
                              __half* __restrict__ wf) {
    __shared__ float tl[32][33];
    int z = blockIdx.z, lyr = z >> 2, which = z & 3;
    const float* src;
    size_t doff;
    switch (which) {
        case 0: src = Wq; doff = WOFF_QKV;          break;
        case 1: src = Wk; doff = WOFF_QKV + 262144; break;
        case 2: src = Wv; doff = WOFF_QKV + 524288; break;
        default: src = Wo; doff = WOFF_O;           break;
    }
    src += (size_t)lyr * 262144;
    wf  += (size_t)lyr * WL_STRIDE + doff;
    int n0 = blockIdx.x*32, k0 = blockIdx.y*32;
    int tx = threadIdx.x & 31, tg = threadIdx.x >> 5;
    #pragma unroll
    for (int r = tg; r < 32; r += 8)
        tl[r][tx] = src[(size_t)(k0 + r)*512 + n0 + tx];
    __syncthreads();
    #pragma unroll
    for (int r = tg; r < 32; r += 8)
        wf[(size_t)(n0 + r)*512 + k0 + tx] = __float2half(tl[tx][r]);
}

__global__ void wconv_kernel(const float* __restrict__ src,
                             __half* __restrict__ wf,
                             int K, int N, long srcStride, long dstStride) {
    __shared__ float tl[32][33];
    int l = blockIdx.z;
    src += (size_t)l * srcStride;
    wf  += (size_t)l * dstStride;
    int n0 = blockIdx.x*32, k0 = blockIdx.y*32;
    int tx = threadIdx.x & 31, tg = threadIdx.x >> 5;
    #pragma unroll
    for (int r = tg; r < 32; r += 8)
        tl[r][tx] = src[(size_t)(k0 + r)*N + n0 + tx];
    __syncthreads();
    #pragma unroll
    for (int r = tg; r < 32; r += 8)
        wf[(size_t)(n0 + r)*K + k0 + tx] = __float2half(tl[tx][r]);
}

// ---------------- 3-stage pipelined fp16 2-term GEMM: C = A @ Bt^T --------------
// D = (A_h + A_l) * B_f  (A fp16 split 2-term, B single fp16; error ~A*B_l ~2^-12)
// Tile 128x128, 8 warps (4m x 2n), warp tile 32x64, K-chunks of 64.
#define GSTG      55296
#define GEMM_SMEM (3*GSTG)   // 165888

__device__ __forceinline__ void gemm_stage_load(
        uint32_t sbase, int t,
        const __half* Ah, const __half* Al, const __half* Bf,
        int m0, int n0, int k0, int K) {
    #pragma unroll
    for (int i = 0; i < 4; i++) {
        int seg = i*256 + t;
        int r = seg >> 3, c = seg & 7;
        uint32_t so = (uint32_t)r*144 + c*16;
        size_t ga = (size_t)(m0 + r)*K + k0 + c*8;
        size_t gb = (size_t)(n0 + r)*K + k0 + c*8;
        cpa16(sbase +         so, Ah + ga);
        cpa16(sbase + 18432 + so, Al + ga);
        cpa16(sbase + 36864 + so, Bf + gb);
    }
}

template<int MODE>
__global__ __launch_bounds__(256) void mma_gemm(
        const __half* __restrict__ Ah, const __half* __restrict__ Al,
        const __half* __restrict__ Bf,
        float* __restrict__ Cf,
        uint16_t* __restrict__ Ch, uint16_t* __restrict__ Cl,
        int N, int K) {
    extern __shared__ char sm[];
    const uint32_t sb = smem_u32(sm);
    int t = threadIdx.x, l = t & 31, wid = t >> 5;
    int m0 = blockIdx.y * 128, n0 = blockIdx.x * 128;
    int wm = (wid & 3) * 32, wn = (wid >> 2) * 64;

    float acc[2][8][4];
    #pragma unroll
    for (int i = 0; i < 2; i++)
        #pragma unroll
        for (int j = 0; j < 8; j++)
            #pragma unroll
            for (int q = 0; q < 4; q++) acc[i][j][q] = 0.f;

    const int NK = K >> 6;
    gemm_stage_load(sb, t, Ah, Al, Bf, m0, n0, 0, K);
    CP_COMMIT();
    if (NK > 1) {
        gemm_stage_load(sb + GSTG, t, Ah, Al, Bf, m0, n0, 64, K);
        CP_COMMIT();
    }

    int s_cur = 0, s_pre = 2;
    for (int kc = 0; kc < NK; kc++) {
        if (kc < NK - 1) cp_wait<1>(); else cp_wait<0>();
        __syncthreads();
        if (kc + 2 < NK) {
            gemm_stage_load(sb + s_pre*GSTG, t, Ah, Al, Bf,
                            m0, n0, (kc+2)*64, K);
            CP_COMMIT();
        }

        const uint32_t SB = sb + s_cur*GSTG;
        const uint32_t AH = SB, AL = SB + 18432, BF = SB + 36864;
        #pragma unroll
        for (int ks = 0; ks < 4; ks++) {
            uint32_t aH[2][4], aL[2][4];
            #pragma unroll
            for (int ra = 0; ra < 2; ra++) {
                uint32_t off = (uint32_t)(wm + ra*16 + (l & 15))*144 + (ks*16 + (l >> 4)*8)*2;
                ldm4(aH[ra], AH + off);
                ldm4(aL[ra], AL + off);
            }
            #pragma unroll
            for (int g = 0; g < 4; g++) {
                uint32_t bF[4];
                uint32_t off = (uint32_t)(wn + g*16 + (l & 7) + ((l >> 4) << 3))*144
                             + (ks*16 + ((l >> 3) & 1)*8)*2;
                ldm4(bF, BF + off);
                mma16816h(acc[0][2*g],   aH[0], &bF[0]);
                mma16816h(acc[0][2*g+1], aH[0], &bF[2]);
                mma16816h(acc[1][2*g],   aH[1], &bF[0]);
                mma16816h(acc[1][2*g+1], aH[1], &bF[2]);
                mma16816h(acc[0][2*g],   aL[0], &bF[0]);
                mma16816h(acc[0][2*g+1], aL[0], &bF[2]);
                mma16816h(acc[1][2*g],   aL[1], &bF[0]);
                mma16816h(acc[1][2*g+1], aL[1], &bF[2]);
            }
        }
        s_cur = (s_cur == 2) ? 0 : s_cur + 1;
        s_pre = (s_pre == 2) ? 0 : s_pre + 1;
    }

    #pragma unroll
    for (int ra = 0; ra < 2; ra++)
        #pragma unroll
        for (int na = 0; na < 8; na++) {
            int n = n0 + wn + na*8 + 2*(l & 3);
            #pragma unroll
            for (int half = 0; half < 2; half++) {
                int m = m0 + wm + ra*16 + (l >> 2) + half*8;
                float2 v = make_float2(acc[ra][na][half*2], acc[ra][na][half*2 + 1]);
                if (MODE == 0) {
                    *(float2*)&Cf[(size_t)m*N + n] = v;
                } else {
                    uint32_t hh, ll;
                    size_t off;
                    if (MODE == 1) {                       // q/k/v: bf16 for attn
                        split2(v.x, v.y, hh, ll);
                        int sel = n >> 9, n2 = n & 511;
                        int h = n2 >> 6, dk = n2 & 63;
                        int b = m >> 10, s = m & 1023;
                        off = (size_t)sel*MROWS*DMODEL
                            + ((size_t)((b*NHEADS + h)*SEQ + s))*DK + dk;
                    } else {                               // f: relu + fp16
                        v.x = fmaxf(v.x, 0.f); v.y = fmaxf(v.y, 0.f);
                        split2h(v.x, v.y, hh, ll);
                        off = (size_t)m*N + n;
                    }
                    *(uint32_t*)&Ch[off] = hh;
                    *(uint32_t*)&Cl[off] = ll;
                }
            }
        }
}

// ---------------- single-pass bf16 3-term HMMA attention, K double-buffered ------
#define ATTN_SMEM 221184

__global__ __launch_bounds__(256) void attn_kernel(
        const int* __restrict__ tok, float* __restrict__ attn_out,
        float* __restrict__ rinv_g, int layer) {
    extern __shared__ char sm[];
    const uint32_t sb = smem_u32(sm);
    const uint32_t QH = sb,           QL = sb + 18432;
    const uint32_t VH = sb + 110592,  VL = sb + 129024;
    const uint32_t PH = sb + 147456,  PL = sb + 182272;
    char* cPH = sm + 147456;  char* cPL = sm + 182272;
    float* mskS = (float*)(sm + 217088);   // 1024 floats

    int t = threadIdx.x, l = t & 31, wid = t >> 5;
    int qb = blockIdx.x, h = blockIdx.y, b = blockIdx.z;
    int q0 = qb * 128;
    size_t hoff = ((size_t)(b*NHEADS + h)*SEQ)*DK;
    const __nv_bfloat16* qh = g_qh + hoff + (size_t)q0*DK;
    const __nv_bfloat16* ql = g_ql + hoff + (size_t)q0*DK;
    const __nv_bfloat16* kh = g_qh + (size_t)MROWS*DMODEL + hoff;
    const __nv_bfloat16* kl = g_ql + (size_t)MROWS*DMODEL + hoff;
    const __nv_bfloat16* vh = kh + (size_t)MROWS*DMODEL;
    const __nv_bfloat16* vl = kl + (size_t)MROWS*DMODEL;

    for (int j = t; j < SEQ; j += 256)
        mskS[j] = (tok[b*SEQ + j] == 0) ? 1.f : 0.f;
    #pragma unroll
    for (int i = 0; i < 4; i++) {                 // Q + K(0) prologue
        int seg = i*256 + t, r = seg >> 3, c = seg & 7;
        uint32_t so = (uint32_t)r*144 + c*16;
        cpa16(QH + so, qh + (size_t)r*64 + c*8);
        cpa16(QL + so, ql + (size_t)r*64 + c*8);
        cpa16(sb + 36864 + so, kh + (size_t)r*64 + c*8);
        cpa16(sb + 55296 + so, kl + (size_t)r*64 + c*8);
    }
    CP_COMMIT(); cp_wait<0>();
    __syncthreads();

    float rs0 = 0.f, rs1 = 0.f;
    float cacc[8][4];
    #pragma unroll
    for (int j = 0; j < 8; j++)
        #pragma unroll
        for (int q = 0; q < 4; q++) cacc[j][q] = 0.f;

    int r0 = wid*16 + (l >> 2);
    long long abase = ((((long long)layer*BATCH + b)*NHEADS + h)*SEQ + q0)
                      * (long long)SEQ;

    for (int kc = 0; kc < 8; kc++) {
        const uint32_t KHc = sb + 36864 + (uint32_t)(kc & 1)*36864;
        const uint32_t KLc = KHc + 18432;
        #pragma unroll
        for (int i = 0; i < 4; i++) {
            int seg = i*256 + t, r = seg >> 3, c = seg & 7;
            uint32_t so = (uint32_t)r*144 + c*16;
            cpa16(VH + so, vh + (size_t)(kc*128 + r)*64 + c*8);
            cpa16(VL + so, vl + (size_t)(kc*128 + r)*64 + c*8);
        }
        CP_COMMIT();
        if (kc < 7) {
            const uint32_t KHn = sb + 36864 + (uint32_t)((kc+1) & 1)*36864;
            #pragma unroll
            for (int i = 0; i < 4; i++) {
                int seg = i*256 + t, r = seg >> 3, c = seg & 7;
                uint32_t so = (uint32_t)r*144 + c*16;
                cpa16(KHn + so,         kh + (size_t)((kc+1)*128 + r)*64 + c*8);
                cpa16(KHn + 18432 + so, kl + (size_t)((kc+1)*128 + r)*64 + c*8);
            }
            CP_COMMIT();
        }

        // ---- QK on resident K(kc) ----
        float sacc[16][4];
        #pragma unroll
        for (int j = 0; j < 16; j++)
            #pragma unroll
            for (int q = 0; q < 4; q++) sacc[j][q] = 0.f;

        #pragma unroll
        for (int ks = 0; ks < 4; ks++) {
            uint32_t aH[4], aL[4];
            uint32_t aoff = (uint32_t)(wid*16 + (l & 15))*144 + (ks*16 + (l >> 4)*8)*2;
            ldm4(aH, QH + aoff); ldm4(aL, QL + aoff);
            #pragma unroll
            for (int gp = 0; gp < 4; gp++) {
                int g0 = 2*gp, g1 = g0 + 1;
                uint32_t b0H[4], b0L[4], b1H[4], b1L[4];
                uint32_t bo0 = (uint32_t)(g0*16 + (l & 7) + ((l >> 4) << 3))*144
                             + (ks*16 + ((l >> 3) & 1)*8)*2;
                uint32_t bo1 = (uint32_t)(g1*16 + (l & 7) + ((l >> 4) << 3))*144
                             + (ks*16 + ((l >> 3) & 1)*8)*2;
                ldm4(b0H, KHc + bo0); ldm4(b0L, KLc + bo0);
                ldm4(b1H, KHc + bo1); ldm4(b1L, KLc + bo1);
                mma16816(sacc[2*g0],   aH, &b0H[0]);
                mma16816(sacc[2*g0+1], aH, &b0H[2]);
                mma16816(sacc[2*g1],   aH, &b1H[0]);
                mma16816(sacc[2*g1+1], aH, &b1H[2]);
                mma16816(sacc[2*g0],   aH, &b0L[0]);
                mma16816(sacc[2*g0+1], aH, &b0L[2]);
                mma16816(sacc[2*g1],   aH, &b1L[0]);
                mma16816(sacc[2*g1+1], aH, &b1L[2]);
                mma16816(sacc[2*g0],   aL, &b0H[0]);
                mma16816(sacc[2*g0+1], aL, &b0H[2]);
                mma16816(sacc[2*g1],   aL, &b1H[0]);
                mma16816(sacc[2*g1+1], aL, &b1H[2]);
            }
        }

        // ---- exp, rowsum, attn write, P split -> smem ----
        #pragma unroll
        for (int na = 0; na < 16; na++) {
            float e[4];
            #pragma unroll
            for (int j = 0; j < 4; j++) {
                int col = kc*128 + na*8 + 2*(l & 3) + (j & 1);
                e[j] = (mskS[col] != 0.f) ? 0.f : __expf(sacc[na][j]*0.125f);
            }
            rs0 += e[0] + e[1];
            rs1 += e[2] + e[3];
            int c0 = kc*128 + na*8 + 2*(l & 3);
            if (attn_out) {
                *(float2*)&attn_out[abase + (long long)r0*SEQ + c0]
                    = make_float2(e[0], e[1]);
                *(float2*)&attn_out[abase + (long long)(r0 + 8)*SEQ + c0]
                    = make_float2(e[2], e[3]);
            }
            uint32_t h01, l01, h23, l23;
            split2(e[0], e[1], h01, l01);
            split2(e[2], e[3], h23, l23);
            int pc = na*8 + 2*(l & 3);
            *(uint32_t*)(cPH + r0*272 + pc*2)     = h01;
            *(uint32_t*)(cPL + r0*272 + pc*2)     = l01;
            *(uint32_t*)(cPH + (r0+8)*272 + pc*2) = h23;
            *(uint32_t*)(cPL + (r0+8)*272 + pc*2) = l23;
        }

        if (kc < 7) cp_wait<1>(); else cp_wait<0>();   // V ready
        __syncthreads();                                // V + P visible

        // ---- PV ----
        #pragma unroll
        for (int ks = 0; ks < 8; ks++) {
            uint32_t pH[4], pL[4];
            uint32_t poff = (uint32_t)(wid*16 + (l & 15))*272 + (ks*16 + (l >> 4)*8)*2;
            ldm4(pH, PH + poff); ldm4(pL, PL + poff);
            #pragma unroll
            for (int gp = 0; gp < 2; gp++) {
                int g0 = 2*gp, g1 = g0 + 1;
                uint32_t v0H[4], v0L[4], v1H[4], v1L[4];
                uint32_t vo0 = (uint32_t)(ks*16 + (l & 15))*144 + (g0*16 + ((l >> 4) << 3))*2;
                uint32_t vo1 = (uint32_t)(ks*16 + (l & 15))*144 + (g1*16 + ((l >> 4) << 3))*2;
                ldm4t(v0H, VH + vo0); ldm4t(v0L, VL + vo0);
                ldm4t(v1H, VH + vo1); ldm4t(v1L, VL + vo1);
                mma16816(cacc[2*g0],   pH, &v0H[0]);
                mma16816(cacc[2*g0+1], pH, &v0H[2]);
                mma16816(cacc[2*g1],   pH, &v1H[0]);
                mma16816(cacc[2*g1+1], pH, &v1H[2]);
                mma16816(cacc[2*g0],   pH, &v0L[0]);
                mma16816(cacc[2*g0+1], pH, &v0L[2]);
                mma16816(cacc[2*g1],   pH, &v1L[0]);
                mma16816(cacc[2*g1+1], pH, &v1L[2]);
                mma16816(cacc[2*g0],   pL, &v0H[0]);
                mma16816(cacc[2*g0+1], pL, &v0H[2]);
                mma16816(cacc[2*g1],   pL, &v1H[0]);
                mma16816(cacc[2*g1+1], pL, &v1H[2]);
            }
        }

        cp_wait<0>();      // K(kc+1) complete
        __syncthreads();
    }

    rs0 += __shfl_xor_sync(0xffffffffu, rs0, 1);
    rs0 += __shfl_xor_sync(0xffffffffu, rs0, 2);
    rs1 += __shfl_xor_sync(0xffffffffu, rs1, 1);
    rs1 += __shfl_xor_sync(0xffffffffu, rs1, 2);
    float inv0 = 1.f / rs0, inv1 = 1.f / rs1;
    if ((l & 3) == 0) {
        size_t rb = ((size_t)(layer*BATCH + b)*NHEADS + h)*SEQ + q0;
        rinv_g[rb + r0]     = inv0;
        rinv_g[rb + r0 + 8] = inv1;
    }
    #pragma unroll
    for (int na = 0; na < 8; na++) {
        int d = na*8 + 2*(l & 3);
        size_t o = ((size_t)(b*SEQ + q0 + r0))*DMODEL + h*DK + d;
        uint32_t h0, l0, h1, l1;
        split2h(cacc[na][0]*inv0, cacc[na][1]*inv0, h0, l0);   // ctx -> fp16
        split2h(cacc[na][2]*inv1, cacc[na][3]*inv1, h1, l1);
        *(uint32_t*)&g_ch[o]            = h0;
        *(uint32_t*)&g_cl[o]            = l0;
        *(uint32_t*)&g_ch[o + 8*DMODEL] = h1;
        *(uint32_t*)&g_cl[o + 8*DMODEL] = l1;
    }
}

// ---------------- normalize one layer's attention in place ----------------------
__global__ void attn_scale_kernel(float* __restrict__ attn,
                                  const float* __restrict__ rinv) {
    size_t i4 = ((size_t)blockIdx.x*256 + threadIdx.x) * 4;
    float inv = __ldg(&rinv[i4 >> 10]);
    float4 v = *(float4*)&attn[i4];
    v.x *= inv; v.y *= inv; v.z *= inv; v.w *= inv;
    *(float4*)&attn[i4] = v;
}

// ---------------- x = LayerNorm(y + x), writes x fp32 + fp16 split ---------------
__global__ __launch_bounds__(128) void add_ln_kernel(
        const float* __restrict__ y, float* __restrict__ x,
        __half* __restrict__ xh, __half* __restrict__ xl) {
    int row = blockIdx.x;
    int t   = threadIdx.x;
    const float* yr = y + (size_t)row*DMODEL;
    float*       xr = x + (size_t)row*DMODEL;
    float4 a = *(const float4*)&xr[t*4];
    float4 c = *(const float4*)&yr[t*4];
    float v[4] = {a.x + c.x, a.y + c.y, a.z + c.z, a.w + c.w};
    float s = v[0]+v[1]+v[2]+v[3];
    float s2 = v[0]*v[0]+v[1]*v[1]+v[2]*v[2]+v[3]*v[3];
    #pragma unroll
    for (int o = 16; o; o >>= 1) {
        s  += __shfl_xor_sync(0xffffffffu, s,  o);
        s2 += __shfl_xor_sync(0xffffffffu, s2, o);
    }
    __shared__ float sh[8];
    int w = t >> 5;
    if ((t & 31) == 0) { sh[w] = s; sh[4 + w] = s2; }
    __syncthreads();
    s  = sh[0] + sh[1] + sh[2] + sh[3];
    s2 = sh[4] + sh[5] + sh[6] + sh[7];
    float mean = s * (1.f/DMODEL);
    float var  = s2 * (1.f/DMODEL) - mean*mean;
    float invs = rsqrtf(var + 1e-5f);
    float o0 = (v[0]-mean)*invs, o1 = (v[1]-mean)*invs;
    float o2 = (v[2]-mean)*invs, o3 = (v[3]-mean)*invs;
    *(float4*)&xr[t*4] = make_float4(o0, o1, o2, o3);
    uint32_t h0, l0, h1, l1;
    split2h(o0, o1, h0, l0); split2h(o2, o3, h1, l1);
    size_t ob = (size_t)row*DMODEL + t*4;
    *(uint32_t*)&xh[ob]     = h0;  *(uint32_t*)&xl[ob]     = l0;
    *(uint32_t*)&xh[ob + 2] = h1;  *(uint32_t*)&xl[ob + 2] = l1;
}

__global__ void copy_x_kernel(float* __restrict__ out) {
    int i = blockIdx.x*256 + threadIdx.x;
    if (i < MROWS*DMODEL) out[i] = g_x[i];
}

// ---------------- driver ---------------------------------------------------------
extern "C" void kernel_launch(void* const* d_in, const int* in_sizes, int n_in,
                              void* d_out, int out_size) {
    const int*   tok = (const int*)  d_in[0];
    const float* emb = (const float*)d_in[1];
    const float* Wq  = (const float*)d_in[2];
    const float* Wk  = (const float*)d_in[3];
    const float* Wv  = (const float*)d_in[4];
    const float* Wo  = (const float*)d_in[5];
    const float* W1  = (const float*)d_in[6];
    const float* W2  = (const float*)d_in[7];
    float* out = (float*)d_out;

    float* attn_base = out + MROWS*DMODEL;
    bool   write_x   = true;
    if (out_size == MROWS*DMODEL)   { attn_base = nullptr; }
    else if (out_size == 201326592) { attn_base = out; write_x = false; }

    float *px, *py, *prinv;
    cudaGetSymbolAddress((void**)&px, g_x);
    cudaGetSymbolAddress((void**)&py, g_y);
    cudaGetSymbolAddress((void**)&prinv, g_rinv);
    __half *xh, *xl, *ch, *cl, *fh, *fl, *wf;
    __nv_bfloat16 *qh, *ql;
    cudaGetSymbolAddress((void**)&xh, g_xh);
    cudaGetSymbolAddress((void**)&xl, g_xl);
    cudaGetSymbolAddress((void**)&qh, g_qh);
    cudaGetSymbolAddress((void**)&ql, g_ql);
    cudaGetSymbolAddress((void**)&ch, g_ch);
    cudaGetSymbolAddress((void**)&cl, g_cl);
    cudaGetSymbolAddress((void**)&fh, g_fh);
    cudaGetSymbolAddress((void**)&fl, g_fl);
    cudaGetSymbolAddress((void**)&wf, g_wf);

    cudaFuncSetAttribute(attn_kernel, cudaFuncAttributeMaxDynamicSharedMemorySize, ATTN_SMEM);
    cudaFuncSetAttribute(mma_gemm<0>, cudaFuncAttributeMaxDynamicSharedMemorySize, GEMM_SMEM);
    cudaFuncSetAttribute(mma_gemm<1>, cudaFuncAttributeMaxDynamicSharedMemorySize, GEMM_SMEM);
    cudaFuncSetAttribute(mma_gemm<2>, cudaFuncAttributeMaxDynamicSharedMemorySize, GEMM_SMEM);

    // ---- side stream used ONLY for attn_scale overlap (round-8 pattern). ----
    cudaStream_t side = 0;
    cudaEvent_t evFork[NLAYERS], evJoin;
    bool useSide = attn_base != nullptr;
    if (useSide && cudaStreamCreateWithFlags(&side, cudaStreamNonBlocking) != cudaSuccess)
        useSide = false;
    if (useSide) {
        for (int l = 0; l < NLAYERS && useSide; l++)
            if (cudaEventCreateWithFlags(&evFork[l], cudaEventDisableTiming) != cudaSuccess)
                useSide = false;
        if (useSide && cudaEventCreateWithFlags(&evJoin, cudaEventDisableTiming) != cudaSuccess)
            useSide = false;
    }

    embed_kernel<<<(MROWS*DMODEL/2 + 255)/256, 256>>>(tok, emb);
    {
        dim3 g4(16, 16, 4*NLAYERS);
        wconv4_kernel<<<g4, 256>>>(Wq, Wk, Wv, Wo, wf);
        dim3 g1(64, 16, NLAYERS);
        wconv_kernel<<<g1, 256>>>(W1, wf + WOFF_1, 512, 2048,
                                  (long)DMODEL*DFFN, (long)WL_STRIDE);
        dim3 g2(16, 64, NLAYERS);
        wconv_kernel<<<g2, 256>>>(W2, wf + WOFF_2, 2048, 512,
                                  (long)DFFN*DMODEL, (long)WL_STRIDE);
    }

    dim3 gQKV(12, 32);    // N=1536
    dim3 gO(4, 32);       // N=512
    dim3 gF1(16, 32);     // N=2048
    dim3 gAttn(SEQ/128, NHEADS, BATCH);
    const unsigned gScale = (unsigned)(ALSTRIDE/1024);

    for (int l = 0; l < NLAYERS; l++) {
        const __half* w = wf + (size_t)l*WL_STRIDE;

        mma_gemm<1><<<gQKV, 256, GEMM_SMEM>>>(xh, xl, w + WOFF_QKV, nullptr,
                                              (uint16_t*)qh, (uint16_t*)ql, 1536, 512);
        attn_kernel<<<gAttn, 256, ATTN_SMEM>>>(tok, attn_base, prinv, l);

        if (attn_base) {
            float* al = attn_base + (long long)l*ALSTRIDE;
            const float* rl = prinv + (size_t)l*BATCH*NHEADS*SEQ;
            if (useSide) {
                cudaEventRecord(evFork[l], 0);
                cudaStreamWaitEvent(side, evFork[l], 0);
                attn_scale_kernel<<<gScale, 256, 0, side>>>(al, rl);
            } else {
                attn_scale_kernel<<<gScale, 256>>>(al, rl);
            }
        }

        mma_gemm<0><<<gO, 256, GEMM_SMEM>>>(ch, cl, w + WOFF_O,
                                            py, nullptr, nullptr, 512, 512);
        add_ln_kernel<<<MROWS, 128>>>(py, px, xh, xl);
        mma_gemm<2><<<gF1, 256, GEMM_SMEM>>>(xh, xl, w + WOFF_1, nullptr,
                                             (uint16_t*)fh, (uint16_t*)fl, 2048, 512);
        mma_gemm<0><<<gO, 256, GEMM_SMEM>>>(fh, fl, w + WOFF_2,
                                            py, nullptr, nullptr, 512, 2048);
        add_ln_kernel<<<MROWS, 128>>>(py, px, xh, xl);
    }

    // copy_x is independent of attn normalization — launch before the join
    if (write_x)
        copy_x_kernel<<<(MROWS*DMODEL + 255)/256, 256>>>(out);

    if (useSide) {          // join side stream back into the captured main stream
        cudaEventRecord(evJoin, side);
        cudaStreamWaitEvent(0, evJoin, 0);
    }
}

// round 14
// speedup vs baseline: 1.1802x; 1.0102x over previous
#include <cuda_runtime.h>
#include <cuda_bf16.h>
#include <cuda_fp16.h>
#include <cstdint>

#define BATCH   4
#define SEQ     1024
#define DMODEL  512
#define NHEADS  8
#define DK      64
#define NLAYERS 6
#define DFFN    2048
#define MROWS   (BATCH*SEQ)   // 4096
#define ALSTRIDE ((long long)BATCH*NHEADS*SEQ*SEQ)   // attn layer stride

// ---------------- scratch (device globals) -------------------------------------
__device__ float g_x  [MROWS*DMODEL];     // residual stream (fp32)
__device__ float g_y  [MROWS*DMODEL];     // gemm fp32 out (pre-LN)
__device__ float g_rinv[NLAYERS*BATCH*NHEADS*SEQ];                    // 1/rowsum
__device__ __half g_xh[MROWS*DMODEL],  g_xl[MROWS*DMODEL];           // x fp16 split
__device__ __nv_bfloat16 g_qh[3*MROWS*DMODEL], g_ql[3*MROWS*DMODEL]; // q|k|v bf16 split
__device__ __half g_ch[MROWS*DMODEL],  g_cl[MROWS*DMODEL];           // ctx fp16 split
__device__ __half g_fh[MROWS*DFFN],    g_fl[MROWS*DFFN];             // ffn fp16 split

// single-fp16 transposed weights Wt[n][k]: qkv(1536x512)|o(512x512)|w1(2048x512)|w2(512x2048)
#define WL_STRIDE 3145728
#define WOFF_QKV  0
#define WOFF_O    786432
#define WOFF_1    1048576
#define WOFF_2    2097152
__device__ __half g_wf[NLAYERS*WL_STRIDE];

// ---------------- helpers -------------------------------------------------------
__device__ __forceinline__ uint32_t smem_u32(const void* p) {
    uint32_t a;
    asm("{ .reg .u64 t; cvta.to.shared.u64 t, %1; cvt.u32.u64 %0, t; }" : "=r"(a) : "l"(p));
    return a;
}
__device__ __forceinline__ void ldm4(uint32_t* r, uint32_t a) {
    asm volatile("ldmatrix.sync.aligned.m8n8.x4.shared.b16 {%0,%1,%2,%3}, [%4];"
        : "=r"(r[0]), "=r"(r[1]), "=r"(r[2]), "=r"(r[3]) : "r"(a));
}
__device__ __forceinline__ void ldm4t(uint32_t* r, uint32_t a) {
    asm volatile("ldmatrix.sync.aligned.m8n8.x4.trans.shared.b16 {%0,%1,%2,%3}, [%4];"
        : "=r"(r[0]), "=r"(r[1]), "=r"(r[2]), "=r"(r[3]) : "r"(a));
}
// bf16 MMA (attention path)
__device__ __forceinline__ void mma16816(float* d, const uint32_t* a, const uint32_t* b) {
    asm volatile("mma.sync.aligned.m16n8k16.row.col.f32.bf16.bf16.f32 "
        "{%0,%1,%2,%3}, {%4,%5,%6,%7}, {%8,%9}, {%0,%1,%2,%3};"
        : "+f"(d[0]), "+f"(d[1]), "+f"(d[2]), "+f"(d[3])
        : "r"(a[0]), "r"(a[1]), "r"(a[2]), "r"(a[3]), "r"(b[0]), "r"(b[1]));
}
// fp16 MMA (linear GEMMs)
__device__ __forceinline__ void mma16816h(float* d, const uint32_t* a, const uint32_t* b) {
    asm volatile("mma.sync.aligned.m16n8k16.row.col.f32.f16.f16.f32 "
        "{%0,%1,%2,%3}, {%4,%5,%6,%7}, {%8,%9}, {%0,%1,%2,%3};"
        : "+f"(d[0]), "+f"(d[1]), "+f"(d[2]), "+f"(d[3])
        : "r"(a[0]), "r"(a[1]), "r"(a[2]), "r"(a[3]), "r"(b[0]), "r"(b[1]));
}
// fp32 pair -> bf16 hi/lo (attention operands)
__device__ __forceinline__ void split2(float x, float y, uint32_t& hi, uint32_t& lo) {
    __nv_bfloat162 h = __floats2bfloat162_rn(x, y);
    float hx = __bfloat162float(h.x), hy = __bfloat162float(h.y);
    __nv_bfloat162 l2 = __floats2bfloat162_rn(x - hx, y - hy);
    hi = *(uint32_t*)&h;
    lo = *(uint32_t*)&l2;
}
// fp32 pair -> fp16 hi/lo (linear-GEMM A operands)
__device__ __forceinline__ void split2h(float x, float y, uint32_t& hi, uint32_t& lo) {
    __half2 h = __floats2half2_rn(x, y);
    float hx = __low2float(h), hy = __high2float(h);
    __half2 l2 = __floats2half2_rn(x - hx, y - hy);
    hi = *(uint32_t*)&h;
    lo = *(uint32_t*)&l2;
}
__device__ __forceinline__ void cpa16(uint32_t dst, const void* src) {
    asm volatile("cp.async.cg.shared.global [%0], [%1], 16;" :: "r"(dst), "l"(src));
}
#define CP_COMMIT() asm volatile("cp.async.commit_group;" ::: "memory")
template<int N> __device__ __forceinline__ void cp_wait() {
    asm volatile("cp.async.wait_group %0;" :: "n"(N) : "memory");
}

// ---------------- embedding + positional encoding (writes x + fp16 split) ------
__global__ void embed_kernel(const int* __restrict__ tok,
                             const float* __restrict__ emb) {
    int p = blockIdx.x * 256 + threadIdx.x;
    if (p >= MROWS*DMODEL/2) return;
    int idx = p * 2;
    int row = idx >> 9;
    int d   = idx & (DMODEL-1);
    int s   = row & (SEQ-1);
    int tk  = tok[row];
    float freq = expf((float)d * (-9.210340371976184f / (float)DMODEL));
    float ang  = (float)s * freq;
    float v0 = emb[tk*DMODEL + d]     + sinf(ang);
    float v1 = emb[tk*DMODEL + d + 1] + cosf(ang);
    *(float2*)&g_x[idx] = make_float2(v0, v1);
    uint32_t h, l; split2h(v0, v1, h, l);
    *(uint32_t*)&g_xh[idx] = h;
    *(uint32_t*)&g_xl[idx] = l;
}

// ---------------- unified weight transpose + fp16 convert (one launch) ----------
// 12 slices per layer, each a 512x512 transpose unit:
//  0..3 : Wq,Wk,Wv,Wo     4..7 : W1 quarter (n)     8..11 : W2 quarter (k)
__global__ void wconv_all_kernel(const float* __restrict__ Wq, const float* __restrict__ Wk,
                                 const float* __restrict__ Wv, const float* __restrict__ Wo,
                                 const float* __restrict__ W1, const float* __restrict__ W2,
                                 __half* __restrict__ wf) {
    __shared__ float tl[32][33];
    int z = blockIdx.z, lyr = z / 12, s = z % 12;
    const float* src;
    size_t doff;
    int srcN, dstK, kb = 0, nb = 0;
    if (s < 4) {
        switch (s) {
            case 0: src = Wq; doff = WOFF_QKV;          break;
            case 1: src = Wk; doff = WOFF_QKV + 262144; break;
            case 2: src = Wv; doff = WOFF_QKV + 524288; break;
            default: src = Wo; doff = WOFF_O;           break;
        }
        src += (size_t)lyr * 262144;
        srcN = 512; dstK = 512;
    } else if (s < 8) {
        src = W1 + (size_t)lyr * DMODEL * DFFN;
        doff = WOFF_1; srcN = 2048; dstK = 512;
        nb = (s - 4) * 512;
    } else {
        src = W2 + (size_t)lyr * DFFN * DMODEL;
        doff = WOFF_2; srcN = 512; dstK = 2048;
        kb = (s - 8) * 512;
    }
    __half* dst = wf + (size_t)lyr * WL_STRIDE + doff;
    int n0 = nb + blockIdx.x*32, k0 = kb + blockIdx.y*32;
    int tx = threadIdx.x & 31, tg = threadIdx.x >> 5;
    #pragma unroll
    for (int r = tg; r < 32; r += 8)
        tl[r][tx] = src[(size_t)(k0 + r)*srcN + n0 + tx];
    __syncthreads();
    #pragma unroll
    for (int r = tg; r < 32; r += 8)
        dst[(size_t)(n0 + r)*dstK + k0 + tx] = __float2half(tl[tx][r]);
}

// ---------------- 2-stage fp16 2-term GEMM, 2 CTAs/SM ---------------------------
// D = (A_h + A_l) * B_f. Tile 128x128, 8 warps (4m x 2n), K-chunks of 64.
// Stage = 55296 B; 2 stages = 110592 B -> two CTAs co-resident per SM.
#define GSTG      55296
#define GEMM_SMEM (2*GSTG)   // 110592

__device__ __forceinline__ void gemm_stage_load(
        uint32_t sbase, int t,
        const __half* Ah, const __half* Al, const __half* Bf,
        int m0, int n0, int k0, int K) {
    #pragma unroll
    for (int i = 0; i < 4; i++) {
        int seg = i*256 + t;
        int r = seg >> 3, c = seg & 7;
        uint32_t so = (uint32_t)r*144 + c*16;
        size_t ga = (size_t)(m0 + r)*K + k0 + c*8;
        size_t gb = (size_t)(n0 + r)*K + k0 + c*8;
        cpa16(sbase +         so, Ah + ga);
        cpa16(sbase + 18432 + so, Al + ga);
        cpa16(sbase + 36864 + so, Bf + gb);
    }
}

template<int MODE>
__global__ __launch_bounds__(256, 2) void mma_gemm(
        const __half* __restrict__ Ah, const __half* __restrict__ Al,
        const __half* __restrict__ Bf,
        float* __restrict__ Cf,
        uint16_t* __restrict__ Ch, uint16_t* __restrict__ Cl,
        int N, int K) {
    extern __shared__ char sm[];
    const uint32_t sb = smem_u32(sm);
    int t = threadIdx.x, l = t & 31, wid = t >> 5;
    int m0 = blockIdx.y * 128, n0 = blockIdx.x * 128;
    int wm = (wid & 3) * 32, wn = (wid >> 2) * 64;

    float acc[2][8][4];
    #pragma unroll
    for (int i = 0; i < 2; i++)
        #pragma unroll
        for (int j = 0; j < 8; j++)
            #pragma unroll
            for (int q = 0; q < 4; q++) acc[i][j][q] = 0.f;

    const int NK = K >> 6;
    gemm_stage_load(sb, t, Ah, Al, Bf, m0, n0, 0, K);
    CP_COMMIT();

    for (int kc = 0; kc < NK; kc++) {
        if (kc + 1 < NK) {
            gemm_stage_load(sb + ((kc+1)&1)*GSTG, t, Ah, Al, Bf,
                            m0, n0, (kc+1)*64, K);
            CP_COMMIT();
            cp_wait<1>();
        } else {
            cp_wait<0>();
        }
        __syncthreads();

        const uint32_t SB = sb + (kc & 1)*GSTG;
        const uint32_t AH = SB, AL = SB + 18432, BF = SB + 36864;
        #pragma unroll
        for (int ks = 0; ks < 4; ks++) {
            uint32_t aH[2][4], aL[2][4];
            #pragma unroll
            for (int ra = 0; ra < 2; ra++) {
                uint32_t off = (uint32_t)(wm + ra*16 + (l & 15))*144 + (ks*16 + (l >> 4)*8)*2;
                ldm4(aH[ra], AH + off);
                ldm4(aL[ra], AL + off);
            }
            #pragma unroll
            for (int g = 0; g < 4; g++) {
                uint32_t bF[4];
                uint32_t off = (uint32_t)(wn + g*16 + (l & 7) + ((l >> 4) << 3))*144
                             + (ks*16 + ((l >> 3) & 1)*8)*2;
                ldm4(bF, BF + off);
                mma16816h(acc[0][2*g],   aH[0], &bF[0]);
                mma16816h(acc[0][2*g+1], aH[0], &bF[2]);
                mma16816h(acc[1][2*g],   aH[1], &bF[0]);
                mma16816h(acc[1][2*g+1], aH[1], &bF[2]);
                mma16816h(acc[0][2*g],   aL[0], &bF[0]);
                mma16816h(acc[0][2*g+1], aL[0], &bF[2]);
                mma16816h(acc[1][2*g],   aL[1], &bF[0]);
                mma16816h(acc[1][2*g+1], aL[1], &bF[2]);
            }
        }
        __syncthreads();
    }

    #pragma unroll
    for (int ra = 0; ra < 2; ra++)
        #pragma unroll
        for (int na = 0; na < 8; na++) {
            int n = n0 + wn + na*8 + 2*(l & 3);
            #pragma unroll
            for (int half = 0; half < 2; half++) {
                int m = m0 + wm + ra*16 + (l >> 2) + half*8;
                float2 v = make_float2(acc[ra][na][half*2], acc[ra][na][half*2 + 1]);
                if (MODE == 0) {
                    *(float2*)&Cf[(size_t)m*N + n] = v;
                } else {
                    uint32_t hh, ll;
                    size_t off;
                    if (MODE == 1) {                       // q/k/v: bf16 for attn
                        split2(v.x, v.y, hh, ll);
                        int sel = n >> 9, n2 = n & 511;
                        int h = n2 >> 6, dk = n2 & 63;
                        int b = m >> 10, s = m & 1023;
                        off = (size_t)sel*MROWS*DMODEL
                            + ((size_t)((b*NHEADS + h)*SEQ + s))*DK + dk;
                    } else {                               // f: relu + fp16
                        v.x = fmaxf(v.x, 0.f); v.y = fmaxf(v.y, 0.f);
                        split2h(v.x, v.y, hh, ll);
                        off = (size_t)m*N + n;
                    }
                    *(uint32_t*)&Ch[off] = hh;
                    *(uint32_t*)&Cl[off] = ll;
                }
            }
        }
}

// ---------------- single-pass bf16 3-term HMMA attention, K double-buffered ------
#define ATTN_SMEM 221184

__global__ __launch_bounds__(256) void attn_kernel(
        const int* __restrict__ tok, float* __restrict__ attn_out,
        float* __restrict__ rinv_g, int layer) {
    extern __shared__ char sm[];
    const uint32_t sb = smem_u32(sm);
    const uint32_t QH = sb,           QL = sb + 18432;
    const uint32_t VH = sb + 110592,  VL = sb + 129024;
    const uint32_t PH = sb + 147456,  PL = sb + 182272;
    char* cPH = sm + 147456;  char* cPL = sm + 182272;
    float* mskS = (float*)(sm + 217088);   // 1024 floats

    int t = threadIdx.x, l = t & 31, wid = t >> 5;
    int qb = blockIdx.x, h = blockIdx.y, b = blockIdx.z;
    int q0 = qb * 128;
    size_t hoff = ((size_t)(b*NHEADS + h)*SEQ)*DK;
    const __nv_bfloat16* qh = g_qh + hoff + (size_t)q0*DK;
    const __nv_bfloat16* ql = g_ql + hoff + (size_t)q0*DK;
    const __nv_bfloat16* kh = g_qh + (size_t)MROWS*DMODEL + hoff;
    const __nv_bfloat16* kl = g_ql + (size_t)MROWS*DMODEL + hoff;
    const __nv_bfloat16* vh = kh + (size_t)MROWS*DMODEL;
    const __nv_bfloat16* vl = kl + (size_t)MROWS*DMODEL;

    for (int j = t; j < SEQ; j += 256)
        mskS[j] = (tok[b*SEQ + j] == 0) ? 1.f : 0.f;
    #pragma unroll
    for (int i = 0; i < 4; i++) {                 // Q + K(0) prologue
        int seg = i*256 + t, r = seg >> 3, c = seg & 7;
        uint32_t so = (uint32_t)r*144 + c*16;
        cpa16(QH + so, qh + (size_t)r*64 + c*8);
        cpa16(QL + so, ql + (size_t)r*64 + c*8);
        cpa16(sb + 36864 + so, kh + (size_t)r*64 + c*8);
        cpa16(sb + 55296 + so, kl + (size_t)r*64 + c*8);
    }
    CP_COMMIT(); cp_wait<0>();
    __syncthreads();

    float rs0 = 0.f, rs1 = 0.f;
    float cacc[8][4];
    #pragma unroll
    for (int j = 0; j < 8; j++)
        #pragma unroll
        for (int q = 0; q < 4; q++) cacc[j][q] = 0.f;

    int r0 = wid*16 + (l >> 2);
    long long abase = ((((long long)layer*BATCH + b)*NHEADS + h)*SEQ + q0)
                      * (long long)SEQ;

    for (int kc = 0; kc < 8; kc++) {
        const uint32_t KHc = sb + 36864 + (uint32_t)(kc & 1)*36864;
        const uint32_t KLc = KHc + 18432;
        #pragma unroll
        for (int i = 0; i < 4; i++) {
            int seg = i*256 + t, r = seg >> 3, c = seg & 7;
            uint32_t so = (uint32_t)r*144 + c*16;
            cpa16(VH + so, vh + (size_t)(kc*128 + r)*64 + c*8);
            cpa16(VL + so, vl + (size_t)(kc*128 + r)*64 + c*8);
        }
        CP_COMMIT();
        if (kc < 7) {
            const uint32_t KHn = sb + 36864 + (uint32_t)((kc+1) & 1)*36864;
            #pragma unroll
            for (int i = 0; i < 4; i++) {
                int seg = i*256 + t, r = seg >> 3, c = seg & 7;
                uint32_t so = (uint32_t)r*144 + c*16;
                cpa16(KHn + so,         kh + (size_t)((kc+1)*128 + r)*64 + c*8);
                cpa16(KHn + 18432 + so, kl + (size_t)((kc+1)*128 + r)*64 + c*8);
            }
            CP_COMMIT();
        }

        // ---- QK on resident K(kc) ----
        float sacc[16][4];
        #pragma unroll
        for (int j = 0; j < 16; j++)
            #pragma unroll
            for (int q = 0; q < 4; q++) sacc[j][q] = 0.f;

        #pragma unroll
        for (int ks = 0; ks < 4; ks++) {
            uint32_t aH[4], aL[4];
            uint32_t aoff = (uint32_t)(wid*16 + (l & 15))*144 + (ks*16 + (l >> 4)*8)*2;
            ldm4(aH, QH + aoff); ldm4(aL, QL + aoff);
            #pragma unroll
            for (int gp = 0; gp < 4; gp++) {
                int g0 = 2*gp, g1 = g0 + 1;
                uint32_t b0H[4], b0L[4], b1H[4], b1L[4];
                uint32_t bo0 = (uint32_t)(g0*16 + (l & 7) + ((l >> 4) << 3))*144
                             + (ks*16 + ((l >> 3) & 1)*8)*2;
                uint32_t bo1 = (uint32_t)(g1*16 + (l & 7) + ((l >> 4) << 3))*144
                             + (ks*16 + ((l >> 3) & 1)*8)*2;
                ldm4(b0H, KHc + bo0); ldm4(b0L, KLc + bo0);
                ldm4(b1H, KHc + bo1); ldm4(b1L, KLc + bo1);
                mma16816(sacc[2*g0],   aH, &b0H[0]);
                mma16816(sacc[2*g0+1], aH, &b0H[2]);
                mma16816(sacc[2*g1],   aH, &b1H[0]);
                mma16816(sacc[2*g1+1], aH, &b1H[2]);
                mma16816(sacc[2*g0],   aH, &b0L[0]);
                mma16816(sacc[2*g0+1], aH, &b0L[2]);
                mma16816(sacc[2*g1],   aH, &b1L[0]);
                mma16816(sacc[2*g1+1], aH, &b1L[2]);
                mma16816(sacc[2*g0],   aL, &b0H[0]);
                mma16816(sacc[2*g0+1], aL, &b0H[2]);
                mma16816(sacc[2*g1],   aL, &b1H[0]);
                mma16816(sacc[2*g1+1], aL, &b1H[2]);
            }
        }

        // ---- exp, rowsum, attn write, P split -> smem ----
        #pragma unroll
        for (int na = 0; na < 16; na++) {
            float e[4];
            #pragma unroll
            for (int j = 0; j < 4; j++) {
                int col = kc*128 + na*8 + 2*(l & 3) + (j & 1);
                e[j] = (mskS[col] != 0.f) ? 0.f : __expf(sacc[na][j]*0.125f);
            }
            rs0 += e[0] + e[1];
            rs1 += e[2] + e[3];
            int c0 = kc*128 + na*8 + 2*(l & 3);
            if (attn_out) {
                *(float2*)&attn_out[abase + (long long)r0*SEQ + c0]
                    = make_float2(e[0], e[1]);
                *(float2*)&attn_out[abase + (long long)(r0 + 8)*SEQ + c0]
                    = make_float2(e[2], e[3]);
            }
            uint32_t h01, l01, h23, l23;
            split2(e[0], e[1], h01, l01);
            split2(e[2], e[3], h23, l23);
            int pc = na*8 + 2*(l & 3);
            *(uint32_t*)(cPH + r0*272 + pc*2)     = h01;
            *(uint32_t*)(cPL + r0*272 + pc*2)     = l01;
            *(uint32_t*)(cPH + (r0+8)*272 + pc*2) = h23;
            *(uint32_t*)(cPL + (r0+8)*272 + pc*2) = l23;
        }

        if (kc < 7) cp_wait<1>(); else cp_wait<0>();   // V ready
        __syncthreads();                                // V + P visible

        // ---- PV ----
        #pragma unroll
        for (int ks = 0; ks < 8; ks++) {
            uint32_t pH[4], pL[4];
            uint32_t poff = (uint32_t)(wid*16 + (l & 15))*272 + (ks*16 + (l >> 4)*8)*2;
            ldm4(pH, PH + poff); ldm4(pL, PL + poff);
            #pragma unroll
            for (int gp = 0; gp < 2; gp++) {
                int g0 = 2*gp, g1 = g0 + 1;
                uint32_t v0H[4], v0L[4], v1H[4], v1L[4];
                uint32_t vo0 = (uint32_t)(ks*16 + (l & 15))*144 + (g0*16 + ((l >> 4) << 3))*2;
                uint32_t vo1 = (uint32_t)(ks*16 + (l & 15))*144 + (g1*16 + ((l >> 4) << 3))*2;
                ldm4t(v0H, VH + vo0); ldm4t(v0L, VL + vo0);
                ldm4t(v1H, VH + vo1); ldm4t(v1L, VL + vo1);
                mma16816(cacc[2*g0],   pH, &v0H[0]);
                mma16816(cacc[2*g0+1], pH, &v0H[2]);
                mma16816(cacc[2*g1],   pH, &v1H[0]);
                mma16816(cacc[2*g1+1], pH, &v1H[2]);
                mma16816(cacc[2*g0],   pH, &v0L[0]);
                mma16816(cacc[2*g0+1], pH, &v0L[2]);
                mma16816(cacc[2*g1],   pH, &v1L[0]);
                mma16816(cacc[2*g1+1], pH, &v1L[2]);
                mma16816(cacc[2*g0],   pL, &v0H[0]);
                mma16816(cacc[2*g0+1], pL, &v0H[2]);
                mma16816(cacc[2*g1],   pL, &v1H[0]);
                mma16816(cacc[2*g1+1], pL, &v1H[2]);
            }
        }

        cp_wait<0>();      // K(kc+1) complete
        __syncthreads();
    }

    rs0 += __shfl_xor_sync(0xffffffffu, rs0, 1);
    rs0 += __shfl_xor_sync(0xffffffffu, rs0, 2);
    rs1 += __shfl_xor_sync(0xffffffffu, rs1, 1);
    rs1 += __shfl_xor_sync(0xffffffffu, rs1, 2);
    float inv0 = 1.f / rs0, inv1 = 1.f / rs1;
    if ((l & 3) == 0) {
        size_t rb = ((size_t)(layer*BATCH + b)*NHEADS + h)*SEQ + q0;
        rinv_g[rb + r0]     = inv0;
        rinv_g[rb + r0 + 8] = inv1;
    }
    #pragma unroll
    for (int na = 0; na < 8; na++) {
        int d = na*8 + 2*(l & 3);
        size_t o = ((size_t)(b*SEQ + q0 + r0))*DMODEL + h*DK + d;
        uint32_t h0, l0, h1, l1;
        split2h(cacc[na][0]*inv0, cacc[na][1]*inv0, h0, l0);   // ctx -> fp16
        split2h(cacc[na][2]*inv1, cacc[na][3]*inv1, h1, l1);
        *(uint32_t*)&g_ch[o]            = h0;
        *(uint32_t*)&g_cl[o]            = l0;
        *(uint32_t*)&g_ch[o + 8*DMODEL] = h1;
        *(uint32_t*)&g_cl[o + 8*DMODEL] = l1;
    }
}

// ---------------- normalize one layer's attention in place ----------------------
__global__ void attn_scale_kernel(float* __restrict__ attn,
                                  const float* __restrict__ rinv) {
    size_t i4 = ((size_t)blockIdx.x*256 + threadIdx.x) * 4;
    float inv = __ldg(&rinv[i4 >> 10]);
    float4 v = *(float4*)&attn[i4];
    v.x *= inv; v.y *= inv; v.z *= inv; v.w *= inv;
    *(float4*)&attn[i4] = v;
}

// ---------------- x = LayerNorm(y + x), writes x fp32 + fp16 split ---------------
__global__ __launch_bounds__(128) void add_ln_kernel(
        const float* __restrict__ y, float* __restrict__ x,
        __half* __restrict__ xh, __half* __restrict__ xl) {
    int row = blockIdx.x;
    int t   = threadIdx.x;
    const float* yr = y + (size_t)row*DMODEL;
    float*       xr = x + (size_t)row*DMODEL;
    float4 a = *(const float4*)&xr[t*4];
    float4 c = *(const float4*)&yr[t*4];
    float v[4] = {a.x + c.x, a.y + c.y, a.z + c.z, a.w + c.w};
    float s = v[0]+v[1]+v[2]+v[3];
    float s2 = v[0]*v[0]+v[1]*v[1]+v[2]*v[2]+v[3]*v[3];
    #pragma unroll
    for (int o = 16; o; o >>= 1) {
        s  += __shfl_xor_sync(0xffffffffu, s,  o);
        s2 += __shfl_xor_sync(0xffffffffu, s2, o);
    }
    __shared__ float sh[8];
    int w = t >> 5;
    if ((t & 31) == 0) { sh[w] = s; sh[4 + w] = s2; }
    __syncthreads();
    s  = sh[0] + sh[1] + sh[2] + sh[3];
    s2 = sh[4] + sh[5] + sh[6] + sh[7];
    float mean = s * (1.f/DMODEL);
    float var  = s2 * (1.f/DMODEL) - mean*mean;
    float invs = rsqrtf(var + 1e-5f);
    float o0 = (v[0]-mean)*invs, o1 = (v[1]-mean)*invs;
    float o2 = (v[2]-mean)*invs, o3 = (v[3]-mean)*invs;
    *(float4*)&xr[t*4] = make_float4(o0, o1, o2, o3);
    uint32_t h0, l0, h1, l1;
    split2h(o0, o1, h0, l0); split2h(o2, o3, h1, l1);
    size_t ob = (size_t)row*DMODEL + t*4;
    *(uint32_t*)&xh[ob]     = h0;  *(uint32_t*)&xl[ob]     = l0;
    *(uint32_t*)&xh[ob + 2] = h1;  *(uint32_t*)&xl[ob + 2] = l1;
}

__global__ void copy_x_kernel(float* __restrict__ out) {
    int i = blockIdx.x*256 + threadIdx.x;
    if (i < MROWS*DMODEL) out[i] = g_x[i];
}

// ---------------- driver ---------------------------------------------------------
extern "C" void kernel_launch(void* const* d_in, const int* in_sizes, int n_in,
                              void* d_out, int out_size) {
    const int*   tok = (const int*)  d_in[0];
    const float* emb = (const float*)d_in[1];
    const float* Wq  = (const float*)d_in[2];
    const float* Wk  = (const float*)d_in[3];
    const float* Wv  = (const float*)d_in[4];
    const float* Wo  = (const float*)d_in[5];
    const float* W1  = (const float*)d_in[6];
    const float* W2  = (const float*)d_in[7];
    float* out = (float*)d_out;

    float* attn_base = out + MROWS*DMODEL;
    bool   write_x   = true;
    if (out_size == MROWS*DMODEL)   { attn_base = nullptr; }
    else if (out_size == 201326592) { attn_base = out; write_x = false; }

    float *px, *py, *prinv;
    cudaGetSymbolAddress((void**)&px, g_x);
    cudaGetSymbolAddress((void**)&py, g_y);
    cudaGetSymbolAddress((void**)&prinv, g_rinv);
    __half *xh, *xl, *ch, *cl, *fh, *fl, *wf;
    __nv_bfloat16 *qh, *ql;
    cudaGetSymbolAddress((void**)&xh, g_xh);
    cudaGetSymbolAddress((void**)&xl, g_xl);
    cudaGetSymbolAddress((void**)&qh, g_qh);
    cudaGetSymbolAddress((void**)&ql, g_ql);
    cudaGetSymbolAddress((void**)&ch, g_ch);
    cudaGetSymbolAddress((void**)&cl, g_cl);
    cudaGetSymbolAddress((void**)&fh, g_fh);
    cudaGetSymbolAddress((void**)&fl, g_fl);
    cudaGetSymbolAddress((void**)&wf, g_wf);

    cudaFuncSetAttribute(attn_kernel, cudaFuncAttributeMaxDynamicSharedMemorySize, ATTN_SMEM);
    cudaFuncSetAttribute(mma_gemm<0>, cudaFuncAttributeMaxDynamicSharedMemorySize, GEMM_SMEM);
    cudaFuncSetAttribute(mma_gemm<1>, cudaFuncAttributeMaxDynamicSharedMemorySize, GEMM_SMEM);
    cudaFuncSetAttribute(mma_gemm<2>, cudaFuncAttributeMaxDynamicSharedMemorySize, GEMM_SMEM);

    // ---- side stream used ONLY for attn_scale overlap (round-8 pattern). ----
    cudaStream_t side = 0;
    cudaEvent_t evFork[NLAYERS], evJoin;
    bool useSide = attn_base != nullptr;
    if (useSide && cudaStreamCreateWithFlags(&side, cudaStreamNonBlocking) != cudaSuccess)
        useSide = false;
    if (useSide) {
        for (int l = 0; l < NLAYERS && useSide; l++)
            if (cudaEventCreateWithFlags(&evFork[l], cudaEventDisableTiming) != cudaSuccess)
                useSide = false;
        if (useSide && cudaEventCreateWithFlags(&evJoin, cudaEventDisableTiming) != cudaSuccess)
            useSide = false;
    }

    embed_kernel<<<(MROWS*DMODEL/2 + 255)/256, 256>>>(tok, emb);
    {
        dim3 gAll(16, 16, 12*NLAYERS);
        wconv_all_kernel<<<gAll, 256>>>(Wq, Wk, Wv, Wo, W1, W2, wf);
    }

    dim3 gQKV(12, 32);    // N=1536
    dim3 gO(4, 32);       // N=512
    dim3 gF1(16, 32);     // N=2048
    dim3 gAttn(SEQ/128, NHEADS, BATCH);
    const unsigned gScale = (unsigned)(ALSTRIDE/1024);

    for (int l = 0; l < NLAYERS; l++) {
        const __half* w = wf + (size_t)l*WL_STRIDE;

        mma_gemm<1><<<gQKV, 256, GEMM_SMEM>>>(xh, xl, w + WOFF_QKV, nullptr,
                                              (uint16_t*)qh, (uint16_t*)ql, 1536, 512);
        attn_kernel<<<gAttn, 256, ATTN_SMEM>>>(tok, attn_base, prinv, l);

        if (attn_base) {
            float* al = attn_base + (long long)l*ALSTRIDE;
            const float* rl = prinv + (size_t)l*BATCH*NHEADS*SEQ;
            if (useSide) {
                cudaEventRecord(evFork[l], 0);
                cudaStreamWaitEvent(side, evFork[l], 0);
                attn_scale_kernel<<<gScale, 256, 0, side>>>(al, rl);
            } else {
                attn_scale_kernel<<<gScale, 256>>>(al, rl);
            }
        }

        mma_gemm<0><<<gO, 256, GEMM_SMEM>>>(ch, cl, w + WOFF_O,
                                            py, nullptr, nullptr, 512, 512);
        add_ln_kernel<<<MROWS, 128>>>(py, px, xh, xl);
        mma_gemm<2><<<gF1, 256, GEMM_SMEM>>>(xh, xl, w + WOFF_1, nullptr,
                                             (uint16_t*)fh, (uint16_t*)fl, 2048, 512);
        mma_gemm<0><<<gO, 256, GEMM_SMEM>>>(fh, fl, w + WOFF_2,
                                            py, nullptr, nullptr, 512, 2048);
        add_ln_kernel<<<MROWS, 128>>>(py, px, xh, xl);
    }

    // copy_x is independent of attn normalization — launch before the join
    if (write_x)
        copy_x_kernel<<<(MROWS*DMODEL + 255)/256, 256>>>(out);

    if (useSide) {          // join side stream back into the captured main stream
        cudaEventRecord(evJoin, side);
        cudaStreamWaitEvent(0, evJoin, 0);
    }
}

// round 15
// speedup vs baseline: 1.1892x; 1.0076x over previous
#include <cuda_runtime.h>
#include <cuda_bf16.h>
#include <cuda_fp16.h>
#include <cstdint>

#define BATCH   4
#define SEQ     1024
#define DMODEL  512
#define NHEADS  8
#define DK      64
#define NLAYERS 6
#define DFFN    2048
#define MROWS   (BATCH*SEQ)   // 4096
#define ALSTRIDE ((long long)BATCH*NHEADS*SEQ*SEQ)   // attn layer stride

// ---------------- scratch (device globals) -------------------------------------
__device__ float g_x  [MROWS*DMODEL];     // residual stream (fp32)
__device__ float g_y  [MROWS*DMODEL];     // gemm fp32 out (pre-LN)
__device__ float g_rinv[NLAYERS*BATCH*NHEADS*SEQ];                    // 1/rowsum
__device__ __half g_xh[MROWS*DMODEL],  g_xl[MROWS*DMODEL];           // x fp16 split
__device__ __nv_bfloat16 g_qh[3*MROWS*DMODEL], g_ql[3*MROWS*DMODEL]; // q|k|v bf16 split
__device__ __half g_ch[MROWS*DMODEL],  g_cl[MROWS*DMODEL];           // ctx fp16 split
__device__ __half g_fh[MROWS*DFFN],    g_fl[MROWS*DFFN];             // ffn fp16 split

// single-fp16 transposed weights Wt[n][k]: qkv(1536x512)|o(512x512)|w1(2048x512)|w2(512x2048)
#define WL_STRIDE 3145728
#define WOFF_QKV  0
#define WOFF_O    786432
#define WOFF_1    1048576
#define WOFF_2    2097152
__device__ __half g_wf[NLAYERS*WL_STRIDE];

// ---------------- helpers -------------------------------------------------------
__device__ __forceinline__ uint32_t smem_u32(const void* p) {
    uint32_t a;
    asm("{ .reg .u64 t; cvta.to.shared.u64 t, %1; cvt.u32.u64 %0, t; }" : "=r"(a) : "l"(p));
    return a;
}
__device__ __forceinline__ void ldm4(uint32_t* r, uint32_t a) {
    asm volatile("ldmatrix.sync.aligned.m8n8.x4.shared.b16 {%0,%1,%2,%3}, [%4];"
        : "=r"(r[0]), "=r"(r[1]), "=r"(r[2]), "=r"(r[3]) : "r"(a));
}
__device__ __forceinline__ void ldm4t(uint32_t* r, uint32_t a) {
    asm volatile("ldmatrix.sync.aligned.m8n8.x4.trans.shared.b16 {%0,%1,%2,%3}, [%4];"
        : "=r"(r[0]), "=r"(r[1]), "=r"(r[2]), "=r"(r[3]) : "r"(a));
}
// bf16 MMA (attention path)
__device__ __forceinline__ void mma16816(float* d, const uint32_t* a, const uint32_t* b) {
    asm volatile("mma.sync.aligned.m16n8k16.row.col.f32.bf16.bf16.f32 "
        "{%0,%1,%2,%3}, {%4,%5,%6,%7}, {%8,%9}, {%0,%1,%2,%3};"
        : "+f"(d[0]), "+f"(d[1]), "+f"(d[2]), "+f"(d[3])
        : "r"(a[0]), "r"(a[1]), "r"(a[2]), "r"(a[3]), "r"(b[0]), "r"(b[1]));
}
// fp16 MMA (linear GEMMs)
__device__ __forceinline__ void mma16816h(float* d, const uint32_t* a, const uint32_t* b) {
    asm volatile("mma.sync.aligned.m16n8k16.row.col.f32.f16.f16.f32 "
        "{%0,%1,%2,%3}, {%4,%5,%6,%7}, {%8,%9}, {%0,%1,%2,%3};"
        : "+f"(d[0]), "+f"(d[1]), "+f"(d[2]), "+f"(d[3])
        : "r"(a[0]), "r"(a[1]), "r"(a[2]), "r"(a[3]), "r"(b[0]), "r"(b[1]));
}
// fp32 pair -> bf16 hi/lo (attention operands)
__device__ __forceinline__ void split2(float x, float y, uint32_t& hi, uint32_t& lo) {
    __nv_bfloat162 h = __floats2bfloat162_rn(x, y);
    float hx = __bfloat162float(h.x), hy = __bfloat162float(h.y);
    __nv_bfloat162 l2 = __floats2bfloat162_rn(x - hx, y - hy);
    hi = *(uint32_t*)&h;
    lo = *(uint32_t*)&l2;
}
// fp32 pair -> fp16 hi/lo (linear-GEMM A operands)
__device__ __forceinline__ void split2h(float x, float y, uint32_t& hi, uint32_t& lo) {
    __half2 h = __floats2half2_rn(x, y);
    float hx = __low2float(h), hy = __high2float(h);
    __half2 l2 = __floats2half2_rn(x - hx, y - hy);
    hi = *(uint32_t*)&h;
    lo = *(uint32_t*)&l2;
}
__device__ __forceinline__ void cpa16(uint32_t dst, const void* src) {
    asm volatile("cp.async.cg.shared.global [%0], [%1], 16;" :: "r"(dst), "l"(src));
}
#define CP_COMMIT() asm volatile("cp.async.commit_group;" ::: "memory")
template<int N> __device__ __forceinline__ void cp_wait() {
    asm volatile("cp.async.wait_group %0;" :: "n"(N) : "memory");
}

// ---------------- embedding + positional encoding (writes x + fp16 split) ------
__global__ void embed_kernel(const int* __restrict__ tok,
                             const float* __restrict__ emb) {
    int p = blockIdx.x * 256 + threadIdx.x;
    if (p >= MROWS*DMODEL/2) return;
    int idx = p * 2;
    int row = idx >> 9;
    int d   = idx & (DMODEL-1);
    int s   = row & (SEQ-1);
    int tk  = tok[row];
    float freq = expf((float)d * (-9.210340371976184f / (float)DMODEL));
    float ang  = (float)s * freq;
    float v0 = emb[tk*DMODEL + d]     + sinf(ang);
    float v1 = emb[tk*DMODEL + d + 1] + cosf(ang);
    *(float2*)&g_x[idx] = make_float2(v0, v1);
    uint32_t h, l; split2h(v0, v1, h, l);
    *(uint32_t*)&g_xh[idx] = h;
    *(uint32_t*)&g_xl[idx] = l;
}

// ---------------- unified weight transpose + fp16 convert (one launch) ----------
__global__ void wconv_all_kernel(const float* __restrict__ Wq, const float* __restrict__ Wk,
                                 const float* __restrict__ Wv, const float* __restrict__ Wo,
                                 const float* __restrict__ W1, const float* __restrict__ W2,
                                 __half* __restrict__ wf) {
    __shared__ float tl[32][33];
    int z = blockIdx.z, lyr = z / 12, s = z % 12;
    const float* src;
    size_t doff;
    int srcN, dstK, kb = 0, nb = 0;
    if (s < 4) {
        switch (s) {
            case 0: src = Wq; doff = WOFF_QKV;          break;
            case 1: src = Wk; doff = WOFF_QKV + 262144; break;
            case 2: src = Wv; doff = WOFF_QKV + 524288; break;
            default: src = Wo; doff = WOFF_O;           break;
        }
        src += (size_t)lyr * 262144;
        srcN = 512; dstK = 512;
    } else if (s < 8) {
        src = W1 + (size_t)lyr * DMODEL * DFFN;
        doff = WOFF_1; srcN = 2048; dstK = 512;
        nb = (s - 4) * 512;
    } else {
        src = W2 + (size_t)lyr * DFFN * DMODEL;
        doff = WOFF_2; srcN = 512; dstK = 2048;
        kb = (s - 8) * 512;
    }
    __half* dst = wf + (size_t)lyr * WL_STRIDE + doff;
    int n0 = nb + blockIdx.x*32, k0 = kb + blockIdx.y*32;
    int tx = threadIdx.x & 31, tg = threadIdx.x >> 5;
    #pragma unroll
    for (int r = tg; r < 32; r += 8)
        tl[r][tx] = src[(size_t)(k0 + r)*srcN + n0 + tx];
    __syncthreads();
    #pragma unroll
    for (int r = tg; r < 32; r += 8)
        dst[(size_t)(n0 + r)*dstK + k0 + tx] = __float2half(tl[tx][r]);
}

// ---------------- 2-stage fp16 2-term GEMM, 2 CTAs/SM ---------------------------
#define GSTG      55296
#define GEMM_SMEM (2*GSTG)

__device__ __forceinline__ void gemm_stage_load(
        uint32_t sbase, int t,
        const __half* Ah, const __half* Al, const __half* Bf,
        int m0, int n0, int k0, int K) {
    #pragma unroll
    for (int i = 0; i < 4; i++) {
        int seg = i*256 + t;
        int r = seg >> 3, c = seg & 7;
        uint32_t so = (uint32_t)r*144 + c*16;
        size_t ga = (size_t)(m0 + r)*K + k0 + c*8;
        size_t gb = (size_t)(n0 + r)*K + k0 + c*8;
        cpa16(sbase +         so, Ah + ga);
        cpa16(sbase + 18432 + so, Al + ga);
        cpa16(sbase + 36864 + so, Bf + gb);
    }
}

template<int MODE>
__global__ __launch_bounds__(256, 2) void mma_gemm(
        const __half* __restrict__ Ah, const __half* __restrict__ Al,
        const __half* __restrict__ Bf,
        float* __restrict__ Cf,
        uint16_t* __restrict__ Ch, uint16_t* __restrict__ Cl,
        int N, int K) {
    extern __shared__ char sm[];
    const uint32_t sb = smem_u32(sm);
    int t = threadIdx.x, l = t & 31, wid = t >> 5;
    int m0 = blockIdx.y * 128, n0 = blockIdx.x * 128;
    int wm = (wid & 3) * 32, wn = (wid >> 2) * 64;

    float acc[2][8][4];
    #pragma unroll
    for (int i = 0; i < 2; i++)
        #pragma unroll
        for (int j = 0; j < 8; j++)
            #pragma unroll
            for (int q = 0; q < 4; q++) acc[i][j][q] = 0.f;

    const int NK = K >> 6;
    gemm_stage_load(sb, t, Ah, Al, Bf, m0, n0, 0, K);
    CP_COMMIT();

    for (int kc = 0; kc < NK; kc++) {
        if (kc + 1 < NK) {
            gemm_stage_load(sb + ((kc+1)&1)*GSTG, t, Ah, Al, Bf,
                            m0, n0, (kc+1)*64, K);
            CP_COMMIT();
            cp_wait<1>();
        } else {
            cp_wait<0>();
        }
        __syncthreads();

        const uint32_t SB = sb + (kc & 1)*GSTG;
        const uint32_t AH = SB, AL = SB + 18432, BF = SB + 36864;
        #pragma unroll
        for (int ks = 0; ks < 4; ks++) {
            uint32_t aH[2][4], aL[2][4];
            #pragma unroll
            for (int ra = 0; ra < 2; ra++) {
                uint32_t off = (uint32_t)(wm + ra*16 + (l & 15))*144 + (ks*16 + (l >> 4)*8)*2;
                ldm4(aH[ra], AH + off);
                ldm4(aL[ra], AL + off);
            }
            #pragma unroll
            for (int g = 0; g < 4; g++) {
                uint32_t bF[4];
                uint32_t off = (uint32_t)(wn + g*16 + (l & 7) + ((l >> 4) << 3))*144
                             + (ks*16 + ((l >> 3) & 1)*8)*2;
                ldm4(bF, BF + off);
                mma16816h(acc[0][2*g],   aH[0], &bF[0]);
                mma16816h(acc[0][2*g+1], aH[0], &bF[2]);
                mma16816h(acc[1][2*g],   aH[1], &bF[0]);
                mma16816h(acc[1][2*g+1], aH[1], &bF[2]);
                mma16816h(acc[0][2*g],   aL[0], &bF[0]);
                mma16816h(acc[0][2*g+1], aL[0], &bF[2]);
                mma16816h(acc[1][2*g],   aL[1], &bF[0]);
                mma16816h(acc[1][2*g+1], aL[1], &bF[2]);
            }
        }
        __syncthreads();
    }

    #pragma unroll
    for (int ra = 0; ra < 2; ra++)
        #pragma unroll
        for (int na = 0; na < 8; na++) {
            int n = n0 + wn + na*8 + 2*(l & 3);
            #pragma unroll
            for (int half = 0; half < 2; half++) {
                int m = m0 + wm + ra*16 + (l >> 2) + half*8;
                float2 v = make_float2(acc[ra][na][half*2], acc[ra][na][half*2 + 1]);
                if (MODE == 0) {
                    *(float2*)&Cf[(size_t)m*N + n] = v;
                } else {
                    uint32_t hh, ll;
                    size_t off;
                    if (MODE == 1) {                       // q/k/v: bf16 for attn
                        split2(v.x, v.y, hh, ll);
                        int sel = n >> 9, n2 = n & 511;
                        int h = n2 >> 6, dk = n2 & 63;
                        int b = m >> 10, s = m & 1023;
                        off = (size_t)sel*MROWS*DMODEL
                            + ((size_t)((b*NHEADS + h)*SEQ + s))*DK + dk;
                    } else {                               // f: relu + fp16
                        v.x = fmaxf(v.x, 0.f); v.y = fmaxf(v.y, 0.f);
                        split2h(v.x, v.y, hh, ll);
                        off = (size_t)m*N + n;
                    }
                    *(uint32_t*)&Ch[off] = hh;
                    *(uint32_t*)&Cl[off] = ll;
                }
            }
        }
}

// ---------------- single-pass bf16 3-term attention, 16 warps --------------------
// Warp grid 8m x 2n: each warp owns 16 q-rows x 64 k-cols (QK) and
// 16 q-rows x 32 d-cols (PV). Rowsums combined across warp pairs via smem.
#define ATTN_SMEM 221184

__global__ __launch_bounds__(512) void attn_kernel(
        const int* __restrict__ tok, float* __restrict__ attn_out,
        float* __restrict__ rinv_g, int layer) {
    extern __shared__ char sm[];
    const uint32_t sb = smem_u32(sm);
    const uint32_t QH = sb,           QL = sb + 18432;
    const uint32_t VH = sb + 110592,  VL = sb + 129024;
    const uint32_t PH = sb + 147456,  PL = sb + 182272;
    char* cPH = sm + 147456;  char* cPL = sm + 182272;
    float* mskS = (float*)(sm + 217088);   // 1024 floats (reused for partials)

    int t = threadIdx.x, l = t & 31, wid = t >> 5;
    int wm = wid & 7;          // m-stripe (16 q-rows)
    int wn2 = wid >> 3;        // n-half (64 k-cols / 32 d-cols)
    int qb = blockIdx.x, h = blockIdx.y, b = blockIdx.z;
    int q0 = qb * 128;
    size_t hoff = ((size_t)(b*NHEADS + h)*SEQ)*DK;
    const __nv_bfloat16* qh = g_qh + hoff + (size_t)q0*DK;
    const __nv_bfloat16* ql = g_ql + hoff + (size_t)q0*DK;
    const __nv_bfloat16* kh = g_qh + (size_t)MROWS*DMODEL + hoff;
    const __nv_bfloat16* kl = g_ql + (size_t)MROWS*DMODEL + hoff;
    const __nv_bfloat16* vh = kh + (size_t)MROWS*DMODEL;
    const __nv_bfloat16* vl = kl + (size_t)MROWS*DMODEL;

    for (int j = t; j < SEQ; j += 512)
        mskS[j] = (tok[b*SEQ + j] == 0) ? 1.f : 0.f;
    #pragma unroll
    for (int i = 0; i < 2; i++) {                 // Q + K(0) prologue
        int seg = i*512 + t, r = seg >> 3, c = seg & 7;
        uint32_t so = (uint32_t)r*144 + c*16;
        cpa16(QH + so, qh + (size_t)r*64 + c*8);
        cpa16(QL + so, ql + (size_t)r*64 + c*8);
        cpa16(sb + 36864 + so, kh + (size_t)r*64 + c*8);
        cpa16(sb + 55296 + so, kl + (size_t)r*64 + c*8);
    }
    CP_COMMIT(); cp_wait<0>();
    __syncthreads();

    float rs0 = 0.f, rs1 = 0.f;        // partial (half-row) sums
    float cacc[4][4];
    #pragma unroll
    for (int j = 0; j < 4; j++)
        #pragma unroll
        for (int q = 0; q < 4; q++) cacc[j][q] = 0.f;

    int r0 = wm*16 + (l >> 2);
    long long abase = ((((long long)layer*BATCH + b)*NHEADS + h)*SEQ + q0)
                      * (long long)SEQ;

    for (int kc = 0; kc < 8; kc++) {
        const uint32_t KHc = sb + 36864 + (uint32_t)(kc & 1)*36864;
        const uint32_t KLc = KHc + 18432;
        #pragma unroll
        for (int i = 0; i < 2; i++) {
            int seg = i*512 + t, r = seg >> 3, c = seg & 7;
            uint32_t so = (uint32_t)r*144 + c*16;
            cpa16(VH + so, vh + (size_t)(kc*128 + r)*64 + c*8);
            cpa16(VL + so, vl + (size_t)(kc*128 + r)*64 + c*8);
        }
        CP_COMMIT();
        if (kc < 7) {
            const uint32_t KHn = sb + 36864 + (uint32_t)((kc+1) & 1)*36864;
            #pragma unroll
            for (int i = 0; i < 2; i++) {
                int seg = i*512 + t, r = seg >> 3, c = seg & 7;
                uint32_t so = (uint32_t)r*144 + c*16;
                cpa16(KHn + so,         kh + (size_t)((kc+1)*128 + r)*64 + c*8);
                cpa16(KHn + 18432 + so, kl + (size_t)((kc+1)*128 + r)*64 + c*8);
            }
            CP_COMMIT();
        }

        // ---- QK: 16 q-rows x 64 k-cols (k-tiles wn2*4 .. wn2*4+3) ----
        float sacc[8][4];
        #pragma unroll
        for (int j = 0; j < 8; j++)
            #pragma unroll
            for (int q = 0; q < 4; q++) sacc[j][q] = 0.f;

        #pragma unroll
        for (int ks = 0; ks < 4; ks++) {
            uint32_t aH[4], aL[4];
            uint32_t aoff = (uint32_t)(wm*16 + (l & 15))*144 + (ks*16 + (l >> 4)*8)*2;
            ldm4(aH, QH + aoff); ldm4(aL, QL + aoff);
            #pragma unroll
            for (int gp = 0; gp < 2; gp++) {
                int g0l = 2*gp, g1l = g0l + 1;               // local groups
                int G0 = wn2*4 + g0l, G1 = wn2*4 + g1l;       // global k-tile groups
                uint32_t b0H[4], b0L[4], b1H[4], b1L[4];
                uint32_t bo0 = (uint32_t)(G0*16 + (l & 7) + ((l >> 4) << 3))*144
                             + (ks*16 + ((l >> 3) & 1)*8)*2;
                uint32_t bo1 = (uint32_t)(G1*16 + (l & 7) + ((l >> 4) << 3))*144
                             + (ks*16 + ((l >> 3) & 1)*8)*2;
                ldm4(b0H, KHc + bo0); ldm4(b0L, KLc + bo0);
                ldm4(b1H, KHc + bo1); ldm4(b1L, KLc + bo1);
                mma16816(sacc[2*g0l],   aH, &b0H[0]);
                mma16816(sacc[2*g0l+1], aH, &b0H[2]);
                mma16816(sacc[2*g1l],   aH, &b1H[0]);
                mma16816(sacc[2*g1l+1], aH, &b1H[2]);
                mma16816(sacc[2*g0l],   aH, &b0L[0]);
                mma16816(sacc[2*g0l+1], aH, &b0L[2]);
                mma16816(sacc[2*g1l],   aH, &b1L[0]);
                mma16816(sacc[2*g1l+1], aH, &b1L[2]);
                mma16816(sacc[2*g0l],   aL, &b0H[0]);
                mma16816(sacc[2*g0l+1], aL, &b0H[2]);
                mma16816(sacc[2*g1l],   aL, &b1H[0]);
                mma16816(sacc[2*g1l+1], aL, &b1H[2]);
            }
        }

        // ---- exp, partial rowsum, attn write, P split -> smem ----
        #pragma unroll
        for (int na = 0; na < 8; na++) {
            float e[4];
            #pragma unroll
            for (int j = 0; j < 4; j++) {
                int col = kc*128 + wn2*64 + na*8 + 2*(l & 3) + (j & 1);
                e[j] = (mskS[col] != 0.f) ? 0.f : __expf(sacc[na][j]*0.125f);
            }
            rs0 += e[0] + e[1];
            rs1 += e[2] + e[3];
            int c0 = kc*128 + wn2*64 + na*8 + 2*(l & 3);
            if (attn_out) {
                *(float2*)&attn_out[abase + (long long)r0*SEQ + c0]
                    = make_float2(e[0], e[1]);
                *(float2*)&attn_out[abase + (long long)(r0 + 8)*SEQ + c0]
                    = make_float2(e[2], e[3]);
            }
            uint32_t h01, l01, h23, l23;
            split2(e[0], e[1], h01, l01);
            split2(e[2], e[3], h23, l23);
            int pc = wn2*64 + na*8 + 2*(l & 3);
            *(uint32_t*)(cPH + r0*272 + pc*2)     = h01;
            *(uint32_t*)(cPL + r0*272 + pc*2)     = l01;
            *(uint32_t*)(cPH + (r0+8)*272 + pc*2) = h23;
            *(uint32_t*)(cPL + (r0+8)*272 + pc*2) = l23;
        }

        if (kc < 7) cp_wait<1>(); else cp_wait<0>();   // V ready
        __syncthreads();                                // V + P visible

        // ---- PV: 16 q-rows x 32 d-cols (d-tiles wn2*2 .. wn2*2+1) ----
        #pragma unroll
        for (int ks = 0; ks < 8; ks++) {
            uint32_t pH[4], pL[4];
            uint32_t poff = (uint32_t)(wm*16 + (l & 15))*272 + (ks*16 + (l >> 4)*8)*2;
            ldm4(pH, PH + poff); ldm4(pL, PL + poff);
            #pragma unroll
            for (int g = 0; g < 2; g++) {
                int D = wn2*2 + g;                       // global d-group
                uint32_t vH[4], vL[4];
                uint32_t vo = (uint32_t)(ks*16 + (l & 15))*144 + (D*16 + ((l >> 4) << 3))*2;
                ldm4t(vH, VH + vo); ldm4t(vL, VL + vo);
                mma16816(cacc[2*g],   pH, &vH[0]);
                mma16816(cacc[2*g+1], pH, &vH[2]);
                mma16816(cacc[2*g],   pH, &vL[0]);
                mma16816(cacc[2*g+1], pH, &vL[2]);
                mma16816(cacc[2*g],   pL, &vH[0]);
                mma16816(cacc[2*g+1], pL, &vH[2]);
            }
        }

        cp_wait<0>();      // K(kc+1) complete
        __syncthreads();
    }

    // ---- combine half-row sums across warp pairs ----
    rs0 += __shfl_xor_sync(0xffffffffu, rs0, 1);
    rs0 += __shfl_xor_sync(0xffffffffu, rs0, 2);
    rs1 += __shfl_xor_sync(0xffffffffu, rs1, 1);
    rs1 += __shfl_xor_sync(0xffffffffu, rs1, 2);
    float* part = mskS;                 // reuse: 128 rows x 2 halves
    if ((l & 3) == 0) {
        part[r0*2 + wn2]       = rs0;
        part[(r0 + 8)*2 + wn2] = rs1;
    }
    __syncthreads();
    float inv0 = 1.f / (part[r0*2]       + part[r0*2 + 1]);
    float inv1 = 1.f / (part[(r0+8)*2]   + part[(r0+8)*2 + 1]);
    if (wn2 == 0 && (l & 3) == 0) {
        size_t rb = ((size_t)(layer*BATCH + b)*NHEADS + h)*SEQ + q0;
        rinv_g[rb + r0]     = inv0;
        rinv_g[rb + r0 + 8] = inv1;
    }
    #pragma unroll
    for (int na = 0; na < 4; na++) {
        int d = wn2*32 + na*8 + 2*(l & 3);
        size_t o = ((size_t)(b*SEQ + q0 + r0))*DMODEL + h*DK + d;
        uint32_t h0, l0, h1, l1;
        split2h(cacc[na][0]*inv0, cacc[na][1]*inv0, h0, l0);   // ctx -> fp16
        split2h(cacc[na][2]*inv1, cacc[na][3]*inv1, h1, l1);
        *(uint32_t*)&g_ch[o]            = h0;
        *(uint32_t*)&g_cl[o]            = l0;
        *(uint32_t*)&g_ch[o + 8*DMODEL] = h1;
        *(uint32_t*)&g_cl[o + 8*DMODEL] = l1;
    }
}

// ---------------- normalize one layer's attention in place ----------------------
__global__ void attn_scale_kernel(float* __restrict__ attn,
                                  const float* __restrict__ rinv) {
    size_t i4 = ((size_t)blockIdx.x*256 + threadIdx.x) * 4;
    float inv = __ldg(&rinv[i4 >> 10]);
    float4 v = *(float4*)&attn[i4];
    v.x *= inv; v.y *= inv; v.z *= inv; v.w *= inv;
    *(float4*)&attn[i4] = v;
}

// ---------------- x = LayerNorm(y + x), writes x fp32 + fp16 split ---------------
__global__ __launch_bounds__(128) void add_ln_kernel(
        const float* __restrict__ y, float* __restrict__ x,
        __half* __restrict__ xh, __half* __restrict__ xl) {
    int row = blockIdx.x;
    int t   = threadIdx.x;
    const float* yr = y + (size_t)row*DMODEL;
    float*       xr = x + (size_t)row*DMODEL;
    float4 a = *(const float4*)&xr[t*4];
    float4 c = *(const float4*)&yr[t*4];
    float v[4] = {a.x + c.x, a.y + c.y, a.z + c.z, a.w + c.w};
    float s = v[0]+v[1]+v[2]+v[3];
    float s2 = v[0]*v[0]+v[1]*v[1]+v[2]*v[2]+v[3]*v[3];
    #pragma unroll
    for (int o = 16; o; o >>= 1) {
        s  += __shfl_xor_sync(0xffffffffu, s,  o);
        s2 += __shfl_xor_sync(0xffffffffu, s2, o);
    }
    __shared__ float sh[8];
    int w = t >> 5;
    if ((t & 31) == 0) { sh[w] = s; sh[4 + w] = s2; }
    __syncthreads();
    s  = sh[0] + sh[1] + sh[2] + sh[3];
    s2 = sh[4] + sh[5] + sh[6] + sh[7];
    float mean = s * (1.f/DMODEL);
    float var  = s2 * (1.f/DMODEL) - mean*mean;
    float invs = rsqrtf(var + 1e-5f);
    float o0 = (v[0]-mean)*invs, o1 = (v[1]-mean)*invs;
    float o2 = (v[2]-mean)*invs, o3 = (v[3]-mean)*invs;
    *(float4*)&xr[t*4] = make_float4(o0, o1, o2, o3);
    uint32_t h0, l0, h1, l1;
    split2h(o0, o1, h0, l0); split2h(o2, o3, h1, l1);
    size_t ob = (size_t)row*DMODEL + t*4;
    *(uint32_t*)&xh[ob]     = h0;  *(uint32_t*)&xl[ob]     = l0;
    *(uint32_t*)&xh[ob + 2] = h1;  *(uint32_t*)&xl[ob + 2] = l1;
}

__global__ void copy_x_kernel(float* __restrict__ out) {
    int i = blockIdx.x*256 + threadIdx.x;
    if (i < MROWS*DMODEL) out[i] = g_x[i];
}

// ---------------- driver ---------------------------------------------------------
extern "C" void kernel_launch(void* const* d_in, const int* in_sizes, int n_in,
                              void* d_out, int out_size) {
    const int*   tok = (const int*)  d_in[0];
    const float* emb = (const float*)d_in[1];
    const float* Wq  = (const float*)d_in[2];
    const float* Wk  = (const float*)d_in[3];
    const float* Wv  = (const float*)d_in[4];
    const float* Wo  = (const float*)d_in[5];
    const float* W1  = (const float*)d_in[6];
    const float* W2  = (const float*)d_in[7];
    float* out = (float*)d_out;

    float* attn_base = out + MROWS*DMODEL;
    bool   write_x   = true;
    if (out_size == MROWS*DMODEL)   { attn_base = nullptr; }
    else if (out_size == 201326592) { attn_base = out; write_x = false; }

    float *px, *py, *prinv;
    cudaGetSymbolAddress((void**)&px, g_x);
    cudaGetSymbolAddress((void**)&py, g_y);
    cudaGetSymbolAddress((void**)&prinv, g_rinv);
    __half *xh, *xl, *ch, *cl, *fh, *fl, *wf;
    __nv_bfloat16 *qh, *ql;
    cudaGetSymbolAddress((void**)&xh, g_xh);
    cudaGetSymbolAddress((void**)&xl, g_xl);
    cudaGetSymbolAddress((void**)&qh, g_qh);
    cudaGetSymbolAddress((void**)&ql, g_ql);
    cudaGetSymbolAddress((void**)&ch, g_ch);
    cudaGetSymbolAddress((void**)&cl, g_cl);
    cudaGetSymbolAddress((void**)&fh, g_fh);
    cudaGetSymbolAddress((void**)&fl, g_fl);
    cudaGetSymbolAddress((void**)&wf, g_wf);

    cudaFuncSetAttribute(attn_kernel, cudaFuncAttributeMaxDynamicSharedMemorySize, ATTN_SMEM);
    cudaFuncSetAttribute(mma_gemm<0>, cudaFuncAttributeMaxDynamicSharedMemorySize, GEMM_SMEM);
    cudaFuncSetAttribute(mma_gemm<1>, cudaFuncAttributeMaxDynamicSharedMemorySize, GEMM_SMEM);
    cudaFuncSetAttribute(mma_gemm<2>, cudaFuncAttributeMaxDynamicSharedMemorySize, GEMM_SMEM);

    // ---- side stream used ONLY for attn_scale overlap (round-8 pattern). ----
    cudaStream_t side = 0;
    cudaEvent_t evFork[NLAYERS], evJoin;
    bool useSide = attn_base != nullptr;
    if (useSide && cudaStreamCreateWithFlags(&side, cudaStreamNonBlocking) != cudaSuccess)
        useSide = false;
    if (useSide) {
        for (int l = 0; l < NLAYERS && useSide; l++)
            if (cudaEventCreateWithFlags(&evFork[l], cudaEventDisableTiming) != cudaSuccess)
                useSide = false;
        if (useSide && cudaEventCreateWithFlags(&evJoin, cudaEventDisableTiming) != cudaSuccess)
            useSide = false;
    }

    embed_kernel<<<(MROWS*DMODEL/2 + 255)/256, 256>>>(tok, emb);
    {
        dim3 gAll(16, 16, 12*NLAYERS);
        wconv_all_kernel<<<gAll, 256>>>(Wq, Wk, Wv, Wo, W1, W2, wf);
    }

    dim3 gQKV(12, 32);    // N=1536
    dim3 gO(4, 32);       // N=512
    dim3 gF1(16, 32);     // N=2048
    dim3 gAttn(SEQ/128, NHEADS, BATCH);
    const unsigned gScale = (unsigned)(ALSTRIDE/1024);

    for (int l = 0; l < NLAYERS; l++) {
        const __half* w = wf + (size_t)l*WL_STRIDE;

        mma_gemm<1><<<gQKV, 256, GEMM_SMEM>>>(xh, xl, w + WOFF_QKV, nullptr,
                                              (uint16_t*)qh, (uint16_t*)ql, 1536, 512);
        attn_kernel<<<gAttn, 512, ATTN_SMEM>>>(tok, attn_base, prinv, l);

        if (attn_base) {
            float* al = attn_base + (long long)l*ALSTRIDE;
            const float* rl = prinv + (size_t)l*BATCH*NHEADS*SEQ;
            if (useSide) {
                cudaEventRecord(evFork[l], 0);
                cudaStreamWaitEvent(side, evFork[l], 0);
                attn_scale_kernel<<<gScale, 256, 0, side>>>(al, rl);
            } else {
                attn_scale_kernel<<<gScale, 256>>>(al, rl);
            }
        }

        mma_gemm<0><<<gO, 256, GEMM_SMEM>>>(ch, cl, w + WOFF_O,
                                            py, nullptr, nullptr, 512, 512);
        add_ln_kernel<<<MROWS, 128>>>(py, px, xh, xl);
        mma_gemm<2><<<gF1, 256, GEMM_SMEM>>>(xh, xl, w + WOFF_1, nullptr,
                                             (uint16_t*)fh, (uint16_t*)fl, 2048, 512);
        mma_gemm<0><<<gO, 256, GEMM_SMEM>>>(fh, fl, w + WOFF_2,
                                            py, nullptr, nullptr, 512, 2048);
        add_ln_kernel<<<MROWS, 128>>>(py, px, xh, xl);
    }

    // copy_x is independent of attn normalization — launch before the join
    if (write_x)
        copy_x_kernel<<<(MROWS*DMODEL + 255)/256, 256>>>(out);

    if (useSide) {          // join side stream back into the captured main stream
        cudaEventRecord(evJoin, side);
        cudaStreamWaitEvent(0, evJoin, 0);
    }
}

// round 16
// speedup vs baseline: 1.2067x; 1.0147x over previous
#include <cuda_runtime.h>
#include <cuda_bf16.h>
#include <cuda_fp16.h>
#include <cstdint>

#define BATCH   4
#define SEQ     1024
#define DMODEL  512
#define NHEADS  8
#define DK      64
#define NLAYERS 6
#define DFFN    2048
#define MROWS   (BATCH*SEQ)   // 4096
#define ALSTRIDE ((long long)BATCH*NHEADS*SEQ*SEQ)   // attn layer stride

// ---------------- scratch (device globals) -------------------------------------
__device__ float g_x  [MROWS*DMODEL];     // residual stream (fp32)
__device__ float g_y  [MROWS*DMODEL];     // gemm fp32 out (pre-LN)
__device__ float g_rinv[NLAYERS*BATCH*NHEADS*SEQ];                    // 1/rowsum
__device__ __half g_xh[MROWS*DMODEL],  g_xl[MROWS*DMODEL];           // x fp16 split
__device__ __nv_bfloat16 g_qh[3*MROWS*DMODEL], g_ql[3*MROWS*DMODEL]; // q|k|v bf16 split
__device__ __half g_ch[MROWS*DMODEL],  g_cl[MROWS*DMODEL];           // ctx fp16 split
__device__ __half g_fh[MROWS*DFFN],    g_fl[MROWS*DFFN];             // ffn fp16 split

// single-fp16 transposed weights Wt[n][k]
#define WL_STRIDE 3145728
#define WOFF_QKV  0
#define WOFF_O    786432
#define WOFF_1    1048576
#define WOFF_2    2097152
__device__ __half g_wf[NLAYERS*WL_STRIDE];

// ---------------- helpers -------------------------------------------------------
__device__ __forceinline__ uint32_t smem_u32(const void* p) {
    uint32_t a;
    asm("{ .reg .u64 t; cvta.to.shared.u64 t, %1; cvt.u32.u64 %0, t; }" : "=r"(a) : "l"(p));
    return a;
}
__device__ __forceinline__ void ldm4(uint32_t* r, uint32_t a) {
    asm volatile("ldmatrix.sync.aligned.m8n8.x4.shared.b16 {%0,%1,%2,%3}, [%4];"
        : "=r"(r[0]), "=r"(r[1]), "=r"(r[2]), "=r"(r[3]) : "r"(a));
}
__device__ __forceinline__ void ldm4t(uint32_t* r, uint32_t a) {
    asm volatile("ldmatrix.sync.aligned.m8n8.x4.trans.shared.b16 {%0,%1,%2,%3}, [%4];"
        : "=r"(r[0]), "=r"(r[1]), "=r"(r[2]), "=r"(r[3]) : "r"(a));
}
__device__ __forceinline__ void mma16816(float* d, const uint32_t* a, const uint32_t* b) {
    asm volatile("mma.sync.aligned.m16n8k16.row.col.f32.bf16.bf16.f32 "
        "{%0,%1,%2,%3}, {%4,%5,%6,%7}, {%8,%9}, {%0,%1,%2,%3};"
        : "+f"(d[0]), "+f"(d[1]), "+f"(d[2]), "+f"(d[3])
        : "r"(a[0]), "r"(a[1]), "r"(a[2]), "r"(a[3]), "r"(b[0]), "r"(b[1]));
}
__device__ __forceinline__ void mma16816h(float* d, const uint32_t* a, const uint32_t* b) {
    asm volatile("mma.sync.aligned.m16n8k16.row.col.f32.f16.f16.f32 "
        "{%0,%1,%2,%3}, {%4,%5,%6,%7}, {%8,%9}, {%0,%1,%2,%3};"
        : "+f"(d[0]), "+f"(d[1]), "+f"(d[2]), "+f"(d[3])
        : "r"(a[0]), "r"(a[1]), "r"(a[2]), "r"(a[3]), "r"(b[0]), "r"(b[1]));
}
__device__ __forceinline__ void split2(float x, float y, uint32_t& hi, uint32_t& lo) {
    __nv_bfloat162 h = __floats2bfloat162_rn(x, y);
    float hx = __bfloat162float(h.x), hy = __bfloat162float(h.y);
    __nv_bfloat162 l2 = __floats2bfloat162_rn(x - hx, y - hy);
    hi = *(uint32_t*)&h;
    lo = *(uint32_t*)&l2;
}
__device__ __forceinline__ void split2h(float x, float y, uint32_t& hi, uint32_t& lo) {
    __half2 h = __floats2half2_rn(x, y);
    float hx = __low2float(h), hy = __high2float(h);
    __half2 l2 = __floats2half2_rn(x - hx, y - hy);
    hi = *(uint32_t*)&h;
    lo = *(uint32_t*)&l2;
}
__device__ __forceinline__ void cpa16(uint32_t dst, const void* src) {
    asm volatile("cp.async.cg.shared.global [%0], [%1], 16;" :: "r"(dst), "l"(src));
}
#define CP_COMMIT() asm volatile("cp.async.commit_group;" ::: "memory")
template<int N> __device__ __forceinline__ void cp_wait() {
    asm volatile("cp.async.wait_group %0;" :: "n"(N) : "memory");
}

// ---------------- embedding + positional encoding -------------------------------
__global__ void embed_kernel(const int* __restrict__ tok,
                             const float* __restrict__ emb) {
    int p = blockIdx.x * 256 + threadIdx.x;
    if (p >= MROWS*DMODEL/2) return;
    int idx = p * 2;
    int row = idx >> 9;
    int d   = idx & (DMODEL-1);
    int s   = row & (SEQ-1);
    int tk  = tok[row];
    float freq = expf((float)d * (-9.210340371976184f / (float)DMODEL));
    float ang  = (float)s * freq;
    float v0 = emb[tk*DMODEL + d]     + sinf(ang);
    float v1 = emb[tk*DMODEL + d + 1] + cosf(ang);
    *(float2*)&g_x[idx] = make_float2(v0, v1);
    uint32_t h, l; split2h(v0, v1, h, l);
    *(uint32_t*)&g_xh[idx] = h;
    *(uint32_t*)&g_xl[idx] = l;
}

// ---------------- unified weight transpose + fp16 convert ------------------------
__global__ void wconv_all_kernel(const float* __restrict__ Wq, const float* __restrict__ Wk,
                                 const float* __restrict__ Wv, const float* __restrict__ Wo,
                                 const float* __restrict__ W1, const float* __restrict__ W2,
                                 __half* __restrict__ wf) {
    __shared__ float tl[32][33];
    int z = blockIdx.z, lyr = z / 12, s = z % 12;
    const float* src;
    size_t doff;
    int srcN, dstK, kb = 0, nb = 0;
    if (s < 4) {
        switch (s) {
            case 0: src = Wq; doff = WOFF_QKV;          break;
            case 1: src = Wk; doff = WOFF_QKV + 262144; break;
            case 2: src = Wv; doff = WOFF_QKV + 524288; break;
            default: src = Wo; doff = WOFF_O;           break;
        }
        src += (size_t)lyr * 262144;
        srcN = 512; dstK = 512;
    } else if (s < 8) {
        src = W1 + (size_t)lyr * DMODEL * DFFN;
        doff = WOFF_1; srcN = 2048; dstK = 512;
        nb = (s - 4) * 512;
    } else {
        src = W2 + (size_t)lyr * DFFN * DMODEL;
        doff = WOFF_2; srcN = 512; dstK = 2048;
        kb = (s - 8) * 512;
    }
    __half* dst = wf + (size_t)lyr * WL_STRIDE + doff;
    int n0 = nb + blockIdx.x*32, k0 = kb + blockIdx.y*32;
    int tx = threadIdx.x & 31, tg = threadIdx.x >> 5;
    #pragma unroll
    for (int r = tg; r < 32; r += 8)
        tl[r][tx] = src[(size_t)(k0 + r)*srcN + n0 + tx];
    __syncthreads();
    #pragma unroll
    for (int r = tg; r < 32; r += 8)
        dst[(size_t)(n0 + r)*dstK + k0 + tx] = __float2half(tl[tx][r]);
}

// ---------------- 2-stage fp16 2-term GEMM, 2 CTAs/SM ---------------------------
#define GSTG      55296
#define GEMM_SMEM (2*GSTG)

__device__ __forceinline__ void gemm_stage_load(
        uint32_t sbase, int t,
        const __half* Ah, const __half* Al, const __half* Bf,
        int m0, int n0, int k0, int K) {
    #pragma unroll
    for (int i = 0; i < 4; i++) {
        int seg = i*256 + t;
        int r = seg >> 3, c = seg & 7;
        uint32_t so = (uint32_t)r*144 + c*16;
        size_t ga = (size_t)(m0 + r)*K + k0 + c*8;
        size_t gb = (size_t)(n0 + r)*K + k0 + c*8;
        cpa16(sbase +         so, Ah + ga);
        cpa16(sbase + 18432 + so, Al + ga);
        cpa16(sbase + 36864 + so, Bf + gb);
    }
}

template<int MODE>
__global__ __launch_bounds__(256, 2) void mma_gemm(
        const __half* __restrict__ Ah, const __half* __restrict__ Al,
        const __half* __restrict__ Bf,
        float* __restrict__ Cf,
        uint16_t* __restrict__ Ch, uint16_t* __restrict__ Cl,
        int N, int K) {
    extern __shared__ char sm[];
    const uint32_t sb = smem_u32(sm);
    int t = threadIdx.x, l = t & 31, wid = t >> 5;
    int m0 = blockIdx.y * 128, n0 = blockIdx.x * 128;
    int wm = (wid & 3) * 32, wn = (wid >> 2) * 64;

    float acc[2][8][4];
    #pragma unroll
    for (int i = 0; i < 2; i++)
        #pragma unroll
        for (int j = 0; j < 8; j++)
            #pragma unroll
            for (int q = 0; q < 4; q++) acc[i][j][q] = 0.f;

    const int NK = K >> 6;
    gemm_stage_load(sb, t, Ah, Al, Bf, m0, n0, 0, K);
    CP_COMMIT();

    for (int kc = 0; kc < NK; kc++) {
        if (kc + 1 < NK) {
            gemm_stage_load(sb + ((kc+1)&1)*GSTG, t, Ah, Al, Bf,
                            m0, n0, (kc+1)*64, K);
            CP_COMMIT();
            cp_wait<1>();
        } else {
            cp_wait<0>();
        }
        __syncthreads();

        const uint32_t SB = sb + (kc & 1)*GSTG;
        const uint32_t AH = SB, AL = SB + 18432, BF = SB + 36864;
        #pragma unroll
        for (int ks = 0; ks < 4; ks++) {
            uint32_t aH[2][4], aL[2][4];
            #pragma unroll
            for (int ra = 0; ra < 2; ra++) {
                uint32_t off = (uint32_t)(wm + ra*16 + (l & 15))*144 + (ks*16 + (l >> 4)*8)*2;
                ldm4(aH[ra], AH + off);
                ldm4(aL[ra], AL + off);
            }
            #pragma unroll
            for (int g = 0; g < 4; g++) {
                uint32_t bF[4];
                uint32_t off = (uint32_t)(wn + g*16 + (l & 7) + ((l >> 4) << 3))*144
                             + (ks*16 + ((l >> 3) & 1)*8)*2;
                ldm4(bF, BF + off);
                mma16816h(acc[0][2*g],   aH[0], &bF[0]);
                mma16816h(acc[0][2*g+1], aH[0], &bF[2]);
                mma16816h(acc[1][2*g],   aH[1], &bF[0]);
                mma16816h(acc[1][2*g+1], aH[1], &bF[2]);
                mma16816h(acc[0][2*g],   aL[0], &bF[0]);
                mma16816h(acc[0][2*g+1], aL[0], &bF[2]);
                mma16816h(acc[1][2*g],   aL[1], &bF[0]);
                mma16816h(acc[1][2*g+1], aL[1], &bF[2]);
            }
        }
        __syncthreads();
    }

    #pragma unroll
    for (int ra = 0; ra < 2; ra++)
        #pragma unroll
        for (int na = 0; na < 8; na++) {
            int n = n0 + wn + na*8 + 2*(l & 3);
            #pragma unroll
            for (int half = 0; half < 2; half++) {
                int m = m0 + wm + ra*16 + (l >> 2) + half*8;
                float2 v = make_float2(acc[ra][na][half*2], acc[ra][na][half*2 + 1]);
                if (MODE == 0) {
                    *(float2*)&Cf[(size_t)m*N + n] = v;
                } else {
                    uint32_t hh, ll;
                    size_t off;
                    if (MODE == 1) {
                        split2(v.x, v.y, hh, ll);
                        int sel = n >> 9, n2 = n & 511;
                        int h = n2 >> 6, dk = n2 & 63;
                        int b = m >> 10, s = m & 1023;
                        off = (size_t)sel*MROWS*DMODEL
                            + ((size_t)((b*NHEADS + h)*SEQ + s))*DK + dk;
                    } else {
                        v.x = fmaxf(v.x, 0.f); v.y = fmaxf(v.y, 0.f);
                        split2h(v.x, v.y, hh, ll);
                        off = (size_t)m*N + n;
                    }
                    *(uint32_t*)&Ch[off] = hh;
                    *(uint32_t*)&Cl[off] = ll;
                }
            }
        }
}

// ---------------- attention: register-P, K/V double-buffered, 1 barrier/chunk ----
// smem: QH 0 | QL 18432 | K0 36864 | K1 73728 | V0 110592 | V1 147456 | msk 184320
#define ATTN_SMEM 188416

__global__ __launch_bounds__(512) void attn_kernel(
        const int* __restrict__ tok, float* __restrict__ attn_out,
        float* __restrict__ rinv_g, int layer) {
    extern __shared__ char sm[];
    const uint32_t sb = smem_u32(sm);
    const uint32_t QH = sb, QL = sb + 18432;
    float* mskS = (float*)(sm + 184320);   // 1024 floats (reused for partials)
    float* redS = (float*)(sm + 36864);    // cacc reduction area (K0, free post-loop)

    int t = threadIdx.x, l = t & 31, wid = t >> 5;
    int wm = wid & 7;          // m-stripe (16 q-rows)
    int wn2 = wid >> 3;        // k-half for QK cols / PV k-range
    int qb = blockIdx.x, h = blockIdx.y, b = blockIdx.z;
    int q0 = qb * 128;
    size_t hoff = ((size_t)(b*NHEADS + h)*SEQ)*DK;
    const __nv_bfloat16* qh = g_qh + hoff + (size_t)q0*DK;
    const __nv_bfloat16* ql = g_ql + hoff + (size_t)q0*DK;
    const __nv_bfloat16* kh = g_qh + (size_t)MROWS*DMODEL + hoff;
    const __nv_bfloat16* kl = g_ql + (size_t)MROWS*DMODEL + hoff;
    const __nv_bfloat16* vh = kh + (size_t)MROWS*DMODEL;
    const __nv_bfloat16* vl = kl + (size_t)MROWS*DMODEL;

    for (int j = t; j < SEQ; j += 512)
        mskS[j] = (tok[b*SEQ + j] == 0) ? 1.f : 0.f;
    // prologue: Q + K(0) + V(0) = group 0
    #pragma unroll
    for (int i = 0; i < 2; i++) {
        int seg = i*512 + t, r = seg >> 3, c = seg & 7;
        uint32_t so = (uint32_t)r*144 + c*16;
        size_t go = (size_t)r*64 + c*8;
        cpa16(QH + so, qh + go);
        cpa16(QL + so, ql + go);
        cpa16(sb + 36864 + so, kh + go);
        cpa16(sb + 55296 + so, kl + go);
        cpa16(sb + 110592 + so, vh + go);
        cpa16(sb + 129024 + so, vl + go);
    }
    CP_COMMIT();

    float rs0 = 0.f, rs1 = 0.f;
    float cacc[8][4];
    #pragma unroll
    for (int j = 0; j < 8; j++)
        #pragma unroll
        for (int q = 0; q < 4; q++) cacc[j][q] = 0.f;

    int r0 = wm*16 + (l >> 2);
    long long abase = ((((long long)layer*BATCH + b)*NHEADS + h)*SEQ + q0)
                      * (long long)SEQ;

    for (int kc = 0; kc < 8; kc++) {
        cp_wait<0>();          // group(kc) complete (own thread)
        __syncthreads();       // K(kc)/V(kc) visible; all done reading kc-1 bufs
        if (kc < 7) {          // issue group(kc+1) into the freed buffers
            const uint32_t KHn = sb + 36864  + (uint32_t)((kc+1) & 1)*36864;
            const uint32_t VHn = sb + 110592 + (uint32_t)((kc+1) & 1)*36864;
            #pragma unroll
            for (int i = 0; i < 2; i++) {
                int seg = i*512 + t, r = seg >> 3, c = seg & 7;
                uint32_t so = (uint32_t)r*144 + c*16;
                size_t go = (size_t)((kc+1)*128 + r)*64 + c*8;
                cpa16(KHn + so,         kh + go);
                cpa16(KHn + 18432 + so, kl + go);
                cpa16(VHn + so,         vh + go);
                cpa16(VHn + 18432 + so, vl + go);
            }
            CP_COMMIT();
        }

        const uint32_t KHc = sb + 36864  + (uint32_t)(kc & 1)*36864;
        const uint32_t KLc = KHc + 18432;
        const uint32_t VHc = sb + 110592 + (uint32_t)(kc & 1)*36864;
        const uint32_t VLc = VHc + 18432;

        uint32_t hp[16], lp[16];   // P fragments for this warp's 4 k-tiles

        // ---- QK + exp in two n-half passes (keeps registers low) ----
        #pragma unroll
        for (int hf = 0; hf < 2; hf++) {
            float sacc[4][4];
            #pragma unroll
            for (int j = 0; j < 4; j++)
                #pragma unroll
                for (int q = 0; q < 4; q++) sacc[j][q] = 0.f;

            #pragma unroll
            for (int ks = 0; ks < 4; ks++) {
                uint32_t aH[4], aL[4];
                uint32_t aoff = (uint32_t)(wm*16 + (l & 15))*144 + (ks*16 + (l >> 4)*8)*2;
                ldm4(aH, QH + aoff); ldm4(aL, QL + aoff);
                #pragma unroll
                for (int gl = 0; gl < 2; gl++) {
                    int G = wn2*4 + hf*2 + gl;          // global k-tile group
                    uint32_t bH[4], bL[4];
                    uint32_t bo = (uint32_t)(G*16 + (l & 7) + ((l >> 4) << 3))*144
                                + (ks*16 + ((l >> 3) & 1)*8)*2;
                    ldm4(bH, KHc + bo); ldm4(bL, KLc + bo);
                    mma16816(sacc[2*gl],   aH, &bH[0]);
                    mma16816(sacc[2*gl+1], aH, &bH[2]);
                    mma16816(sacc[2*gl],   aH, &bL[0]);
                    mma16816(sacc[2*gl+1], aH, &bL[2]);
                    mma16816(sacc[2*gl],   aL, &bH[0]);
                    mma16816(sacc[2*gl+1], aL, &bH[2]);
                }
            }

            // exp, rowsum, attn STG, P fragments into registers
            #pragma unroll
            for (int j = 0; j < 4; j++) {
                int na = hf*4 + j;
                int c0 = kc*128 + wn2*64 + na*8 + 2*(l & 3);
                float2 m2 = *(float2*)&mskS[c0];
                float e0 = (m2.x != 0.f) ? 0.f : __expf(sacc[j][0]*0.125f);
                float e1 = (m2.y != 0.f) ? 0.f : __expf(sacc[j][1]*0.125f);
                float e2 = (m2.x != 0.f) ? 0.f : __expf(sacc[j][2]*0.125f);
                float e3 = (m2.y != 0.f) ? 0.f : __expf(sacc[j][3]*0.125f);
                rs0 += e0 + e1;
                rs1 += e2 + e3;
                if (attn_out) {
                    *(float2*)&attn_out[abase + (long long)r0*SEQ + c0]
                        = make_float2(e0, e1);
                    *(float2*)&attn_out[abase + (long long)(r0 + 8)*SEQ + c0]
                        = make_float2(e2, e3);
                }
                uint32_t h01, l01, h23, l23;
                split2(e0, e1, h01, l01);
                split2(e2, e3, h23, l23);
                int tt = na >> 1, sub = na & 1;    // k-tile, a01 vs a23
                hp[tt*4 + sub*2]     = h01;
                hp[tt*4 + sub*2 + 1] = h23;
                lp[tt*4 + sub*2]     = l01;
                lp[tt*4 + sub*2 + 1] = l23;
            }
        }

        // ---- PV: own k-half (4 tiles), full 64 d-cols, P from registers ----
        #pragma unroll
        for (int tt = 0; tt < 4; tt++) {
            int kg = wn2*4 + tt;
            #pragma unroll
            for (int D = 0; D < 4; D++) {
                uint32_t vH[4], vL[4];
                uint32_t vo = (uint32_t)(kg*16 + (l & 15))*144 + (D*16 + ((l >> 4) << 3))*2;
                ldm4t(vH, VHc + vo); ldm4t(vL, VLc + vo);
                mma16816(cacc[2*D],   &hp[4*tt], &vH[0]);
                mma16816(cacc[2*D+1], &hp[4*tt], &vH[2]);
                mma16816(cacc[2*D],   &hp[4*tt], &vL[0]);
                mma16816(cacc[2*D+1], &hp[4*tt], &vL[2]);
                mma16816(cacc[2*D],   &lp[4*tt], &vH[0]);
                mma16816(cacc[2*D+1], &lp[4*tt], &vH[2]);
            }
        }
    }

    // ---- epilogue: combine k-halves (rowsum + cacc), normalize, write ctx ----
    __syncthreads();   // all warps done with loop (smem bufs reusable)
    rs0 += __shfl_xor_sync(0xffffffffu, rs0, 1);
    rs0 += __shfl_xor_sync(0xffffffffu, rs0, 2);
    rs1 += __shfl_xor_sync(0xffffffffu, rs1, 1);
    rs1 += __shfl_xor_sync(0xffffffffu, rs1, 2);
    float* part = mskS;
    if ((l & 3) == 0) {
        part[r0*2 + wn2]       = rs0;
        part[(r0 + 8)*2 + wn2] = rs1;
    }
    if (wn2 == 1) {                        // stash cacc for reduction
        float* dst = redS + ((size_t)(wm*32 + l))*32;
        #pragma unroll
        for (int j = 0; j < 8; j++)
            #pragma unroll
            for (int q = 0; q < 4; q++) dst[j*4 + q] = cacc[j][q];
    }
    __syncthreads();
    if (wn2 == 0) {
        float inv0 = 1.f / (part[r0*2]     + part[r0*2 + 1]);
        float inv1 = 1.f / (part[(r0+8)*2] + part[(r0+8)*2 + 1]);
        if ((l & 3) == 0) {
            size_t rb = ((size_t)(layer*BATCH + b)*NHEADS + h)*SEQ + q0;
            rinv_g[rb + r0]     = inv0;
            rinv_g[rb + r0 + 8] = inv1;
        }
        const float* src = redS + ((size_t)(wm*32 + l))*32;
        #pragma unroll
        for (int j = 0; j < 8; j++) {
            float c0 = (cacc[j][0] + src[j*4+0]) * inv0;
            float c1 = (cacc[j][1] + src[j*4+1]) * inv0;
            float c2 = (cacc[j][2] + src[j*4+2]) * inv1;
            float c3 = (cacc[j][3] + src[j*4+3]) * inv1;
            int d = j*8 + 2*(l & 3);
            size_t o = ((size_t)(b*SEQ + q0 + r0))*DMODEL + h*DK + d;
            uint32_t h0, l0, h1, l1;
            split2h(c0, c1, h0, l0);
            split2h(c2, c3, h1, l1);
            *(uint32_t*)&g_ch[o]            = h0;
            *(uint32_t*)&g_cl[o]            = l0;
            *(uint32_t*)&g_ch[o + 8*DMODEL] = h1;
            *(uint32_t*)&g_cl[o + 8*DMODEL] = l1;
        }
    }
}

// ---------------- normalize one layer's attention in place ----------------------
__global__ void attn_scale_kernel(float* __restrict__ attn,
                                  const float* __restrict__ rinv) {
    size_t i4 = ((size_t)blockIdx.x*256 + threadIdx.x) * 4;
    float inv = __ldg(&rinv[i4 >> 10]);
    float4 v = *(float4*)&attn[i4];
    v.x *= inv; v.y *= inv; v.z *= inv; v.w *= inv;
    *(float4*)&attn[i4] = v;
}

// ---------------- x = LayerNorm(y + x), writes x fp32 + fp16 split ---------------
__global__ __launch_bounds__(128) void add_ln_kernel(
        const float* __restrict__ y, float* __restrict__ x,
        __half* __restrict__ xh, __half* __restrict__ xl) {
    int row = blockIdx.x;
    int t   = threadIdx.x;
    const float* yr = y + (size_t)row*DMODEL;
    float*       xr = x + (size_t)row*DMODEL;
    float4 a = *(const float4*)&xr[t*4];
    float4 c = *(const float4*)&yr[t*4];
    float v[4] = {a.x + c.x, a.y + c.y, a.z + c.z, a.w + c.w};
    float s = v[0]+v[1]+v[2]+v[3];
    float s2 = v[0]*v[0]+v[1]*v[1]+v[2]*v[2]+v[3]*v[3];
    #pragma unroll
    for (int o = 16; o; o >>= 1) {
        s  += __shfl_xor_sync(0xffffffffu, s,  o);
        s2 += __shfl_xor_sync(0xffffffffu, s2, o);
    }
    __shared__ float sh[8];
    int w = t >> 5;
    if ((t & 31) == 0) { sh[w] = s; sh[4 + w] = s2; }
    __syncthreads();
    s  = sh[0] + sh[1] + sh[2] + sh[3];
    s2 = sh[4] + sh[5] + sh[6] + sh[7];
    float mean = s * (1.f/DMODEL);
    float var  = s2 * (1.f/DMODEL) - mean*mean;
    float invs = rsqrtf(var + 1e-5f);
    float o0 = (v[0]-mean)*invs, o1 = (v[1]-mean)*invs;
    float o2 = (v[2]-mean)*invs, o3 = (v[3]-mean)*invs;
    *(float4*)&xr[t*4] = make_float4(o0, o1, o2, o3);
    uint32_t h0, l0, h1, l1;
    split2h(o0, o1, h0, l0); split2h(o2, o3, h1, l1);
    size_t ob = (size_t)row*DMODEL + t*4;
    *(uint32_t*)&xh[ob]     = h0;  *(uint32_t*)&xl[ob]     = l0;
    *(uint32_t*)&xh[ob + 2] = h1;  *(uint32_t*)&xl[ob + 2] = l1;
}

__global__ void copy_x_kernel(float* __restrict__ out) {
    int i = blockIdx.x*256 + threadIdx.x;
    if (i < MROWS*DMODEL) out[i] = g_x[i];
}

// ---------------- driver ---------------------------------------------------------
extern "C" void kernel_launch(void* const* d_in, const int* in_sizes, int n_in,
                              void* d_out, int out_size) {
    const int*   tok = (const int*)  d_in[0];
    const float* emb = (const float*)d_in[1];
    const float* Wq  = (const float*)d_in[2];
    const float* Wk  = (const float*)d_in[3];
    const float* Wv  = (const float*)d_in[4];
    const float* Wo  = (const float*)d_in[5];
    const float* W1  = (const float*)d_in[6];
    const float* W2  = (const float*)d_in[7];
    float* out = (float*)d_out;

    float* attn_base = out + MROWS*DMODEL;
    bool   write_x   = true;
    if (out_size == MROWS*DMODEL)   { attn_base = nullptr; }
    else if (out_size == 201326592) { attn_base = out; write_x = false; }

    float *px, *py, *prinv;
    cudaGetSymbolAddress((void**)&px, g_x);
    cudaGetSymbolAddress((void**)&py, g_y);
    cudaGetSymbolAddress((void**)&prinv, g_rinv);
    __half *xh, *xl, *ch, *cl, *fh, *fl, *wf;
    __nv_bfloat16 *qh, *ql;
    cudaGetSymbolAddress((void**)&xh, g_xh);
    cudaGetSymbolAddress((void**)&xl, g_xl);
    cudaGetSymbolAddress((void**)&qh, g_qh);
    cudaGetSymbolAddress((void**)&ql, g_ql);
    cudaGetSymbolAddress((void**)&ch, g_ch);
    cudaGetSymbolAddress((void**)&cl, g_cl);
    cudaGetSymbolAddress((void**)&fh, g_fh);
    cudaGetSymbolAddress((void**)&fl, g_fl);
    cudaGetSymbolAddress((void**)&wf, g_wf);

    cudaFuncSetAttribute(attn_kernel, cudaFuncAttributeMaxDynamicSharedMemorySize, ATTN_SMEM);
    cudaFuncSetAttribute(mma_gemm<0>, cudaFuncAttributeMaxDynamicSharedMemorySize, GEMM_SMEM);
    cudaFuncSetAttribute(mma_gemm<1>, cudaFuncAttributeMaxDynamicSharedMemorySize, GEMM_SMEM);
    cudaFuncSetAttribute(mma_gemm<2>, cudaFuncAttributeMaxDynamicSharedMemorySize, GEMM_SMEM);

    // ---- side stream used ONLY for attn_scale overlap ----
    cudaStream_t side = 0;
    cudaEvent_t evFork[NLAYERS], evJoin;
    bool useSide = attn_base != nullptr;
    if (useSide && cudaStreamCreateWithFlags(&side, cudaStreamNonBlocking) != cudaSuccess)
        useSide = false;
    if (useSide) {
        for (int l = 0; l < NLAYERS && useSide; l++)
            if (cudaEventCreateWithFlags(&evFork[l], cudaEventDisableTiming) != cudaSuccess)
                useSide = false;
        if (useSide && cudaEventCreateWithFlags(&evJoin, cudaEventDisableTiming) != cudaSuccess)
            useSide = false;
    }

    embed_kernel<<<(MROWS*DMODEL/2 + 255)/256, 256>>>(tok, emb);
    {
        dim3 gAll(16, 16, 12*NLAYERS);
        wconv_all_kernel<<<gAll, 256>>>(Wq, Wk, Wv, Wo, W1, W2, wf);
    }

    dim3 gQKV(12, 32);    // N=1536
    dim3 gO(4, 32);       // N=512
    dim3 gF1(16, 32);     // N=2048
    dim3 gAttn(SEQ/128, NHEADS, BATCH);
    const unsigned gScale = (unsigned)(ALSTRIDE/1024);

    for (int l = 0; l < NLAYERS; l++) {
        const __half* w = wf + (size_t)l*WL_STRIDE;

        mma_gemm<1><<<gQKV, 256, GEMM_SMEM>>>(xh, xl, w + WOFF_QKV, nullptr,
                                              (uint16_t*)qh, (uint16_t*)ql, 1536, 512);
        attn_kernel<<<gAttn, 512, ATTN_SMEM>>>(tok, attn_base, prinv, l);

        if (attn_base) {
            float* al = attn_base + (long long)l*ALSTRIDE;
            const float* rl = prinv + (size_t)l*BATCH*NHEADS*SEQ;
            if (useSide) {
                cudaEventRecord(evFork[l], 0);
                cudaStreamWaitEvent(side, evFork[l], 0);
                attn_scale_kernel<<<gScale, 256, 0, side>>>(al, rl);
            } else {
                attn_scale_kernel<<<gScale, 256>>>(al, rl);
            }
        }

        mma_gemm<0><<<gO, 256, GEMM_SMEM>>>(ch, cl, w + WOFF_O,
                                            py, nullptr, nullptr, 512, 512);
        add_ln_kernel<<<MROWS, 128>>>(py, px, xh, xl);
        mma_gemm<2><<<gF1, 256, GEMM_SMEM>>>(xh, xl, w + WOFF_1, nullptr,
                                             (uint16_t*)fh, (uint16_t*)fl, 2048, 512);
        mma_gemm<0><<<gO, 256, GEMM_SMEM>>>(fh, fl, w + WOFF_2,
                                            py, nullptr, nullptr, 512, 2048);
        add_ln_kernel<<<MROWS, 128>>>(py, px, xh, xl);
    }

    if (write_x)
        copy_x_kernel<<<(MROWS*DMODEL + 255)/256, 256>>>(out);

    if (useSide) {
        cudaEventRecord(evJoin, side);
        cudaStreamWaitEvent(0, evJoin, 0);
    }
}

// round 17
// speedup vs baseline: 1.3170x; 1.0915x over previous
#include <cuda_runtime.h>
#include <cuda_bf16.h>
#include <cuda_fp16.h>
#include <cstdint>

#define BATCH   4
#define SEQ     1024
#define DMODEL  512
#define NHEADS  8
#define DK      64
#define NLAYERS 6
#define DFFN    2048
#define MROWS   (BATCH*SEQ)   // 4096
#define ALSTRIDE ((long long)BATCH*NHEADS*SEQ*SEQ)   // attn layer stride

// ---------------- scratch (device globals) -------------------------------------
__device__ float g_x  [MROWS*DMODEL];     // residual stream (fp32)
__device__ float g_y  [MROWS*DMODEL];     // gemm fp32 out (pre-LN)
__device__ float g_rinv[NLAYERS*BATCH*NHEADS*SEQ];                    // 1/rowsum
__device__ __half g_xh[MROWS*DMODEL],  g_xl[MROWS*DMODEL];           // x fp16 split
__device__ __half g_qh[3*MROWS*DMODEL], g_ql[3*MROWS*DMODEL];        // q|k|v fp16 split
__device__ __half g_ch[MROWS*DMODEL],  g_cl[MROWS*DMODEL];           // ctx fp16 split
__device__ __half g_fh[MROWS*DFFN],    g_fl[MROWS*DFFN];             // ffn fp16 split

// single-fp16 transposed weights Wt[n][k]
#define WL_STRIDE 3145728
#define WOFF_QKV  0
#define WOFF_O    786432
#define WOFF_1    1048576
#define WOFF_2    2097152
__device__ __half g_wf[NLAYERS*WL_STRIDE];

// ---------------- helpers -------------------------------------------------------
__device__ __forceinline__ uint32_t smem_u32(const void* p) {
    uint32_t a;
    asm("{ .reg .u64 t; cvta.to.shared.u64 t, %1; cvt.u32.u64 %0, t; }" : "=r"(a) : "l"(p));
    return a;
}
__device__ __forceinline__ void ldm4(uint32_t* r, uint32_t a) {
    asm volatile("ldmatrix.sync.aligned.m8n8.x4.shared.b16 {%0,%1,%2,%3}, [%4];"
        : "=r"(r[0]), "=r"(r[1]), "=r"(r[2]), "=r"(r[3]) : "r"(a));
}
__device__ __forceinline__ void ldm4t(uint32_t* r, uint32_t a) {
    asm volatile("ldmatrix.sync.aligned.m8n8.x4.trans.shared.b16 {%0,%1,%2,%3}, [%4];"
        : "=r"(r[0]), "=r"(r[1]), "=r"(r[2]), "=r"(r[3]) : "r"(a));
}
__device__ __forceinline__ void mma16816h(float* d, const uint32_t* a, const uint32_t* b) {
    asm volatile("mma.sync.aligned.m16n8k16.row.col.f32.f16.f16.f32 "
        "{%0,%1,%2,%3}, {%4,%5,%6,%7}, {%8,%9}, {%0,%1,%2,%3};"
        : "+f"(d[0]), "+f"(d[1]), "+f"(d[2]), "+f"(d[3])
        : "r"(a[0]), "r"(a[1]), "r"(a[2]), "r"(a[3]), "r"(b[0]), "r"(b[1]));
}
__device__ __forceinline__ void split2h(float x, float y, uint32_t& hi, uint32_t& lo) {
    __half2 h = __floats2half2_rn(x, y);
    float hx = __low2float(h), hy = __high2float(h);
    __half2 l2 = __floats2half2_rn(x - hx, y - hy);
    hi = *(uint32_t*)&h;
    lo = *(uint32_t*)&l2;
}
__device__ __forceinline__ uint32_t pack2h(float x, float y) {
    __half2 h = __floats2half2_rn(x, y);
    return *(uint32_t*)&h;
}
__device__ __forceinline__ void cpa16(uint32_t dst, const void* src) {
    asm volatile("cp.async.cg.shared.global [%0], [%1], 16;" :: "r"(dst), "l"(src));
}
#define CP_COMMIT() asm volatile("cp.async.commit_group;" ::: "memory")
template<int N> __device__ __forceinline__ void cp_wait() {
    asm volatile("cp.async.wait_group %0;" :: "n"(N) : "memory");
}

// ---------------- embedding + positional encoding -------------------------------
__global__ void embed_kernel(const int* __restrict__ tok,
                             const float* __restrict__ emb) {
    int p = blockIdx.x * 256 + threadIdx.x;
    if (p >= MROWS*DMODEL/2) return;
    int idx = p * 2;
    int row = idx >> 9;
    int d   = idx & (DMODEL-1);
    int s   = row & (SEQ-1);
    int tk  = tok[row];
    float freq = expf((float)d * (-9.210340371976184f / (float)DMODEL));
    float ang  = (float)s * freq;
    float v0 = emb[tk*DMODEL + d]     + sinf(ang);
    float v1 = emb[tk*DMODEL + d + 1] + cosf(ang);
    *(float2*)&g_x[idx] = make_float2(v0, v1);
    uint32_t h, l; split2h(v0, v1, h, l);
    *(uint32_t*)&g_xh[idx] = h;
    *(uint32_t*)&g_xl[idx] = l;
}

// ---------------- unified weight transpose + fp16 convert ------------------------
__global__ void wconv_all_kernel(const float* __restrict__ Wq, const float* __restrict__ Wk,
                                 const float* __restrict__ Wv, const float* __restrict__ Wo,
                                 const float* __restrict__ W1, const float* __restrict__ W2,
                                 __half* __restrict__ wf) {
    __shared__ float tl[32][33];
    int z = blockIdx.z, lyr = z / 12, s = z % 12;
    const float* src;
    size_t doff;
    int srcN, dstK, kb = 0, nb = 0;
    if (s < 4) {
        switch (s) {
            case 0: src = Wq; doff = WOFF_QKV;          break;
            case 1: src = Wk; doff = WOFF_QKV + 262144; break;
            case 2: src = Wv; doff = WOFF_QKV + 524288; break;
            default: src = Wo; doff = WOFF_O;           break;
        }
        src += (size_t)lyr * 262144;
        srcN = 512; dstK = 512;
    } else if (s < 8) {
        src = W1 + (size_t)lyr * DMODEL * DFFN;
        doff = WOFF_1; srcN = 2048; dstK = 512;
        nb = (s - 4) * 512;
    } else {
        src = W2 + (size_t)lyr * DFFN * DMODEL;
        doff = WOFF_2; srcN = 512; dstK = 2048;
        kb = (s - 8) * 512;
    }
    __half* dst = wf + (size_t)lyr * WL_STRIDE + doff;
    int n0 = nb + blockIdx.x*32, k0 = kb + blockIdx.y*32;
    int tx = threadIdx.x & 31, tg = threadIdx.x >> 5;
    #pragma unroll
    for (int r = tg; r < 32; r += 8)
        tl[r][tx] = src[(size_t)(k0 + r)*srcN + n0 + tx];
    __syncthreads();
    #pragma unroll
    for (int r = tg; r < 32; r += 8)
        dst[(size_t)(n0 + r)*dstK + k0 + tx] = __float2half(tl[tx][r]);
}

// ---------------- 2-stage fp16 2-term GEMM, 2 CTAs/SM ---------------------------
#define GSTG      55296
#define GEMM_SMEM (2*GSTG)

__device__ __forceinline__ void gemm_stage_load(
        uint32_t sbase, int t,
        const __half* Ah, const __half* Al, const __half* Bf,
        int m0, int n0, int k0, int K) {
    #pragma unroll
    for (int i = 0; i < 4; i++) {
        int seg = i*256 + t;
        int r = seg >> 3, c = seg & 7;
        uint32_t so = (uint32_t)r*144 + c*16;
        size_t ga = (size_t)(m0 + r)*K + k0 + c*8;
        size_t gb = (size_t)(n0 + r)*K + k0 + c*8;
        cpa16(sbase +         so, Ah + ga);
        cpa16(sbase + 18432 + so, Al + ga);
        cpa16(sbase + 36864 + so, Bf + gb);
    }
}

template<int MODE>
__global__ __launch_bounds__(256, 2) void mma_gemm(
        const __half* __restrict__ Ah, const __half* __restrict__ Al,
        const __half* __restrict__ Bf,
        float* __restrict__ Cf,
        uint16_t* __restrict__ Ch, uint16_t* __restrict__ Cl,
        int N, int K) {
    extern __shared__ char sm[];
    const uint32_t sb = smem_u32(sm);
    int t = threadIdx.x, l = t & 31, wid = t >> 5;
    int m0 = blockIdx.y * 128, n0 = blockIdx.x * 128;
    int wm = (wid & 3) * 32, wn = (wid >> 2) * 64;

    float acc[2][8][4];
    #pragma unroll
    for (int i = 0; i < 2; i++)
        #pragma unroll
        for (int j = 0; j < 8; j++)
            #pragma unroll
            for (int q = 0; q < 4; q++) acc[i][j][q] = 0.f;

    const int NK = K >> 6;
    gemm_stage_load(sb, t, Ah, Al, Bf, m0, n0, 0, K);
    CP_COMMIT();

    for (int kc = 0; kc < NK; kc++) {
        if (kc + 1 < NK) {
            gemm_stage_load(sb + ((kc+1)&1)*GSTG, t, Ah, Al, Bf,
                            m0, n0, (kc+1)*64, K);
            CP_COMMIT();
            cp_wait<1>();
        } else {
            cp_wait<0>();
        }
        __syncthreads();

        const uint32_t SB = sb + (kc & 1)*GSTG;
        const uint32_t AH = SB, AL = SB + 18432, BF = SB + 36864;
        #pragma unroll
        for (int ks = 0; ks < 4; ks++) {
            uint32_t aH[2][4], aL[2][4];
            #pragma unroll
            for (int ra = 0; ra < 2; ra++) {
                uint32_t off = (uint32_t)(wm + ra*16 + (l & 15))*144 + (ks*16 + (l >> 4)*8)*2;
                ldm4(aH[ra], AH + off);
                ldm4(aL[ra], AL + off);
            }
            #pragma unroll
            for (int g = 0; g < 4; g++) {
                uint32_t bF[4];
                uint32_t off = (uint32_t)(wn + g*16 + (l & 7) + ((l >> 4) << 3))*144
                             + (ks*16 + ((l >> 3) & 1)*8)*2;
                ldm4(bF, BF + off);
                mma16816h(acc[0][2*g],   aH[0], &bF[0]);
                mma16816h(acc[0][2*g+1], aH[0], &bF[2]);
                mma16816h(acc[1][2*g],   aH[1], &bF[0]);
                mma16816h(acc[1][2*g+1], aH[1], &bF[2]);
                mma16816h(acc[0][2*g],   aL[0], &bF[0]);
                mma16816h(acc[0][2*g+1], aL[0], &bF[2]);
                mma16816h(acc[1][2*g],   aL[1], &bF[0]);
                mma16816h(acc[1][2*g+1], aL[1], &bF[2]);
            }
        }
        __syncthreads();
    }

    #pragma unroll
    for (int ra = 0; ra < 2; ra++)
        #pragma unroll
        for (int na = 0; na < 8; na++) {
            int n = n0 + wn + na*8 + 2*(l & 3);
            #pragma unroll
            for (int half = 0; half < 2; half++) {
                int m = m0 + wm + ra*16 + (l >> 2) + half*8;
                float2 v = make_float2(acc[ra][na][half*2], acc[ra][na][half*2 + 1]);
                if (MODE == 0) {
                    *(float2*)&Cf[(size_t)m*N + n] = v;
                } else {
                    uint32_t hh, ll;
                    size_t off;
                    if (MODE == 1) {                       // q/k/v: fp16 splits
                        split2h(v.x, v.y, hh, ll);
                        int sel = n >> 9, n2 = n & 511;
                        int h = n2 >> 6, dk = n2 & 63;
                        int b = m >> 10, s = m & 1023;
                        off = (size_t)sel*MROWS*DMODEL
                            + ((size_t)((b*NHEADS + h)*SEQ + s))*DK + dk;
                    } else {
                        v.x = fmaxf(v.x, 0.f); v.y = fmaxf(v.y, 0.f);
                        split2h(v.x, v.y, hh, ll);
                        off = (size_t)m*N + n;
                    }
                    *(uint32_t*)&Ch[off] = hh;
                    *(uint32_t*)&Cl[off] = ll;
                }
            }
        }
}

// ---------------- attention: fp16, QK 2-MMA + PV 2-MMA, register P --------------
// smem: QH 0 | QL 18432 | K0 36864 | K1 55296 | V0 73728(H)/92160(L) |
//       V1 110592/129024 | msk 147456    total 151552
#define ATTN_SMEM 151552
#define PSCALE    0.00390625f   // 2^-8  (P prescale; compensated in ctx normalize)

__global__ __launch_bounds__(512) void attn_kernel(
        const int* __restrict__ tok, float* __restrict__ attn_out,
        float* __restrict__ rinv_g, int layer) {
    extern __shared__ char sm[];
    const uint32_t sb = smem_u32(sm);
    const uint32_t QH = sb, QL = sb + 18432;
    float* mskS = (float*)(sm + 147456);   // 1024 floats (reused for partials)
    float* redS = (float*)(sm + 36864);    // cacc reduction area (K bufs, post-loop)

    int t = threadIdx.x, l = t & 31, wid = t >> 5;
    int wm = wid & 7;          // m-stripe (16 q-rows)
    int wn2 = wid >> 3;        // k-half
    int qb = blockIdx.x, h = blockIdx.y, b = blockIdx.z;
    int q0 = qb * 128;
    size_t hoff = ((size_t)(b*NHEADS + h)*SEQ)*DK;
    const __half* qh = g_qh + hoff + (size_t)q0*DK;
    const __half* ql = g_ql + hoff + (size_t)q0*DK;
    const __half* kh = g_qh + (size_t)MROWS*DMODEL + hoff;      // K single fp16
    const __half* vh = g_qh + (size_t)2*MROWS*DMODEL + hoff;
    const __half* vl = g_ql + (size_t)2*MROWS*DMODEL + hoff;

    for (int j = t; j < SEQ; j += 512)
        mskS[j] = (tok[b*SEQ + j] == 0) ? 1.f : 0.f;
    // prologue: Q(2) + K0(1) + V0(2)
    #pragma unroll
    for (int i = 0; i < 2; i++) {
        int seg = i*512 + t, r = seg >> 3, c = seg & 7;
        uint32_t so = (uint32_t)r*144 + c*16;
        size_t go = (size_t)r*64 + c*8;
        cpa16(QH + so, qh + go);
        cpa16(QL + so, ql + go);
        cpa16(sb + 36864 + so, kh + go);
        cpa16(sb + 73728 + so, vh + go);
        cpa16(sb + 92160 + so, vl + go);
    }
    CP_COMMIT();

    float rs0 = 0.f, rs1 = 0.f;
    float cacc[8][4];
    #pragma unroll
    for (int j = 0; j < 8; j++)
        #pragma unroll
        for (int q = 0; q < 4; q++) cacc[j][q] = 0.f;

    int r0 = wm*16 + (l >> 2);
    long long abase = ((((long long)layer*BATCH + b)*NHEADS + h)*SEQ + q0)
                      * (long long)SEQ;

    for (int kc = 0; kc < 8; kc++) {
        cp_wait<0>();
        __syncthreads();
        if (kc < 7) {
            const uint32_t KHn = sb + 36864 + (uint32_t)((kc+1) & 1)*18432;
            const uint32_t VHn = sb + 73728 + (uint32_t)((kc+1) & 1)*36864;
            #pragma unroll
            for (int i = 0; i < 2; i++) {
                int seg = i*512 + t, r = seg >> 3, c = seg & 7;
                uint32_t so = (uint32_t)r*144 + c*16;
                size_t go = (size_t)((kc+1)*128 + r)*64 + c*8;
                cpa16(KHn + so,         kh + go);
                cpa16(VHn + so,         vh + go);
                cpa16(VHn + 18432 + so, vl + go);
            }
            CP_COMMIT();
        }

        const uint32_t KHc = sb + 36864 + (uint32_t)(kc & 1)*18432;
        const uint32_t VHc = sb + 73728 + (uint32_t)(kc & 1)*36864;
        const uint32_t VLc = VHc + 18432;

        uint32_t hp[16];   // prescaled fp16 P fragments (4 regs per k-tile)

        // ---- QK + exp in two n-half passes ----
        #pragma unroll
        for (int hf = 0; hf < 2; hf++) {
            float sacc[4][4];
            #pragma unroll
            for (int j = 0; j < 4; j++)
                #pragma unroll
                for (int q = 0; q < 4; q++) sacc[j][q] = 0.f;

            #pragma unroll
            for (int ks = 0; ks < 4; ks++) {
                uint32_t aH[4], aL[4];
                uint32_t aoff = (uint32_t)(wm*16 + (l & 15))*144 + (ks*16 + (l >> 4)*8)*2;
                ldm4(aH, QH + aoff); ldm4(aL, QL + aoff);
                #pragma unroll
                for (int gl = 0; gl < 2; gl++) {
                    int G = wn2*4 + hf*2 + gl;
                    uint32_t bF[4];
                    uint32_t bo = (uint32_t)(G*16 + (l & 7) + ((l >> 4) << 3))*144
                                + (ks*16 + ((l >> 3) & 1)*8)*2;
                    ldm4(bF, KHc + bo);
                    mma16816h(sacc[2*gl],   aH, &bF[0]);
                    mma16816h(sacc[2*gl+1], aH, &bF[2]);
                    mma16816h(sacc[2*gl],   aL, &bF[0]);
                    mma16816h(sacc[2*gl+1], aL, &bF[2]);
                }
            }

            #pragma unroll
            for (int j = 0; j < 4; j++) {
                int na = hf*4 + j;
                int c0 = kc*128 + wn2*64 + na*8 + 2*(l & 3);
                float2 m2 = *(float2*)&mskS[c0];
                float e0 = (m2.x != 0.f) ? 0.f : __expf(sacc[j][0]*0.125f);
                float e1 = (m2.y != 0.f) ? 0.f : __expf(sacc[j][1]*0.125f);
                float e2 = (m2.x != 0.f) ? 0.f : __expf(sacc[j][2]*0.125f);
                float e3 = (m2.y != 0.f) ? 0.f : __expf(sacc[j][3]*0.125f);
                rs0 += e0 + e1;
                rs1 += e2 + e3;
                if (attn_out) {
                    *(float2*)&attn_out[abase + (long long)r0*SEQ + c0]
                        = make_float2(e0, e1);
                    *(float2*)&attn_out[abase + (long long)(r0 + 8)*SEQ + c0]
                        = make_float2(e2, e3);
                }
                int tt = na >> 1, sub = na & 1;
                hp[tt*4 + sub*2]     = pack2h(e0*PSCALE, e1*PSCALE);
                hp[tt*4 + sub*2 + 1] = pack2h(e2*PSCALE, e3*PSCALE);
            }
        }

        // ---- PV: own k-half (4 tiles), full 64 d-cols, 2 MMAs per (tt,D) ----
        #pragma unroll
        for (int tt = 0; tt < 4; tt++) {
            int kg = wn2*4 + tt;
            #pragma unroll
            for (int D = 0; D < 4; D++) {
                uint32_t vH[4], vL[4];
                uint32_t vo = (uint32_t)(kg*16 + (l & 15))*144 + (D*16 + ((l >> 4) << 3))*2;
                ldm4t(vH, VHc + vo); ldm4t(vL, VLc + vo);
                mma16816h(cacc[2*D],   &hp[4*tt], &vH[0]);
                mma16816h(cacc[2*D+1], &hp[4*tt], &vH[2]);
                mma16816h(cacc[2*D],   &hp[4*tt], &vL[0]);
                mma16816h(cacc[2*D+1], &hp[4*tt], &vL[2]);
            }
        }
    }

    // ---- epilogue: combine k-halves, normalize (with 2^8 compensation) ----
    __syncthreads();
    rs0 += __shfl_xor_sync(0xffffffffu, rs0, 1);
    rs0 += __shfl_xor_sync(0xffffffffu, rs0, 2);
    rs1 += __shfl_xor_sync(0xffffffffu, rs1, 1);
    rs1 += __shfl_xor_sync(0xffffffffu, rs1, 2);
    float* part = mskS;
    if ((l & 3) == 0) {
        part[r0*2 + wn2]       = rs0;
        part[(r0 + 8)*2 + wn2] = rs1;
    }
    if (wn2 == 1) {
        float* dst = redS + ((size_t)(wm*32 + l))*32;
        #pragma unroll
        for (int j = 0; j < 8; j++)
            #pragma unroll
            for (int q = 0; q < 4; q++) dst[j*4 + q] = cacc[j][q];
    }
    __syncthreads();
    if (wn2 == 0) {
        float sum0 = part[r0*2]     + part[r0*2 + 1];
        float sum1 = part[(r0+8)*2] + part[(r0+8)*2 + 1];
        float inv0 = 256.f / sum0;      // 2^8 undoes the P prescale
        float inv1 = 256.f / sum1;
        if ((l & 3) == 0) {
            size_t rb = ((size_t)(layer*BATCH + b)*NHEADS + h)*SEQ + q0;
            rinv_g[rb + r0]     = 1.f / sum0;
            rinv_g[rb + r0 + 8] = 1.f / sum1;
        }
        const float* src = redS + ((size_t)(wm*32 + l))*32;
        #pragma unroll
        for (int j = 0; j < 8; j++) {
            float c0 = (cacc[j][0] + src[j*4+0]) * inv0;
            float c1 = (cacc[j][1] + src[j*4+1]) * inv0;
            float c2 = (cacc[j][2] + src[j*4+2]) * inv1;
            float c3 = (cacc[j][3] + src[j*4+3]) * inv1;
            int d = j*8 + 2*(l & 3);
            size_t o = ((size_t)(b*SEQ + q0 + r0))*DMODEL + h*DK + d;
            uint32_t h0, l0, h1, l1;
            split2h(c0, c1, h0, l0);
            split2h(c2, c3, h1, l1);
            *(uint32_t*)&g_ch[o]            = h0;
            *(uint32_t*)&g_cl[o]            = l0;
            *(uint32_t*)&g_ch[o + 8*DMODEL] = h1;
            *(uint32_t*)&g_cl[o + 8*DMODEL] = l1;
        }
    }
}

// ---------------- normalize one layer's attention in place ----------------------
__global__ void attn_scale_kernel(float* __restrict__ attn,
                                  const float* __restrict__ rinv) {
    size_t i4 = ((size_t)blockIdx.x*256 + threadIdx.x) * 4;
    float inv = __ldg(&rinv[i4 >> 10]);
    float4 v = *(float4*)&attn[i4];
    v.x *= inv; v.y *= inv; v.z *= inv; v.w *= inv;
    *(float4*)&attn[i4] = v;
}

// ---------------- x = LayerNorm(y + x), writes x fp32 + fp16 split ---------------
__global__ __launch_bounds__(128) void add_ln_kernel(
        const float* __restrict__ y, float* __restrict__ x,
        __half* __restrict__ xh, __half* __restrict__ xl) {
    int row = blockIdx.x;
    int t   = threadIdx.x;
    const float* yr = y + (size_t)row*DMODEL;
    float*       xr = x + (size_t)row*DMODEL;
    float4 a = *(const float4*)&xr[t*4];
    float4 c = *(const float4*)&yr[t*4];
    float v[4] = {a.x + c.x, a.y + c.y, a.z + c.z, a.w + c.w};
    float s = v[0]+v[1]+v[2]+v[3];
    float s2 = v[0]*v[0]+v[1]*v[1]+v[2]*v[2]+v[3]*v[3];
    #pragma unroll
    for (int o = 16; o; o >>= 1) {
        s  += __shfl_xor_sync(0xffffffffu, s,  o);
        s2 += __shfl_xor_sync(0xffffffffu, s2, o);
    }
    __shared__ float sh[8];
    int w = t >> 5;
    if ((t & 31) == 0) { sh[w] = s; sh[4 + w] = s2; }
    __syncthreads();
    s  = sh[0] + sh[1] + sh[2] + sh[3];
    s2 = sh[4] + sh[5] + sh[6] + sh[7];
    float mean = s * (1.f/DMODEL);
    float var  = s2 * (1.f/DMODEL) - mean*mean;
    float invs = rsqrtf(var + 1e-5f);
    float o0 = (v[0]-mean)*invs, o1 = (v[1]-mean)*invs;
    float o2 = (v[2]-mean)*invs, o3 = (v[3]-mean)*invs;
    *(float4*)&xr[t*4] = make_float4(o0, o1, o2, o3);
    uint32_t h0, l0, h1, l1;
    split2h(o0, o1, h0, l0); split2h(o2, o3, h1, l1);
    size_t ob = (size_t)row*DMODEL + t*4;
    *(uint32_t*)&xh[ob]     = h0;  *(uint32_t*)&xl[ob]     = l0;
    *(uint32_t*)&xh[ob + 2] = h1;  *(uint32_t*)&xl[ob + 2] = l1;
}

__global__ void copy_x_kernel(float* __restrict__ out) {
    int i = blockIdx.x*256 + threadIdx.x;
    if (i < MROWS*DMODEL) out[i] = g_x[i];
}

// ---------------- driver ---------------------------------------------------------
extern "C" void kernel_launch(void* const* d_in, const int* in_sizes, int n_in,
                              void* d_out, int out_size) {
    const int*   tok = (const int*)  d_in[0];
    const float* emb = (const float*)d_in[1];
    const float* Wq  = (const float*)d_in[2];
    const float* Wk  = (const float*)d_in[3];
    const float* Wv  = (const float*)d_in[4];
    const float* Wo  = (const float*)d_in[5];
    const float* W1  = (const float*)d_in[6];
    const float* W2  = (const float*)d_in[7];
    float* out = (float*)d_out;

    float* attn_base = out + MROWS*DMODEL;
    bool   write_x   = true;
    if (out_size == MROWS*DMODEL)   { attn_base = nullptr; }
    else if (out_size == 201326592) { attn_base = out; write_x = false; }

    float *px, *py, *prinv;
    cudaGetSymbolAddress((void**)&px, g_x);
    cudaGetSymbolAddress((void**)&py, g_y);
    cudaGetSymbolAddress((void**)&prinv, g_rinv);
    __half *xh, *xl, *qh, *ql, *ch, *cl, *fh, *fl, *wf;
    cudaGetSymbolAddress((void**)&xh, g_xh);
    cudaGetSymbolAddress((void**)&xl, g_xl);
    cudaGetSymbolAddress((void**)&qh, g_qh);
    cudaGetSymbolAddress((void**)&ql, g_ql);
    cudaGetSymbolAddress((void**)&ch, g_ch);
    cudaGetSymbolAddress((void**)&cl, g_cl);
    cudaGetSymbolAddress((void**)&fh, g_fh);
    cudaGetSymbolAddress((void**)&fl, g_fl);
    cudaGetSymbolAddress((void**)&wf, g_wf);

    cudaFuncSetAttribute(attn_kernel, cudaFuncAttributeMaxDynamicSharedMemorySize, ATTN_SMEM);
    cudaFuncSetAttribute(mma_gemm<0>, cudaFuncAttributeMaxDynamicSharedMemorySize, GEMM_SMEM);
    cudaFuncSetAttribute(mma_gemm<1>, cudaFuncAttributeMaxDynamicSharedMemorySize, GEMM_SMEM);
    cudaFuncSetAttribute(mma_gemm<2>, cudaFuncAttributeMaxDynamicSharedMemorySize, GEMM_SMEM);

    // ---- side stream used ONLY for attn_scale overlap ----
    cudaStream_t side = 0;
    cudaEvent_t evFork[NLAYERS], evJoin;
    bool useSide = attn_base != nullptr;
    if (useSide && cudaStreamCreateWithFlags(&side, cudaStreamNonBlocking) != cudaSuccess)
        useSide = false;
    if (useSide) {
        for (int l = 0; l < NLAYERS && useSide; l++)
            if (cudaEventCreateWithFlags(&evFork[l], cudaEventDisableTiming) != cudaSuccess)
                useSide = false;
        if (useSide && cudaEventCreateWithFlags(&evJoin, cudaEventDisableTiming) != cudaSuccess)
            useSide = false;
    }

    embed_kernel<<<(MROWS*DMODEL/2 + 255)/256, 256>>>(tok, emb);
    {
        dim3 gAll(16, 16, 12*NLAYERS);
        wconv_all_kernel<<<gAll, 256>>>(Wq, Wk, Wv, Wo, W1, W2, wf);
    }

    dim3 gQKV(12, 32);    // N=1536
    dim3 gO(4, 32);       // N=512
    dim3 gF1(16, 32);     // N=2048
    dim3 gAttn(SEQ/128, NHEADS, BATCH);
    const unsigned gScale = (unsigned)(ALSTRIDE/1024);

    for (int l = 0; l < NLAYERS; l++) {
        const __half* w = wf + (size_t)l*WL_STRIDE;

        mma_gemm<1><<<gQKV, 256, GEMM_SMEM>>>(xh, xl, w + WOFF_QKV, nullptr,
                                              (uint16_t*)qh, (uint16_t*)ql, 1536, 512);
        attn_kernel<<<gAttn, 512, ATTN_SMEM>>>(tok, attn_base, prinv, l);

        if (attn_base) {
            float* al = attn_base + (long long)l*ALSTRIDE;
            const float* rl = prinv + (size_t)l*BATCH*NHEADS*SEQ;
            if (useSide) {
                cudaEventRecord(evFork[l], 0);
                cudaStreamWaitEvent(side, evFork[l], 0);
                attn_scale_kernel<<<gScale, 256, 0, side>>>(al, rl);
            } else {
                attn_scale_kernel<<<gScale, 256>>>(al, rl);
            }
        }

        mma_gemm<0><<<gO, 256, GEMM_SMEM>>>(ch, cl, w + WOFF_O,
                                            py, nullptr, nullptr, 512, 512);
        add_ln_kernel<<<MROWS, 128>>>(py, px, xh, xl);
        mma_gemm<2><<<gF1, 256, GEMM_SMEM>>>(xh, xl, w + WOFF_1, nullptr,
                                             (uint16_t*)fh, (uint16_t*)fl, 2048, 512);
        mma_gemm<0><<<gO, 256, GEMM_SMEM>>>(fh, fl, w + WOFF_2,
                                            py, nullptr, nullptr, 512, 2048);
        add_ln_kernel<<<MROWS, 128>>>(py, px, xh, xl);
    }

    if (write_x)
        copy_x_kernel<<<(MROWS*DMODEL + 255)/256, 256>>>(out);

    if (useSide) {
        cudaEventRecord(evJoin, side);
        cudaStreamWaitEvent(0, evJoin, 0);
    }
}